// round 3
// baseline (speedup 1.0000x reference)
#include <cuda_runtime.h>

#define BB 32
#define TT 64
#define FF 128
#define DD 64
#define HH 4
#define KK 32
#define HK 128
#define QSCALE 0.17677669529663687f  // 1/sqrt(32)

// ---------------------------------------------------------------------------
// Temporal branch: one CTA per (b, f). Sequence length T=64. 512 threads.
// Shared: Xs[64][64], Qs/Ks/Vs/Os[64][129] (padded), Ss[64][64]
// ---------------------------------------------------------------------------
__global__ void __launch_bounds__(512, 1) temporal_kernel(
    const float* __restrict__ x,
    const float* __restrict__ wq, const float* __restrict__ bq,
    const float* __restrict__ wk, const float* __restrict__ bk,
    const float* __restrict__ wv, const float* __restrict__ bv,
    const float* __restrict__ wo, const float* __restrict__ bo,
    float* __restrict__ out)
{
    extern __shared__ float sm[];
    float* Xs = sm;                 // 64*64
    float* Qs = Xs + 64 * 64;       // 64*129
    float* Ks = Qs + 64 * 129;
    float* Vs = Ks + 64 * 129;
    float* Os = Vs + 64 * 129;
    float* Ss = Os + 64 * 129;      // 64*64

    const int tid = threadIdx.x;
    const int bf  = blockIdx.x;
    const int b   = bf >> 7;        // F = 128
    const int f   = bf & 127;

    // ---- load X slice: x[b, t, f, :] for t in [0,64) ----
    {
        const float4* x4 = (const float4*)x;
        for (int i = tid; i < 64 * 16; i += 512) {
            int t = i >> 4, c = i & 15;
            ((float4*)Xs)[t * 16 + c] =
                x4[((((b * TT + t) * FF + f) * DD) >> 2) + c];
        }
    }
    __syncthreads();

    // ---- Q,K,V projections: [64, 128] each. 16 t-rows/thread, 16 chains ----
    {
        const int hk = tid & 127;
        const int tg = tid >> 7;    // 0..3 -> t = tg*16 + ti
        const float* Xb = Xs + tg * 16 * 64;

        #pragma unroll
        for (int m = 0; m < 3; m++) {
            const float* w = (m == 0) ? wq : (m == 1) ? wk : wv;
            const float* bi = (m == 0) ? bq : (m == 1) ? bk : bv;
            float* dst = (m == 0) ? Qs : (m == 1) ? Ks : Vs;
            float acc[16];
            float bb = bi[hk];
            #pragma unroll
            for (int i = 0; i < 16; i++) acc[i] = bb;
            #pragma unroll
            for (int c = 0; c < 4; c++) {
                float wr[16];
                #pragma unroll
                for (int d = 0; d < 16; d++) wr[d] = w[(c * 16 + d) * HK + hk];
                #pragma unroll
                for (int d = 0; d < 16; d++) {
                    float wv_ = wr[d];
                    #pragma unroll
                    for (int ti = 0; ti < 16; ti++)
                        acc[ti] += wv_ * Xb[ti * 64 + c * 16 + d];
                }
            }
            float sc = (m == 0) ? QSCALE : 1.0f;
            #pragma unroll
            for (int ti = 0; ti < 16; ti++)
                dst[(tg * 16 + ti) * 129 + hk] = acc[ti] * sc;
        }
    }
    __syncthreads();

    // ---- per-head attention ----
    for (int h = 0; h < HH; h++) {
        const int hb = h * 32;
        // scores: S[q][s] = Q[q].K[s]; 8 q/thread
        {
            const int s  = tid & 63;
            const int qg = tid >> 6;   // 0..7
            float kr[32];
            #pragma unroll
            for (int k = 0; k < 32; k++) kr[k] = Ks[s * 129 + hb + k];
            float acc[8];
            #pragma unroll
            for (int i = 0; i < 8; i++) acc[i] = 0.f;
            #pragma unroll
            for (int k = 0; k < 32; k++) {
                float kv = kr[k];
                #pragma unroll
                for (int qi = 0; qi < 8; qi++)
                    acc[qi] += Qs[(qg * 8 + qi) * 129 + hb + k] * kv;
            }
            #pragma unroll
            for (int qi = 0; qi < 8; qi++)
                Ss[(qg * 8 + qi) * 64 + s] = acc[qi];
        }
        __syncthreads();
        // softmax (warp per row, 16 warps)
        {
            const int warp = tid >> 5, lane = tid & 31;
            for (int r = warp; r < 64; r += 16) {
                float v0 = Ss[r * 64 + lane];
                float v1 = Ss[r * 64 + 32 + lane];
                float m = fmaxf(v0, v1);
                #pragma unroll
                for (int o = 16; o > 0; o >>= 1)
                    m = fmaxf(m, __shfl_xor_sync(0xffffffffu, m, o));
                float e0 = __expf(v0 - m), e1 = __expf(v1 - m);
                float su = e0 + e1;
                #pragma unroll
                for (int o = 16; o > 0; o >>= 1)
                    su += __shfl_xor_sync(0xffffffffu, su, o);
                float inv = __frcp_rn(su);
                Ss[r * 64 + lane]      = e0 * inv;
                Ss[r * 64 + 32 + lane] = e1 * inv;
            }
        }
        __syncthreads();
        // O[q][hb+k] = sum_s P[q][s] * V[s][hb+k]; 4 q/thread
        {
            const int k  = tid & 31;
            const int qg = tid >> 5;   // 0..15
            float acc[4];
            #pragma unroll
            for (int i = 0; i < 4; i++) acc[i] = 0.f;
            #pragma unroll
            for (int sc = 0; sc < 2; sc++) {
                float vr[32];
                #pragma unroll
                for (int j = 0; j < 32; j++)
                    vr[j] = Vs[(sc * 32 + j) * 129 + hb + k];
                #pragma unroll
                for (int j = 0; j < 32; j++) {
                    float vv = vr[j];
                    #pragma unroll
                    for (int qi = 0; qi < 4; qi++)
                        acc[qi] += Ss[(qg * 4 + qi) * 64 + sc * 32 + j] * vv;
                }
            }
            #pragma unroll
            for (int qi = 0; qi < 4; qi++)
                Os[(qg * 4 + qi) * 129 + hb + k] = acc[qi];
        }
        __syncthreads();
    }

    // ---- output projection: out[b,t,f,d] = O[t].wo[:,d] + bo[d]; 8 t/thread ----
    {
        const int d  = tid & 63;
        const int tg = tid >> 6;   // 0..7
        float acc[8];
        #pragma unroll
        for (int i = 0; i < 8; i++) acc[i] = 0.f;
        #pragma unroll
        for (int c = 0; c < 8; c++) {
            float wr[16];
            #pragma unroll
            for (int j = 0; j < 16; j++) wr[j] = wo[(c * 16 + j) * DD + d];
            #pragma unroll
            for (int j = 0; j < 16; j++) {
                float wv_ = wr[j];
                #pragma unroll
                for (int qi = 0; qi < 8; qi++)
                    acc[qi] += Os[(tg * 8 + qi) * 129 + c * 16 + j] * wv_;
            }
        }
        float bod = bo[d];
        #pragma unroll
        for (int qi = 0; qi < 8; qi++) {
            int t = tg * 8 + qi;
            out[((b * TT + t) * FF + f) * DD + d] = acc[qi] + bod;
        }
    }
}

// ---------------------------------------------------------------------------
// Feature branch: one CTA per (b, t). Sequence length F=128. 512 threads.
// Shared: Xs[128][64], Qh/Kh/Vh[128][33], Os[128][128], Ss[128][128]
// Adds into out (temporal kernel ran first).
// ---------------------------------------------------------------------------
__global__ void __launch_bounds__(512, 1) feature_kernel(
    const float* __restrict__ x,
    const float* __restrict__ wq, const float* __restrict__ bq,
    const float* __restrict__ wk, const float* __restrict__ bk,
    const float* __restrict__ wv, const float* __restrict__ bv,
    const float* __restrict__ wo, const float* __restrict__ bo,
    float* __restrict__ out)
{
    extern __shared__ float sm[];
    float* Xs = sm;                  // 128*64
    float* Qh = Xs + 128 * 64;       // 128*33
    float* Kh = Qh + 128 * 33;
    float* Vh = Kh + 128 * 33;
    float* Os = Vh + 128 * 33;       // 128*128
    float* Ss = Os + 128 * 128;      // 128*128

    const int tid = threadIdx.x;
    const int bt  = blockIdx.x;
    const int b   = bt >> 6;         // T = 64
    const int t   = bt & 63;

    // ---- load X slice: x[b, t, :, :] (contiguous 8192 floats) ----
    {
        const float4* x4 = (const float4*)(x + (size_t)(b * TT + t) * FF * DD);
        float4* xs4 = (float4*)Xs;
        for (int i = tid; i < 2048; i += 512) xs4[i] = x4[i];
    }
    __syncthreads();

    for (int h = 0; h < HH; h++) {
        const int hb = h * 32;
        // per-head Q,K,V projections: [128, 32]; 8 f-rows/thread
        {
            const int k  = tid & 31;
            const int fg = tid >> 5;   // 0..15
            const float* Xb = Xs + fg * 8 * 64;

            #pragma unroll
            for (int m = 0; m < 3; m++) {
                const float* w = (m == 0) ? wq : (m == 1) ? wk : wv;
                const float* bi = (m == 0) ? bq : (m == 1) ? bk : bv;
                float* dst = (m == 0) ? Qh : (m == 1) ? Kh : Vh;
                float acc[8];
                float bb = bi[hb + k];
                #pragma unroll
                for (int i = 0; i < 8; i++) acc[i] = bb;
                #pragma unroll
                for (int c = 0; c < 4; c++) {
                    float wr[16];
                    #pragma unroll
                    for (int d = 0; d < 16; d++)
                        wr[d] = w[(c * 16 + d) * HK + hb + k];
                    #pragma unroll
                    for (int d = 0; d < 16; d++) {
                        float wv_ = wr[d];
                        #pragma unroll
                        for (int fi = 0; fi < 8; fi++)
                            acc[fi] += wv_ * Xb[fi * 64 + c * 16 + d];
                    }
                }
                float sc = (m == 0) ? QSCALE : 1.0f;
                #pragma unroll
                for (int fi = 0; fi < 8; fi++)
                    dst[(fg * 8 + fi) * 33 + k] = acc[fi] * sc;
            }
        }
        __syncthreads();
        // scores S[q][s], q,s in [0,128); 32 q/thread in 4 groups of 8
        {
            const int s  = tid & 127;
            const int qg = tid >> 7;   // 0..3
            float kr[32];
            #pragma unroll
            for (int k = 0; k < 32; k++) kr[k] = Kh[s * 33 + k];
            #pragma unroll
            for (int g = 0; g < 4; g++) {
                float acc[8];
                #pragma unroll
                for (int i = 0; i < 8; i++) acc[i] = 0.f;
                #pragma unroll
                for (int k = 0; k < 32; k++) {
                    float kv = kr[k];
                    #pragma unroll
                    for (int qi = 0; qi < 8; qi++)
                        acc[qi] += Qh[(qg * 32 + g * 8 + qi) * 33 + k] * kv;
                }
                #pragma unroll
                for (int qi = 0; qi < 8; qi++)
                    Ss[(qg * 32 + g * 8 + qi) * 128 + s] = acc[qi];
            }
        }
        __syncthreads();
        // softmax over 128-wide rows (warp per row, 16 warps)
        {
            const int warp = tid >> 5, lane = tid & 31;
            for (int r = warp; r < 128; r += 16) {
                float v0 = Ss[r * 128 + lane];
                float v1 = Ss[r * 128 + 32 + lane];
                float v2 = Ss[r * 128 + 64 + lane];
                float v3 = Ss[r * 128 + 96 + lane];
                float m = fmaxf(fmaxf(v0, v1), fmaxf(v2, v3));
                #pragma unroll
                for (int o = 16; o > 0; o >>= 1)
                    m = fmaxf(m, __shfl_xor_sync(0xffffffffu, m, o));
                float e0 = __expf(v0 - m), e1 = __expf(v1 - m);
                float e2 = __expf(v2 - m), e3 = __expf(v3 - m);
                float su = (e0 + e1) + (e2 + e3);
                #pragma unroll
                for (int o = 16; o > 0; o >>= 1)
                    su += __shfl_xor_sync(0xffffffffu, su, o);
                float inv = __frcp_rn(su);
                Ss[r * 128 + lane]      = e0 * inv;
                Ss[r * 128 + 32 + lane] = e1 * inv;
                Ss[r * 128 + 64 + lane] = e2 * inv;
                Ss[r * 128 + 96 + lane] = e3 * inv;
            }
        }
        __syncthreads();
        // O[q][hb+k] = sum_s P[q][s] * V[s][k]; 8 q/thread
        {
            const int k  = tid & 31;
            const int qg = tid >> 5;   // 0..15
            float acc[8];
            #pragma unroll
            for (int i = 0; i < 8; i++) acc[i] = 0.f;
            #pragma unroll
            for (int sc = 0; sc < 4; sc++) {
                float vr[32];
                #pragma unroll
                for (int j = 0; j < 32; j++)
                    vr[j] = Vh[(sc * 32 + j) * 33 + k];
                #pragma unroll
                for (int j = 0; j < 32; j++) {
                    float vv = vr[j];
                    #pragma unroll
                    for (int qi = 0; qi < 8; qi++)
                        acc[qi] += Ss[(qg * 8 + qi) * 128 + sc * 32 + j] * vv;
                }
            }
            #pragma unroll
            for (int qi = 0; qi < 8; qi++)
                Os[(qg * 8 + qi) * 128 + hb + k] = acc[qi];
        }
        __syncthreads();
    }

    // ---- output projection + accumulate into out; 16 f-rows/thread ----
    {
        const int d  = tid & 63;
        const int tg = tid >> 6;   // 0..7
        float acc[16];
        #pragma unroll
        for (int i = 0; i < 16; i++) acc[i] = 0.f;
        #pragma unroll
        for (int c = 0; c < 8; c++) {
            float wr[16];
            #pragma unroll
            for (int j = 0; j < 16; j++) wr[j] = wo[(c * 16 + j) * DD + d];
            #pragma unroll
            for (int j = 0; j < 16; j++) {
                float wv_ = wr[j];
                #pragma unroll
                for (int qi = 0; qi < 16; qi++)
                    acc[qi] += Os[(tg * 16 + qi) * 128 + c * 16 + j] * wv_;
            }
        }
        float bod = bo[d];
        #pragma unroll
        for (int qi = 0; qi < 16; qi++) {
            int fr = tg * 16 + qi;
            size_t idx = ((size_t)(b * TT + t) * FF + fr) * DD + d;
            out[idx] += acc[qi] + bod;
        }
    }
}

// ---------------------------------------------------------------------------
extern "C" void kernel_launch(void* const* d_in, const int* in_sizes, int n_in,
                              void* d_out, int out_size)
{
    const float* x = (const float*)d_in[0];
    const float *tqw, *tqb, *tkw, *tkb, *tvw, *tvb, *tow, *tob;
    const float *fqw, *fqb, *fkw, *fkb, *fvw, *fvb, *fow, *fob;

    // Disambiguate input ordering: reference-signature order has to_b (size 64)
    // at index 8; setup_inputs dict order has fq_b (size 128) there.
    if (in_sizes[8] == 64) {
        tqw = (const float*)d_in[1];  tqb = (const float*)d_in[2];
        tkw = (const float*)d_in[3];  tkb = (const float*)d_in[4];
        tvw = (const float*)d_in[5];  tvb = (const float*)d_in[6];
        tow = (const float*)d_in[7];  tob = (const float*)d_in[8];
        fqw = (const float*)d_in[9];  fqb = (const float*)d_in[10];
        fkw = (const float*)d_in[11]; fkb = (const float*)d_in[12];
        fvw = (const float*)d_in[13]; fvb = (const float*)d_in[14];
        fow = (const float*)d_in[15]; fob = (const float*)d_in[16];
    } else {
        tqw = (const float*)d_in[1];  tqb = (const float*)d_in[2];
        tkw = (const float*)d_in[3];  tkb = (const float*)d_in[4];
        tvw = (const float*)d_in[5];  tvb = (const float*)d_in[6];
        fqw = (const float*)d_in[7];  fqb = (const float*)d_in[8];
        fkw = (const float*)d_in[9];  fkb = (const float*)d_in[10];
        fvw = (const float*)d_in[11]; fvb = (const float*)d_in[12];
        tow = (const float*)d_in[13]; tob = (const float*)d_in[14];
        fow = (const float*)d_in[15]; fob = (const float*)d_in[16];
    }

    float* out = (float*)d_out;

    const size_t sm_t = (size_t)(64 * 64 + 4 * 64 * 129 + 64 * 64) * sizeof(float);
    const size_t sm_f = (size_t)(128 * 64 + 3 * 128 * 33 + 2 * 128 * 128) * sizeof(float);

    cudaFuncSetAttribute(temporal_kernel,
                         cudaFuncAttributeMaxDynamicSharedMemorySize, (int)sm_t);
    cudaFuncSetAttribute(feature_kernel,
                         cudaFuncAttributeMaxDynamicSharedMemorySize, (int)sm_f);

    temporal_kernel<<<BB * FF, 512, sm_t>>>(x, tqw, tqb, tkw, tkb, tvw, tvb,
                                            tow, tob, out);
    feature_kernel<<<BB * TT, 512, sm_f>>>(x, fqw, fqb, fkw, fkb, fvw, fvb,
                                           fow, fob, out);
}

// round 4
// speedup vs baseline: 5.1657x; 5.1657x over previous
#include <cuda_runtime.h>

#define QSCALE 0.17677669529663687f  // 1/sqrt(32)

__device__ __forceinline__ unsigned f2tf(float f) {
    unsigned u;
    asm("cvt.rna.tf32.f32 %0, %1;" : "=r"(u) : "f"(f));
    return u;
}

__device__ __forceinline__ void mma8(float* c,
    unsigned a0, unsigned a1, unsigned a2, unsigned a3,
    unsigned b0, unsigned b1)
{
    asm volatile(
        "mma.sync.aligned.m16n8k8.row.col.f32.tf32.tf32.f32 "
        "{%0,%1,%2,%3}, {%4,%5,%6,%7}, {%8,%9}, {%0,%1,%2,%3};"
        : "+f"(c[0]), "+f"(c[1]), "+f"(c[2]), "+f"(c[3])
        : "r"(a0), "r"(a1), "r"(a2), "r"(a3), "r"(b0), "r"(b1));
}

// ---------------------------------------------------------------------------
// Temporal branch: CTA per (b,f), T=64 sequence. 512 threads, 16 warps.
// smem (floats): Xs[64][68], Qs/Ks/Vs/Os[64][132], Ss[64][68], Ws[8704], Bs[448]
// ---------------------------------------------------------------------------
__global__ void __launch_bounds__(512) temporal_kernel(
    const float* __restrict__ x,
    const float* __restrict__ wq, const float* __restrict__ bq,
    const float* __restrict__ wk, const float* __restrict__ bk,
    const float* __restrict__ wv, const float* __restrict__ bv,
    const float* __restrict__ wo, const float* __restrict__ bo,
    float* __restrict__ out)
{
    extern __shared__ float sm[];
    float* Xs = sm;                    // 64*68   = 4352
    float* Qs = sm + 4352;             // 64*132  = 8448
    float* Ks = Qs + 8448;
    float* Vs = Ks + 8448;
    float* Os = Vs + 8448;
    float* Ss = Os + 8448;             // 64*68   = 4352
    float* Ws = Ss + 4352;             // 8704 (views: [64][132] or [128][68])
    float* Bs = Ws + 8704;             // 448: bq@0, bk@128, bv@256, bo@384

    const int tid  = threadIdx.x;
    const int lane = tid & 31, warp = tid >> 5;
    const int g = lane >> 2, t4 = lane & 3;
    const int b = blockIdx.x >> 7, f = blockIdx.x & 127;

    // load X slice x[b, t, f, :]
    {
        const float4* x4 = (const float4*)x;
        for (int i = tid; i < 1024; i += 512) {
            int t = i >> 4, c = i & 15;
            ((float4*)(Xs + t * 68))[c] =
                x4[((((b * 64 + t) * 128 + f) * 64) >> 2) + c];
        }
    }
    if (tid < 448) {
        float v;
        if      (tid < 128) v = bq[tid];
        else if (tid < 256) v = bk[tid - 128];
        else if (tid < 384) v = bv[tid - 256];
        else                v = bo[tid - 384];
        Bs[tid] = v;
    }

    const int mt = warp & 3, nh = warp >> 2;   // nh in 0..3
    const int row0 = mt * 16 + g, row1 = row0 + 8;

    // ---- projections: M=64, N=128, K=64; warp strip = 4 n-tiles ----
    for (int m = 0; m < 3; m++) {
        const float* w   = (m == 0) ? wq : (m == 1) ? wk : wv;
        float*       dst = (m == 0) ? Qs : (m == 1) ? Ks : Vs;
        const float* bb  = Bs + m * 128;
        __syncthreads();
        for (int i = tid; i < 8192; i += 512)
            Ws[(i >> 7) * 132 + (i & 127)] = w[i];   // [d][hk] ld 132
        __syncthreads();

        float acc[4][4];
        #pragma unroll
        for (int nt = 0; nt < 4; nt++) {
            int c0 = nh * 32 + nt * 8 + 2 * t4;
            acc[nt][0] = bb[c0]; acc[nt][1] = bb[c0 + 1];
            acc[nt][2] = acc[nt][0]; acc[nt][3] = acc[nt][1];
        }
        #pragma unroll
        for (int kt = 0; kt < 8; kt++) {
            int k0 = kt * 8 + t4;
            unsigned a0 = f2tf(Xs[row0 * 68 + k0]);
            unsigned a1 = f2tf(Xs[row1 * 68 + k0]);
            unsigned a2 = f2tf(Xs[row0 * 68 + k0 + 4]);
            unsigned a3 = f2tf(Xs[row1 * 68 + k0 + 4]);
            #pragma unroll
            for (int nt = 0; nt < 4; nt++) {
                int n0 = nh * 32 + nt * 8 + g;
                unsigned b0 = f2tf(Ws[k0 * 132 + n0]);
                unsigned b1 = f2tf(Ws[(k0 + 4) * 132 + n0]);
                mma8(acc[nt], a0, a1, a2, a3, b0, b1);
            }
        }
        float sc = (m == 0) ? QSCALE : 1.0f;
        #pragma unroll
        for (int nt = 0; nt < 4; nt++) {
            int c0 = nh * 32 + nt * 8 + 2 * t4;
            dst[row0 * 132 + c0]     = acc[nt][0] * sc;
            dst[row0 * 132 + c0 + 1] = acc[nt][1] * sc;
            dst[row1 * 132 + c0]     = acc[nt][2] * sc;
            dst[row1 * 132 + c0 + 1] = acc[nt][3] * sc;
        }
    }
    __syncthreads();

    // ---- per-head attention ----
    for (int h = 0; h < 4; h++) {
        const int hb = h * 32;
        // scores: M=64, N=64, K=32; warp = 2 n-tiles
        {
            float acc[2][4] = {};
            #pragma unroll
            for (int kt = 0; kt < 4; kt++) {
                int k0 = hb + kt * 8 + t4;
                unsigned a0 = f2tf(Qs[row0 * 132 + k0]);
                unsigned a1 = f2tf(Qs[row1 * 132 + k0]);
                unsigned a2 = f2tf(Qs[row0 * 132 + k0 + 4]);
                unsigned a3 = f2tf(Qs[row1 * 132 + k0 + 4]);
                #pragma unroll
                for (int nt = 0; nt < 2; nt++) {
                    int s0 = nh * 16 + nt * 8 + g;
                    unsigned b0 = f2tf(Ks[s0 * 132 + k0]);
                    unsigned b1 = f2tf(Ks[s0 * 132 + k0 + 4]);
                    mma8(acc[nt], a0, a1, a2, a3, b0, b1);
                }
            }
            #pragma unroll
            for (int nt = 0; nt < 2; nt++) {
                int c0 = nh * 16 + nt * 8 + 2 * t4;
                Ss[row0 * 68 + c0]     = acc[nt][0];
                Ss[row0 * 68 + c0 + 1] = acc[nt][1];
                Ss[row1 * 68 + c0]     = acc[nt][2];
                Ss[row1 * 68 + c0 + 1] = acc[nt][3];
            }
        }
        __syncthreads();
        // softmax (rows 64, cols 64)
        for (int r = warp; r < 64; r += 16) {
            float v0 = Ss[r * 68 + lane], v1 = Ss[r * 68 + 32 + lane];
            float mx = fmaxf(v0, v1);
            #pragma unroll
            for (int o = 16; o > 0; o >>= 1)
                mx = fmaxf(mx, __shfl_xor_sync(0xffffffffu, mx, o));
            float e0 = __expf(v0 - mx), e1 = __expf(v1 - mx);
            float su = e0 + e1;
            #pragma unroll
            for (int o = 16; o > 0; o >>= 1)
                su += __shfl_xor_sync(0xffffffffu, su, o);
            float inv = __frcp_rn(su);
            Ss[r * 68 + lane]      = e0 * inv;
            Ss[r * 68 + 32 + lane] = e1 * inv;
        }
        __syncthreads();
        // AV: M=64, N=32, K=64; warp = 1 n-tile (nh*8)
        {
            float acc[4] = {};
            #pragma unroll
            for (int kt = 0; kt < 8; kt++) {
                int k0 = kt * 8 + t4;
                unsigned a0 = f2tf(Ss[row0 * 68 + k0]);
                unsigned a1 = f2tf(Ss[row1 * 68 + k0]);
                unsigned a2 = f2tf(Ss[row0 * 68 + k0 + 4]);
                unsigned a3 = f2tf(Ss[row1 * 68 + k0 + 4]);
                unsigned b0 = f2tf(Vs[k0 * 132 + hb + nh * 8 + g]);
                unsigned b1 = f2tf(Vs[(k0 + 4) * 132 + hb + nh * 8 + g]);
                mma8(acc, a0, a1, a2, a3, b0, b1);
            }
            int c0 = hb + nh * 8 + 2 * t4;
            Os[row0 * 132 + c0]     = acc[0];
            Os[row0 * 132 + c0 + 1] = acc[1];
            Os[row1 * 132 + c0]     = acc[2];
            Os[row1 * 132 + c0 + 1] = acc[3];
        }
        __syncthreads();
    }

    // ---- output projection: M=64, N=64, K=128; warp = 2 n-tiles ----
    for (int i = tid; i < 8192; i += 512)
        Ws[(i >> 6) * 68 + (i & 63)] = wo[i];    // [hk][d] ld 68
    __syncthreads();
    {
        float acc[2][4];
        #pragma unroll
        for (int nt = 0; nt < 2; nt++) {
            int d0 = nh * 16 + nt * 8 + 2 * t4;
            acc[nt][0] = Bs[384 + d0]; acc[nt][1] = Bs[384 + d0 + 1];
            acc[nt][2] = acc[nt][0];   acc[nt][3] = acc[nt][1];
        }
        #pragma unroll
        for (int kt = 0; kt < 16; kt++) {
            int k0 = kt * 8 + t4;
            unsigned a0 = f2tf(Os[row0 * 132 + k0]);
            unsigned a1 = f2tf(Os[row1 * 132 + k0]);
            unsigned a2 = f2tf(Os[row0 * 132 + k0 + 4]);
            unsigned a3 = f2tf(Os[row1 * 132 + k0 + 4]);
            #pragma unroll
            for (int nt = 0; nt < 2; nt++) {
                int n0 = nh * 16 + nt * 8 + g;
                unsigned b0 = f2tf(Ws[k0 * 68 + n0]);
                unsigned b1 = f2tf(Ws[(k0 + 4) * 68 + n0]);
                mma8(acc[nt], a0, a1, a2, a3, b0, b1);
            }
        }
        #pragma unroll
        for (int nt = 0; nt < 2; nt++) {
            int d0 = nh * 16 + nt * 8 + 2 * t4;
            float2* p0 = (float2*)(out +
                (((size_t)(b * 64 + row0) * 128 + f) * 64 + d0));
            float2* p1 = (float2*)(out +
                (((size_t)(b * 64 + row1) * 128 + f) * 64 + d0));
            *p0 = make_float2(acc[nt][0], acc[nt][1]);
            *p1 = make_float2(acc[nt][2], acc[nt][3]);
        }
    }
}

// ---------------------------------------------------------------------------
// Feature branch: 2 CTAs per (b,t) — each handles 64 of the 128 query rows
// (K/V projections duplicated). 512 threads, 16 warps.
// smem (floats): Xs[128][68], Kh/Vh[128][36], Qh[64][36], Ss[64][132],
//                Oss[64][132], WB[8704], Bs[448]
// ---------------------------------------------------------------------------
__global__ void __launch_bounds__(512) feature_kernel(
    const float* __restrict__ x,
    const float* __restrict__ wq, const float* __restrict__ bq,
    const float* __restrict__ wk, const float* __restrict__ bk,
    const float* __restrict__ wv, const float* __restrict__ bv,
    const float* __restrict__ wo, const float* __restrict__ bo,
    float* __restrict__ out)
{
    extern __shared__ float sm[];
    float* Xs  = sm;                 // 128*68 = 8704
    float* Kh  = sm + 8704;          // 128*36 = 4608
    float* Vh  = Kh + 4608;
    float* Qh  = Vh + 4608;          // 64*36  = 2304
    float* Ss  = Qh + 2304;          // 64*132 = 8448
    float* Oss = Ss + 8448;          // 64*132 = 8448
    float* WB  = Oss + 8448;         // 8704 (slices 3*2304 or Wo [128][68])
    float* Bs  = WB + 8704;          // 448

    const int tid  = threadIdx.x;
    const int lane = tid & 31, warp = tid >> 5;
    const int g = lane >> 2, t4 = lane & 3;
    const int bt = blockIdx.x >> 1, qh = blockIdx.x & 1;
    const int b = bt >> 6, t = bt & 63;

    // load X slice x[b, t, :, :] (contiguous)
    {
        const float4* x4 = (const float4*)(x + (size_t)(b * 64 + t) * 128 * 64);
        for (int i = tid; i < 2048; i += 512) {
            int fr = i >> 4, c = i & 15;
            ((float4*)(Xs + fr * 68))[c] = x4[i];
        }
    }
    if (tid < 448) {
        float v;
        if      (tid < 128) v = bq[tid];
        else if (tid < 256) v = bk[tid - 128];
        else if (tid < 384) v = bv[tid - 256];
        else                v = bo[tid - 384];
        Bs[tid] = v;
    }

    const int mt8 = warp & 7, nh2 = warp >> 3;   // K/V projection map
    const int mt4 = warp & 3, nh4 = warp >> 2;   // Q/scores/AV/out map
    const int r8_0 = mt8 * 16 + g, r8_1 = r8_0 + 8;
    const int r4_0 = mt4 * 16 + g, r4_1 = r4_0 + 8;

    for (int h = 0; h < 4; h++) {
        const int hb = h * 32;
        __syncthreads();   // WB readers of prev head done; also covers Xs/Bs on h=0
        // stage per-head weight slices: Wq@0, Wk@2304, Wv@4608 — [d][k] ld 36
        for (int i = tid; i < 6144; i += 512) {
            int m = i >> 11, r = i & 2047;
            int d = r >> 5, k = r & 31;
            const float* w = (m == 0) ? wq : (m == 1) ? wk : wv;
            WB[m * 2304 + d * 36 + k] = w[d * 128 + hb + k];
        }
        __syncthreads();

        // K,V projections: M=128, N=32, K=64; warp = 2 n-tiles
        #pragma unroll
        for (int m = 1; m <= 2; m++) {
            const float* wsl = WB + m * 2304;
            float*       dst = (m == 1) ? Kh : Vh;
            const float* bb  = Bs + m * 128 + hb;
            float acc[2][4];
            #pragma unroll
            for (int nt = 0; nt < 2; nt++) {
                int c0 = nh2 * 16 + nt * 8 + 2 * t4;
                acc[nt][0] = bb[c0]; acc[nt][1] = bb[c0 + 1];
                acc[nt][2] = acc[nt][0]; acc[nt][3] = acc[nt][1];
            }
            #pragma unroll
            for (int kt = 0; kt < 8; kt++) {
                int k0 = kt * 8 + t4;
                unsigned a0 = f2tf(Xs[r8_0 * 68 + k0]);
                unsigned a1 = f2tf(Xs[r8_1 * 68 + k0]);
                unsigned a2 = f2tf(Xs[r8_0 * 68 + k0 + 4]);
                unsigned a3 = f2tf(Xs[r8_1 * 68 + k0 + 4]);
                #pragma unroll
                for (int nt = 0; nt < 2; nt++) {
                    int n0 = nh2 * 16 + nt * 8 + g;
                    unsigned b0 = f2tf(wsl[k0 * 36 + n0]);
                    unsigned b1 = f2tf(wsl[(k0 + 4) * 36 + n0]);
                    mma8(acc[nt], a0, a1, a2, a3, b0, b1);
                }
            }
            #pragma unroll
            for (int nt = 0; nt < 2; nt++) {
                int c0 = nh2 * 16 + nt * 8 + 2 * t4;
                dst[r8_0 * 36 + c0]     = acc[nt][0];
                dst[r8_0 * 36 + c0 + 1] = acc[nt][1];
                dst[r8_1 * 36 + c0]     = acc[nt][2];
                dst[r8_1 * 36 + c0 + 1] = acc[nt][3];
            }
        }
        // Q projection: M=64 (rows qh*64+..), N=32; warp = 1 n-tile
        {
            const float* bb = Bs + hb;
            int xr0 = qh * 64 + r4_0, xr1 = xr0 + 8;
            float acc[4];
            int c0 = nh4 * 8 + 2 * t4;
            acc[0] = bb[c0]; acc[1] = bb[c0 + 1];
            acc[2] = acc[0]; acc[3] = acc[1];
            #pragma unroll
            for (int kt = 0; kt < 8; kt++) {
                int k0 = kt * 8 + t4;
                unsigned a0 = f2tf(Xs[xr0 * 68 + k0]);
                unsigned a1 = f2tf(Xs[xr1 * 68 + k0]);
                unsigned a2 = f2tf(Xs[xr0 * 68 + k0 + 4]);
                unsigned a3 = f2tf(Xs[xr1 * 68 + k0 + 4]);
                unsigned b0 = f2tf(WB[k0 * 36 + nh4 * 8 + g]);
                unsigned b1 = f2tf(WB[(k0 + 4) * 36 + nh4 * 8 + g]);
                mma8(acc, a0, a1, a2, a3, b0, b1);
            }
            Qh[r4_0 * 36 + c0]     = acc[0] * QSCALE;
            Qh[r4_0 * 36 + c0 + 1] = acc[1] * QSCALE;
            Qh[r4_1 * 36 + c0]     = acc[2] * QSCALE;
            Qh[r4_1 * 36 + c0 + 1] = acc[3] * QSCALE;
        }
        __syncthreads();

        // scores: M=64, N=128, K=32; warp = 4 n-tiles
        {
            float acc[4][4] = {};
            #pragma unroll
            for (int kt = 0; kt < 4; kt++) {
                int k0 = kt * 8 + t4;
                unsigned a0 = f2tf(Qh[r4_0 * 36 + k0]);
                unsigned a1 = f2tf(Qh[r4_1 * 36 + k0]);
                unsigned a2 = f2tf(Qh[r4_0 * 36 + k0 + 4]);
                unsigned a3 = f2tf(Qh[r4_1 * 36 + k0 + 4]);
                #pragma unroll
                for (int nt = 0; nt < 4; nt++) {
                    int s0 = nh4 * 32 + nt * 8 + g;
                    unsigned b0 = f2tf(Kh[s0 * 36 + k0]);
                    unsigned b1 = f2tf(Kh[s0 * 36 + k0 + 4]);
                    mma8(acc[nt], a0, a1, a2, a3, b0, b1);
                }
            }
            #pragma unroll
            for (int nt = 0; nt < 4; nt++) {
                int c0 = nh4 * 32 + nt * 8 + 2 * t4;
                Ss[r4_0 * 132 + c0]     = acc[nt][0];
                Ss[r4_0 * 132 + c0 + 1] = acc[nt][1];
                Ss[r4_1 * 132 + c0]     = acc[nt][2];
                Ss[r4_1 * 132 + c0 + 1] = acc[nt][3];
            }
        }
        __syncthreads();
        // softmax (rows 64, cols 128)
        for (int r = warp; r < 64; r += 16) {
            float v0 = Ss[r * 132 + lane];
            float v1 = Ss[r * 132 + 32 + lane];
            float v2 = Ss[r * 132 + 64 + lane];
            float v3 = Ss[r * 132 + 96 + lane];
            float mx = fmaxf(fmaxf(v0, v1), fmaxf(v2, v3));
            #pragma unroll
            for (int o = 16; o > 0; o >>= 1)
                mx = fmaxf(mx, __shfl_xor_sync(0xffffffffu, mx, o));
            float e0 = __expf(v0 - mx), e1 = __expf(v1 - mx);
            float e2 = __expf(v2 - mx), e3 = __expf(v3 - mx);
            float su = (e0 + e1) + (e2 + e3);
            #pragma unroll
            for (int o = 16; o > 0; o >>= 1)
                su += __shfl_xor_sync(0xffffffffu, su, o);
            float inv = __frcp_rn(su);
            Ss[r * 132 + lane]      = e0 * inv;
            Ss[r * 132 + 32 + lane] = e1 * inv;
            Ss[r * 132 + 64 + lane] = e2 * inv;
            Ss[r * 132 + 96 + lane] = e3 * inv;
        }
        __syncthreads();
        // AV: M=64, N=32, K=128; warp = 1 n-tile
        {
            float acc[4] = {};
            #pragma unroll
            for (int kt = 0; kt < 16; kt++) {
                int k0 = kt * 8 + t4;
                unsigned a0 = f2tf(Ss[r4_0 * 132 + k0]);
                unsigned a1 = f2tf(Ss[r4_1 * 132 + k0]);
                unsigned a2 = f2tf(Ss[r4_0 * 132 + k0 + 4]);
                unsigned a3 = f2tf(Ss[r4_1 * 132 + k0 + 4]);
                unsigned b0 = f2tf(Vh[k0 * 36 + nh4 * 8 + g]);
                unsigned b1 = f2tf(Vh[(k0 + 4) * 36 + nh4 * 8 + g]);
                mma8(acc, a0, a1, a2, a3, b0, b1);
            }
            int c0 = hb + nh4 * 8 + 2 * t4;
            Oss[r4_0 * 132 + c0]     = acc[0];
            Oss[r4_0 * 132 + c0 + 1] = acc[1];
            Oss[r4_1 * 132 + c0]     = acc[2];
            Oss[r4_1 * 132 + c0 + 1] = acc[3];
        }
    }
    __syncthreads();

    // output projection: M=64, N=64, K=128; warp = 2 n-tiles; += into out
    for (int i = tid; i < 8192; i += 512)
        WB[(i >> 6) * 68 + (i & 63)] = wo[i];    // [hk][d] ld 68
    __syncthreads();
    {
        float acc[2][4];
        #pragma unroll
        for (int nt = 0; nt < 2; nt++) {
            int d0 = nh4 * 16 + nt * 8 + 2 * t4;
            acc[nt][0] = Bs[384 + d0]; acc[nt][1] = Bs[384 + d0 + 1];
            acc[nt][2] = acc[nt][0];   acc[nt][3] = acc[nt][1];
        }
        #pragma unroll
        for (int kt = 0; kt < 16; kt++) {
            int k0 = kt * 8 + t4;
            unsigned a0 = f2tf(Oss[r4_0 * 132 + k0]);
            unsigned a1 = f2tf(Oss[r4_1 * 132 + k0]);
            unsigned a2 = f2tf(Oss[r4_0 * 132 + k0 + 4]);
            unsigned a3 = f2tf(Oss[r4_1 * 132 + k0 + 4]);
            #pragma unroll
            for (int nt = 0; nt < 2; nt++) {
                int n0 = nh4 * 16 + nt * 8 + g;
                unsigned b0 = f2tf(WB[k0 * 68 + n0]);
                unsigned b1 = f2tf(WB[(k0 + 4) * 68 + n0]);
                mma8(acc[nt], a0, a1, a2, a3, b0, b1);
            }
        }
        int fr0 = qh * 64 + r4_0, fr1 = fr0 + 8;
        #pragma unroll
        for (int nt = 0; nt < 2; nt++) {
            int d0 = nh4 * 16 + nt * 8 + 2 * t4;
            float2* p0 = (float2*)(out +
                (((size_t)(b * 64 + t) * 128 + fr0) * 64 + d0));
            float2* p1 = (float2*)(out +
                (((size_t)(b * 64 + t) * 128 + fr1) * 64 + d0));
            float2 v0 = *p0, v1 = *p1;
            v0.x += acc[nt][0]; v0.y += acc[nt][1];
            v1.x += acc[nt][2]; v1.y += acc[nt][3];
            *p0 = v0; *p1 = v1;
        }
    }
}

// ---------------------------------------------------------------------------
extern "C" void kernel_launch(void* const* d_in, const int* in_sizes, int n_in,
                              void* d_out, int out_size)
{
    const float* x = (const float*)d_in[0];
    const float *tqw, *tqb, *tkw, *tkb, *tvw, *tvb, *tow, *tob;
    const float *fqw, *fqb, *fkw, *fkb, *fvw, *fvb, *fow, *fob;

    if (in_sizes[8] == 64) {   // reference-signature order
        tqw = (const float*)d_in[1];  tqb = (const float*)d_in[2];
        tkw = (const float*)d_in[3];  tkb = (const float*)d_in[4];
        tvw = (const float*)d_in[5];  tvb = (const float*)d_in[6];
        tow = (const float*)d_in[7];  tob = (const float*)d_in[8];
        fqw = (const float*)d_in[9];  fqb = (const float*)d_in[10];
        fkw = (const float*)d_in[11]; fkb = (const float*)d_in[12];
        fvw = (const float*)d_in[13]; fvb = (const float*)d_in[14];
        fow = (const float*)d_in[15]; fob = (const float*)d_in[16];
    } else {                    // setup_inputs dict order
        tqw = (const float*)d_in[1];  tqb = (const float*)d_in[2];
        tkw = (const float*)d_in[3];  tkb = (const float*)d_in[4];
        tvw = (const float*)d_in[5];  tvb = (const float*)d_in[6];
        fqw = (const float*)d_in[7];  fqb = (const float*)d_in[8];
        fkw = (const float*)d_in[9];  fkb = (const float*)d_in[10];
        fvw = (const float*)d_in[11]; fvb = (const float*)d_in[12];
        tow = (const float*)d_in[13]; tob = (const float*)d_in[14];
        fow = (const float*)d_in[15]; fob = (const float*)d_in[16];
    }

    float* out = (float*)d_out;

    const size_t sm_t = (size_t)(4352 + 4 * 8448 + 4352 + 8704 + 448) * sizeof(float);
    const size_t sm_f = (size_t)(8704 + 2 * 4608 + 2304 + 2 * 8448 + 8704 + 448) * sizeof(float);

    cudaFuncSetAttribute(temporal_kernel,
                         cudaFuncAttributeMaxDynamicSharedMemorySize, (int)sm_t);
    cudaFuncSetAttribute(feature_kernel,
                         cudaFuncAttributeMaxDynamicSharedMemorySize, (int)sm_f);

    temporal_kernel<<<32 * 128, 512, sm_t>>>(x, tqw, tqb, tkw, tkb, tvw, tvb,
                                             tow, tob, out);
    feature_kernel<<<32 * 64 * 2, 512, sm_f>>>(x, fqw, fqb, fkw, fkb, fvw, fvb,
                                               fow, fob, out);
}

// round 6
// speedup vs baseline: 5.5177x; 1.0681x over previous
#include <cuda_runtime.h>

#define QSCALE 0.17677669529663687f  // 1/sqrt(32)

__device__ __forceinline__ unsigned f2tf(float f) {
    unsigned u;
    asm("cvt.rna.tf32.f32 %0, %1;" : "=r"(u) : "f"(f));
    return u;
}
__device__ __forceinline__ float tfs(float f) {   // tf32 bits as float for smem store
    return __uint_as_float(f2tf(f));
}
// column permutation within an 8-slab: logical c -> phys, pairs (t4, t4+4) adjacent
__device__ __forceinline__ int PI8(int s) { return ((s & 3) << 1) | ((s >> 2) & 1); }
__device__ __forceinline__ int cperm(int c) { return (c & ~7) | PI8(c & 7); }

__device__ __forceinline__ uint2 ldp(const float* p) { return *(const uint2*)p; }

__device__ __forceinline__ void mma8(float* c,
    unsigned a0, unsigned a1, unsigned a2, unsigned a3,
    unsigned b0, unsigned b1)
{
    asm volatile(
        "mma.sync.aligned.m16n8k8.row.col.f32.tf32.tf32.f32 "
        "{%0,%1,%2,%3}, {%4,%5,%6,%7}, {%8,%9}, {%0,%1,%2,%3};"
        : "+f"(c[0]), "+f"(c[1]), "+f"(c[2]), "+f"(c[3])
        : "r"(a0), "r"(a1), "r"(a2), "r"(a3), "r"(b0), "r"(b1));
}

// ---------------------------------------------------------------------------
// Temporal branch: CTA per (b,f). T=64. 512 threads / 16 warps.
// smem floats: Xs[64][72] Qs[64][136] Ks[64][136] Vt[128][72] Os[64][136]
//              Ss[64][72] Ws[9216] Bs[448]     total 54208 (216.8 KB)
// All mma operands stored as tf32 bits, k-dim pair-permuted.
// ---------------------------------------------------------------------------
__global__ void __launch_bounds__(512) temporal_kernel(
    const float* __restrict__ x,
    const float* __restrict__ wq, const float* __restrict__ bq,
    const float* __restrict__ wk, const float* __restrict__ bk,
    const float* __restrict__ wv, const float* __restrict__ bv,
    const float* __restrict__ wo, const float* __restrict__ bo,
    float* __restrict__ out)
{
    extern __shared__ float sm[];
    float* Xs = sm;            // 4608
    float* Qs = sm + 4608;     // 8704
    float* Ks = sm + 13312;    // 8704
    float* Vt = sm + 22016;    // 9216  [hk][t]
    float* Os = sm + 31232;    // 8704
    float* Ss = sm + 39936;    // 4608
    float* Ws = sm + 44544;    // 9216
    float* Bs = sm + 53760;    // 448

    const int tid  = threadIdx.x;
    const int lane = tid & 31, warp = tid >> 5;
    const int g = lane >> 2, t4 = lane & 3;
    const int b = blockIdx.x >> 7, f = blockIdx.x & 127;

    // X slice x[b,t,f,:] -> Xs[t][perm(d)] tf32
    {
        const float4* x4 = (const float4*)x;
        for (int i = tid; i < 1024; i += 512) {
            int t = i >> 4, c = i & 15;
            float4 v = x4[((((b * 64 + t) * 128 + f) * 64) >> 2) + c];
            float* d = Xs + t * 72;
            d[cperm(4 * c + 0)] = tfs(v.x);
            d[cperm(4 * c + 1)] = tfs(v.y);
            d[cperm(4 * c + 2)] = tfs(v.z);
            d[cperm(4 * c + 3)] = tfs(v.w);
        }
    }
    if (tid < 448) {
        float v;
        if      (tid < 128) v = bq[tid];
        else if (tid < 256) v = bk[tid - 128];
        else if (tid < 384) v = bv[tid - 256];
        else                v = bo[tid - 384];
        Bs[tid] = v;
    }

    const int mt = warp & 3, nh = warp >> 2;
    const int row0 = mt * 16 + g, row1 = row0 + 8;

    // ---- projections M=64 N=128 K=64, warp tile 16x32 ----
    for (int m = 0; m < 3; m++) {
        const float* w = (m == 0) ? wq : (m == 1) ? wk : wv;
        __syncthreads();
        for (int i = tid; i < 8192; i += 512) {
            int d = i >> 7, hk = i & 127;
            Ws[hk * 72 + cperm(d)] = tfs(w[i]);     // [n=hk][k=d]
        }
        __syncthreads();

        const float* bb = Bs + m * 128;
        float acc[4][4];
        #pragma unroll
        for (int nt = 0; nt < 4; nt++) {
            int c0 = nh * 32 + nt * 8 + 2 * t4;
            acc[nt][0] = bb[c0]; acc[nt][1] = bb[c0 + 1];
            acc[nt][2] = acc[nt][0]; acc[nt][3] = acc[nt][1];
        }
        #pragma unroll
        for (int kt = 0; kt < 8; kt++) {
            int ko = kt * 8 + 2 * t4;
            uint2 pa0 = ldp(Xs + row0 * 72 + ko);
            uint2 pa1 = ldp(Xs + row1 * 72 + ko);
            #pragma unroll
            for (int nt = 0; nt < 4; nt++) {
                int n0 = nh * 32 + nt * 8 + g;
                uint2 pb = ldp(Ws + n0 * 72 + ko);
                mma8(acc[nt], pa0.x, pa1.x, pa0.y, pa1.y, pb.x, pb.y);
            }
        }
        #pragma unroll
        for (int nt = 0; nt < 4; nt++) {
            int c0 = nh * 32 + nt * 8 + 2 * t4;
            if (m == 2) {   // V stored transposed: Vt[hk][perm(t)]
                int pr0 = mt * 16 + PI8(g), pr1 = pr0 + 8;
                Vt[(c0    ) * 72 + pr0] = tfs(acc[nt][0]);
                Vt[(c0 + 1) * 72 + pr0] = tfs(acc[nt][1]);
                Vt[(c0    ) * 72 + pr1] = tfs(acc[nt][2]);
                Vt[(c0 + 1) * 72 + pr1] = tfs(acc[nt][3]);
            } else {
                float* dst = (m == 0) ? Qs : Ks;
                float sc = (m == 0) ? QSCALE : 1.0f;
                int p0 = cperm(c0), p1 = cperm(c0 + 1);
                dst[row0 * 136 + p0] = tfs(acc[nt][0] * sc);
                dst[row0 * 136 + p1] = tfs(acc[nt][1] * sc);
                dst[row1 * 136 + p0] = tfs(acc[nt][2] * sc);
                dst[row1 * 136 + p1] = tfs(acc[nt][3] * sc);
            }
        }
    }

    // ---- per-head attention ----
    for (int h = 0; h < 4; h++) {
        const int hb = h * 32;
        __syncthreads();
        // scores M=64 N=64 K=32, warp tile 16x16
        {
            float acc[2][4] = {};
            #pragma unroll
            for (int kt = 0; kt < 4; kt++) {
                int ko = hb + kt * 8 + 2 * t4;
                uint2 pa0 = ldp(Qs + row0 * 136 + ko);
                uint2 pa1 = ldp(Qs + row1 * 136 + ko);
                #pragma unroll
                for (int nt = 0; nt < 2; nt++) {
                    int s0 = nh * 16 + nt * 8 + g;
                    uint2 pb = ldp(Ks + s0 * 136 + ko);
                    mma8(acc[nt], pa0.x, pa1.x, pa0.y, pa1.y, pb.x, pb.y);
                }
            }
            #pragma unroll
            for (int nt = 0; nt < 2; nt++) {
                int c0 = nh * 16 + nt * 8 + 2 * t4;
                Ss[row0 * 72 + c0]     = acc[nt][0];
                Ss[row0 * 72 + c0 + 1] = acc[nt][1];
                Ss[row1 * 72 + c0]     = acc[nt][2];
                Ss[row1 * 72 + c0 + 1] = acc[nt][3];
            }
        }
        __syncthreads();
        // softmax rows 64 x cols 64; write probs tf32 k-permuted
        for (int r = warp; r < 64; r += 16) {
            float v0 = Ss[r * 72 + lane], v1 = Ss[r * 72 + 32 + lane];
            float mx = fmaxf(v0, v1);
            #pragma unroll
            for (int o = 16; o > 0; o >>= 1)
                mx = fmaxf(mx, __shfl_xor_sync(0xffffffffu, mx, o));
            float e0 = __expf(v0 - mx), e1 = __expf(v1 - mx);
            float su = e0 + e1;
            #pragma unroll
            for (int o = 16; o > 0; o >>= 1)
                su += __shfl_xor_sync(0xffffffffu, su, o);
            float inv = __frcp_rn(su);
            Ss[r * 72 + cperm(lane)]      = tfs(e0 * inv);
            Ss[r * 72 + cperm(32 + lane)] = tfs(e1 * inv);
        }
        __syncthreads();
        // AV M=64 N=32 K=64, warp tile 16x8
        {
            float acc[4] = {};
            int n0 = hb + nh * 8 + g;   // Vt row
            #pragma unroll
            for (int kt = 0; kt < 8; kt++) {
                int ko = kt * 8 + 2 * t4;
                uint2 pa0 = ldp(Ss + row0 * 72 + ko);
                uint2 pa1 = ldp(Ss + row1 * 72 + ko);
                uint2 pb  = ldp(Vt + n0 * 72 + ko);
                mma8(acc, pa0.x, pa1.x, pa0.y, pa1.y, pb.x, pb.y);
            }
            int c0 = hb + nh * 8 + 2 * t4;
            int p0 = cperm(c0), p1 = cperm(c0 + 1);
            Os[row0 * 136 + p0] = tfs(acc[0]);
            Os[row0 * 136 + p1] = tfs(acc[1]);
            Os[row1 * 136 + p0] = tfs(acc[2]);
            Os[row1 * 136 + p1] = tfs(acc[3]);
        }
    }
    __syncthreads();

    // ---- output projection M=64 N=64 K=128, warp tile 16x16 ----
    for (int i = tid; i < 8192; i += 512) {
        int hk = i >> 6, d = i & 63;
        Ws[d * 136 + cperm(hk)] = tfs(wo[i]);       // [n=d][k=hk]
    }
    __syncthreads();
    {
        float acc[2][4];
        #pragma unroll
        for (int nt = 0; nt < 2; nt++) {
            int d0 = nh * 16 + nt * 8 + 2 * t4;
            acc[nt][0] = Bs[384 + d0]; acc[nt][1] = Bs[384 + d0 + 1];
            acc[nt][2] = acc[nt][0];   acc[nt][3] = acc[nt][1];
        }
        #pragma unroll
        for (int kt = 0; kt < 16; kt++) {
            int ko = kt * 8 + 2 * t4;
            uint2 pa0 = ldp(Os + row0 * 136 + ko);
            uint2 pa1 = ldp(Os + row1 * 136 + ko);
            #pragma unroll
            for (int nt = 0; nt < 2; nt++) {
                int n0 = nh * 16 + nt * 8 + g;
                uint2 pb = ldp(Ws + n0 * 136 + ko);
                mma8(acc[nt], pa0.x, pa1.x, pa0.y, pa1.y, pb.x, pb.y);
            }
        }
        #pragma unroll
        for (int nt = 0; nt < 2; nt++) {
            int d0 = nh * 16 + nt * 8 + 2 * t4;
            float2* p0 = (float2*)(out + (((size_t)(b * 64 + row0) * 128 + f) * 64 + d0));
            float2* p1 = (float2*)(out + (((size_t)(b * 64 + row1) * 128 + f) * 64 + d0));
            *p0 = make_float2(acc[nt][0], acc[nt][1]);
            *p1 = make_float2(acc[nt][2], acc[nt][3]);
        }
    }
}

// ---------------------------------------------------------------------------
// Feature branch: 2 CTAs per (b,t), each 64 q-rows. 512 threads / 16 warps.
// smem floats: Xs[128][72] Kh[128][40] Vt[32][136] Qh[64][40] Ss[64][136]
//              Os[64][136] WB[8704] Bs[448]   total 47808 (191.2 KB)
// ---------------------------------------------------------------------------
__global__ void __launch_bounds__(512) feature_kernel(
    const float* __restrict__ x,
    const float* __restrict__ wq, const float* __restrict__ bq,
    const float* __restrict__ wk, const float* __restrict__ bk,
    const float* __restrict__ wv, const float* __restrict__ bv,
    const float* __restrict__ wo, const float* __restrict__ bo,
    float* __restrict__ out)
{
    extern __shared__ float sm[];
    float* Xs = sm;            // 9216
    float* Kh = sm + 9216;     // 5120  [s][k] per head
    float* Vt = sm + 14336;    // 4352  [k][s] per head
    float* Qh = sm + 18688;    // 2560
    float* Ss = sm + 21248;    // 8704
    float* Os = sm + 29952;    // 8704
    float* WB = sm + 38656;    // 8704 (3x2304 per-head slices, or Wo [64][136])
    float* Bs = sm + 47360;    // 448

    const int tid  = threadIdx.x;
    const int lane = tid & 31, warp = tid >> 5;
    const int g = lane >> 2, t4 = lane & 3;
    const int bt = blockIdx.x >> 1, qh = blockIdx.x & 1;
    const int b = bt >> 6, t = bt & 63;

    // X slice x[b,t,:,:] -> Xs[f][perm(d)] tf32
    {
        const float4* x4 = (const float4*)(x + (size_t)(b * 64 + t) * 128 * 64);
        for (int i = tid; i < 2048; i += 512) {
            int fr = i >> 4, c = i & 15;
            float4 v = x4[i];
            float* d = Xs + fr * 72;
            d[cperm(4 * c + 0)] = tfs(v.x);
            d[cperm(4 * c + 1)] = tfs(v.y);
            d[cperm(4 * c + 2)] = tfs(v.z);
            d[cperm(4 * c + 3)] = tfs(v.w);
        }
    }
    if (tid < 448) {
        float v;
        if      (tid < 128) v = bq[tid];
        else if (tid < 256) v = bk[tid - 128];
        else if (tid < 384) v = bv[tid - 256];
        else                v = bo[tid - 384];
        Bs[tid] = v;
    }

    const int mt8 = warp & 7, nh2 = warp >> 3;
    const int mt4 = warp & 3, nh4 = warp >> 2;
    const int r8_0 = mt8 * 16 + g, r8_1 = r8_0 + 8;
    const int r4_0 = mt4 * 16 + g, r4_1 = r4_0 + 8;

    for (int h = 0; h < 4; h++) {
        const int hb = h * 32;
        __syncthreads();
        // stage per-head weight slices [k=32][d perm] tf32: q@0, k@2304, v@4608
        for (int i = tid; i < 6144; i += 512) {
            int m = i >> 11, r = i & 2047;
            int d = r >> 5, k = r & 31;
            const float* w = (m == 0) ? wq : (m == 1) ? wk : wv;
            WB[m * 2304 + k * 72 + cperm(d)] = tfs(w[d * 128 + hb + k]);
        }
        __syncthreads();

        // K+V projections fused: M=128 N=32 K=64, warp tile 16x16 (2 nt)
        {
            float aK[2][4], aV[2][4];
            #pragma unroll
            for (int nt = 0; nt < 2; nt++) {
                int c0 = nh2 * 16 + nt * 8 + 2 * t4;
                aK[nt][0] = Bs[128 + hb + c0]; aK[nt][1] = Bs[128 + hb + c0 + 1];
                aK[nt][2] = aK[nt][0];         aK[nt][3] = aK[nt][1];
                aV[nt][0] = Bs[256 + hb + c0]; aV[nt][1] = Bs[256 + hb + c0 + 1];
                aV[nt][2] = aV[nt][0];         aV[nt][3] = aV[nt][1];
            }
            #pragma unroll
            for (int kt = 0; kt < 8; kt++) {
                int ko = kt * 8 + 2 * t4;
                uint2 pa0 = ldp(Xs + r8_0 * 72 + ko);
                uint2 pa1 = ldp(Xs + r8_1 * 72 + ko);
                #pragma unroll
                for (int nt = 0; nt < 2; nt++) {
                    int n0 = nh2 * 16 + nt * 8 + g;
                    uint2 pk = ldp(WB + 2304 + n0 * 72 + ko);
                    uint2 pv = ldp(WB + 4608 + n0 * 72 + ko);
                    mma8(aK[nt], pa0.x, pa1.x, pa0.y, pa1.y, pk.x, pk.y);
                    mma8(aV[nt], pa0.x, pa1.x, pa0.y, pa1.y, pv.x, pv.y);
                }
            }
            #pragma unroll
            for (int nt = 0; nt < 2; nt++) {
                int c0 = nh2 * 16 + nt * 8 + 2 * t4;
                int p0 = cperm(c0), p1 = cperm(c0 + 1);
                Kh[r8_0 * 40 + p0] = tfs(aK[nt][0]);
                Kh[r8_0 * 40 + p1] = tfs(aK[nt][1]);
                Kh[r8_1 * 40 + p0] = tfs(aK[nt][2]);
                Kh[r8_1 * 40 + p1] = tfs(aK[nt][3]);
                int pr0 = mt8 * 16 + PI8(g), pr1 = pr0 + 8;   // Vt transposed
                Vt[(c0    ) * 136 + pr0] = tfs(aV[nt][0]);
                Vt[(c0 + 1) * 136 + pr0] = tfs(aV[nt][1]);
                Vt[(c0    ) * 136 + pr1] = tfs(aV[nt][2]);
                Vt[(c0 + 1) * 136 + pr1] = tfs(aV[nt][3]);
            }
        }
        // Q projection: M=64 (rows qh*64+r4), N=32, warp tile 16x8
        {
            float acc[4];
            int c0 = nh4 * 8 + 2 * t4;
            acc[0] = Bs[hb + c0]; acc[1] = Bs[hb + c0 + 1];
            acc[2] = acc[0];      acc[3] = acc[1];
            int xr0 = qh * 64 + r4_0, xr1 = xr0 + 8;
            int n0 = nh4 * 8 + g;
            #pragma unroll
            for (int kt = 0; kt < 8; kt++) {
                int ko = kt * 8 + 2 * t4;
                uint2 pa0 = ldp(Xs + xr0 * 72 + ko);
                uint2 pa1 = ldp(Xs + xr1 * 72 + ko);
                uint2 pb  = ldp(WB + n0 * 72 + ko);
                mma8(acc, pa0.x, pa1.x, pa0.y, pa1.y, pb.x, pb.y);
            }
            int p0 = cperm(c0), p1 = cperm(c0 + 1);
            Qh[r4_0 * 40 + p0] = tfs(acc[0] * QSCALE);
            Qh[r4_0 * 40 + p1] = tfs(acc[1] * QSCALE);
            Qh[r4_1 * 40 + p0] = tfs(acc[2] * QSCALE);
            Qh[r4_1 * 40 + p1] = tfs(acc[3] * QSCALE);
        }
        __syncthreads();

        // scores M=64 N=128 K=32, warp tile 16x32
        {
            float acc[4][4] = {};
            #pragma unroll
            for (int kt = 0; kt < 4; kt++) {
                int ko = kt * 8 + 2 * t4;
                uint2 pa0 = ldp(Qh + r4_0 * 40 + ko);
                uint2 pa1 = ldp(Qh + r4_1 * 40 + ko);
                #pragma unroll
                for (int nt = 0; nt < 4; nt++) {
                    int s0 = nh4 * 32 + nt * 8 + g;
                    uint2 pb = ldp(Kh + s0 * 40 + ko);
                    mma8(acc[nt], pa0.x, pa1.x, pa0.y, pa1.y, pb.x, pb.y);
                }
            }
            #pragma unroll
            for (int nt = 0; nt < 4; nt++) {
                int c0 = nh4 * 32 + nt * 8 + 2 * t4;
                Ss[r4_0 * 136 + c0]     = acc[nt][0];
                Ss[r4_0 * 136 + c0 + 1] = acc[nt][1];
                Ss[r4_1 * 136 + c0]     = acc[nt][2];
                Ss[r4_1 * 136 + c0 + 1] = acc[nt][3];
            }
        }
        __syncthreads();
        // softmax rows 64 x cols 128
        for (int r = warp; r < 64; r += 16) {
            float v0 = Ss[r * 136 + lane];
            float v1 = Ss[r * 136 + 32 + lane];
            float v2 = Ss[r * 136 + 64 + lane];
            float v3 = Ss[r * 136 + 96 + lane];
            float mx = fmaxf(fmaxf(v0, v1), fmaxf(v2, v3));
            #pragma unroll
            for (int o = 16; o > 0; o >>= 1)
                mx = fmaxf(mx, __shfl_xor_sync(0xffffffffu, mx, o));
            float e0 = __expf(v0 - mx), e1 = __expf(v1 - mx);
            float e2 = __expf(v2 - mx), e3 = __expf(v3 - mx);
            float su = (e0 + e1) + (e2 + e3);
            #pragma unroll
            for (int o = 16; o > 0; o >>= 1)
                su += __shfl_xor_sync(0xffffffffu, su, o);
            float inv = __frcp_rn(su);
            Ss[r * 136 + cperm(lane)]      = tfs(e0 * inv);
            Ss[r * 136 + cperm(32 + lane)] = tfs(e1 * inv);
            Ss[r * 136 + cperm(64 + lane)] = tfs(e2 * inv);
            Ss[r * 136 + cperm(96 + lane)] = tfs(e3 * inv);
        }
        __syncthreads();
        // AV M=64 N=32 K=128, warp tile 16x8
        {
            float acc[4] = {};
            int n0 = nh4 * 8 + g;   // Vt row
            #pragma unroll
            for (int kt = 0; kt < 16; kt++) {
                int ko = kt * 8 + 2 * t4;
                uint2 pa0 = ldp(Ss + r4_0 * 136 + ko);
                uint2 pa1 = ldp(Ss + r4_1 * 136 + ko);
                uint2 pb  = ldp(Vt + n0 * 136 + ko);
                mma8(acc, pa0.x, pa1.x, pa0.y, pa1.y, pb.x, pb.y);
            }
            int c0 = hb + nh4 * 8 + 2 * t4;
            int p0 = cperm(c0), p1 = cperm(c0 + 1);
            Os[r4_0 * 136 + p0] = tfs(acc[0]);
            Os[r4_0 * 136 + p1] = tfs(acc[1]);
            Os[r4_1 * 136 + p0] = tfs(acc[2]);
            Os[r4_1 * 136 + p1] = tfs(acc[3]);
        }
    }
    __syncthreads();

    // output projection M=64 N=64 K=128; += into out
    for (int i = tid; i < 8192; i += 512) {
        int hk = i >> 6, d = i & 63;
        WB[d * 136 + cperm(hk)] = tfs(wo[i]);
    }
    __syncthreads();
    {
        float acc[2][4];
        #pragma unroll
        for (int nt = 0; nt < 2; nt++) {
            int d0 = nh4 * 16 + nt * 8 + 2 * t4;
            acc[nt][0] = Bs[384 + d0]; acc[nt][1] = Bs[384 + d0 + 1];
            acc[nt][2] = acc[nt][0];   acc[nt][3] = acc[nt][1];
        }
        #pragma unroll
        for (int kt = 0; kt < 16; kt++) {
            int ko = kt * 8 + 2 * t4;
            uint2 pa0 = ldp(Os + r4_0 * 136 + ko);
            uint2 pa1 = ldp(Os + r4_1 * 136 + ko);
            #pragma unroll
            for (int nt = 0; nt < 2; nt++) {
                int n0 = nh4 * 16 + nt * 8 + g;
                uint2 pb = ldp(WB + n0 * 136 + ko);
                mma8(acc[nt], pa0.x, pa1.x, pa0.y, pa1.y, pb.x, pb.y);
            }
        }
        int fr0 = qh * 64 + r4_0, fr1 = fr0 + 8;
        #pragma unroll
        for (int nt = 0; nt < 2; nt++) {
            int d0 = nh4 * 16 + nt * 8 + 2 * t4;
            float2* p0 = (float2*)(out + (((size_t)(b * 64 + t) * 128 + fr0) * 64 + d0));
            float2* p1 = (float2*)(out + (((size_t)(b * 64 + t) * 128 + fr1) * 64 + d0));
            float2 v0 = *p0, v1 = *p1;
            v0.x += acc[nt][0]; v0.y += acc[nt][1];
            v1.x += acc[nt][2]; v1.y += acc[nt][3];
            *p0 = v0; *p1 = v1;
        }
    }
}

// ---------------------------------------------------------------------------
extern "C" void kernel_launch(void* const* d_in, const int* in_sizes, int n_in,
                              void* d_out, int out_size)
{
    const float* x = (const float*)d_in[0];
    const float *tqw, *tqb, *tkw, *tkb, *tvw, *tvb, *tow, *tob;
    const float *fqw, *fqb, *fkw, *fkb, *fvw, *fvb, *fow, *fob;

    if (in_sizes[8] == 64) {   // reference-signature order
        tqw = (const float*)d_in[1];  tqb = (const float*)d_in[2];
        tkw = (const float*)d_in[3];  tkb = (const float*)d_in[4];
        tvw = (const float*)d_in[5];  tvb = (const float*)d_in[6];
        tow = (const float*)d_in[7];  tob = (const float*)d_in[8];
        fqw = (const float*)d_in[9];  fqb = (const float*)d_in[10];
        fkw = (const float*)d_in[11]; fkb = (const float*)d_in[12];
        fvw = (const float*)d_in[13]; fvb = (const float*)d_in[14];
        fow = (const float*)d_in[15]; fob = (const float*)d_in[16];
    } else {                    // setup_inputs dict order
        tqw = (const float*)d_in[1];  tqb = (const float*)d_in[2];
        tkw = (const float*)d_in[3];  tkb = (const float*)d_in[4];
        tvw = (const float*)d_in[5];  tvb = (const float*)d_in[6];
        fqw = (const float*)d_in[7];  fqb = (const float*)d_in[8];
        fkw = (const float*)d_in[9];  fkb = (const float*)d_in[10];
        fvw = (const float*)d_in[11]; fvb = (const float*)d_in[12];
        tow = (const float*)d_in[13]; tob = (const float*)d_in[14];
        fow = (const float*)d_in[15]; fob = (const float*)d_in[16];
    }

    float* out = (float*)d_out;

    const size_t sm_t = 54208 * sizeof(float);   // 216832 B
    const size_t sm_f = 47808 * sizeof(float);   // 191232 B

    cudaFuncSetAttribute(temporal_kernel,
                         cudaFuncAttributeMaxDynamicSharedMemorySize, (int)sm_t);
    cudaFuncSetAttribute(feature_kernel,
                         cudaFuncAttributeMaxDynamicSharedMemorySize, (int)sm_f);

    temporal_kernel<<<32 * 128, 512, sm_t>>>(x, tqw, tqb, tkw, tkb, tvw, tvb,
                                             tow, tob, out);
    feature_kernel<<<32 * 64 * 2, 512, sm_f>>>(x, fqw, fqb, fkw, fkb, fvw, fvb,
                                               fow, fob, out);
}

// round 7
// speedup vs baseline: 6.8264x; 1.2372x over previous
#include <cuda_runtime.h>

#define QSCALE 0.17677669529663687f  // 1/sqrt(32)

__device__ __forceinline__ unsigned f2tf(float f) {
    unsigned u;
    asm("cvt.rna.tf32.f32 %0, %1;" : "=r"(u) : "f"(f));
    return u;
}
__device__ __forceinline__ float tfs(float f) {   // tf32 bits as float for smem store
    return __uint_as_float(f2tf(f));
}
// column permutation within an 8-slab: logical c -> phys, pairs (t4, t4+4) adjacent
__device__ __forceinline__ int PI8(int s) { return ((s & 3) << 1) | ((s >> 2) & 1); }
__device__ __forceinline__ int cperm(int c) { return (c & ~7) | PI8(c & 7); }

__device__ __forceinline__ uint2 ldp(const float* p) { return *(const uint2*)p; }

__device__ __forceinline__ void mma8(float* c,
    unsigned a0, unsigned a1, unsigned a2, unsigned a3,
    unsigned b0, unsigned b1)
{
    asm volatile(
        "mma.sync.aligned.m16n8k8.row.col.f32.tf32.tf32.f32 "
        "{%0,%1,%2,%3}, {%4,%5,%6,%7}, {%8,%9}, {%0,%1,%2,%3};"
        : "+f"(c[0]), "+f"(c[1]), "+f"(c[2]), "+f"(c[3])
        : "r"(a0), "r"(a1), "r"(a2), "r"(a3), "r"(b0), "r"(b1));
}

// ---------------------------------------------------------------------------
// Temporal branch: CTA per (b,f). T=64. 512 threads / 16 warps. (unchanged)
// ---------------------------------------------------------------------------
__global__ void __launch_bounds__(512) temporal_kernel(
    const float* __restrict__ x,
    const float* __restrict__ wq, const float* __restrict__ bq,
    const float* __restrict__ wk, const float* __restrict__ bk,
    const float* __restrict__ wv, const float* __restrict__ bv,
    const float* __restrict__ wo, const float* __restrict__ bo,
    float* __restrict__ out)
{
    extern __shared__ float sm[];
    float* Xs = sm;            // 4608
    float* Qs = sm + 4608;     // 8704
    float* Ks = sm + 13312;    // 8704
    float* Vt = sm + 22016;    // 9216  [hk][t]
    float* Os = sm + 31232;    // 8704
    float* Ss = sm + 39936;    // 4608
    float* Ws = sm + 44544;    // 9216
    float* Bs = sm + 53760;    // 448

    const int tid  = threadIdx.x;
    const int lane = tid & 31, warp = tid >> 5;
    const int g = lane >> 2, t4 = lane & 3;
    const int b = blockIdx.x >> 7, f = blockIdx.x & 127;

    {
        const float4* x4 = (const float4*)x;
        for (int i = tid; i < 1024; i += 512) {
            int t = i >> 4, c = i & 15;
            float4 v = x4[((((b * 64 + t) * 128 + f) * 64) >> 2) + c];
            float* d = Xs + t * 72;
            d[cperm(4 * c + 0)] = tfs(v.x);
            d[cperm(4 * c + 1)] = tfs(v.y);
            d[cperm(4 * c + 2)] = tfs(v.z);
            d[cperm(4 * c + 3)] = tfs(v.w);
        }
    }
    if (tid < 448) {
        float v;
        if      (tid < 128) v = bq[tid];
        else if (tid < 256) v = bk[tid - 128];
        else if (tid < 384) v = bv[tid - 256];
        else                v = bo[tid - 384];
        Bs[tid] = v;
    }

    const int mt = warp & 3, nh = warp >> 2;
    const int row0 = mt * 16 + g, row1 = row0 + 8;

    for (int m = 0; m < 3; m++) {
        const float* w = (m == 0) ? wq : (m == 1) ? wk : wv;
        __syncthreads();
        for (int i = tid; i < 8192; i += 512) {
            int d = i >> 7, hk = i & 127;
            Ws[hk * 72 + cperm(d)] = tfs(w[i]);
        }
        __syncthreads();

        const float* bb = Bs + m * 128;
        float acc[4][4];
        #pragma unroll
        for (int nt = 0; nt < 4; nt++) {
            int c0 = nh * 32 + nt * 8 + 2 * t4;
            acc[nt][0] = bb[c0]; acc[nt][1] = bb[c0 + 1];
            acc[nt][2] = acc[nt][0]; acc[nt][3] = acc[nt][1];
        }
        #pragma unroll
        for (int kt = 0; kt < 8; kt++) {
            int ko = kt * 8 + 2 * t4;
            uint2 pa0 = ldp(Xs + row0 * 72 + ko);
            uint2 pa1 = ldp(Xs + row1 * 72 + ko);
            #pragma unroll
            for (int nt = 0; nt < 4; nt++) {
                int n0 = nh * 32 + nt * 8 + g;
                uint2 pb = ldp(Ws + n0 * 72 + ko);
                mma8(acc[nt], pa0.x, pa1.x, pa0.y, pa1.y, pb.x, pb.y);
            }
        }
        #pragma unroll
        for (int nt = 0; nt < 4; nt++) {
            int c0 = nh * 32 + nt * 8 + 2 * t4;
            if (m == 2) {
                int pr0 = mt * 16 + PI8(g), pr1 = pr0 + 8;
                Vt[(c0    ) * 72 + pr0] = tfs(acc[nt][0]);
                Vt[(c0 + 1) * 72 + pr0] = tfs(acc[nt][1]);
                Vt[(c0    ) * 72 + pr1] = tfs(acc[nt][2]);
                Vt[(c0 + 1) * 72 + pr1] = tfs(acc[nt][3]);
            } else {
                float* dst = (m == 0) ? Qs : Ks;
                float sc = (m == 0) ? QSCALE : 1.0f;
                int p0 = cperm(c0), p1 = cperm(c0 + 1);
                dst[row0 * 136 + p0] = tfs(acc[nt][0] * sc);
                dst[row0 * 136 + p1] = tfs(acc[nt][1] * sc);
                dst[row1 * 136 + p0] = tfs(acc[nt][2] * sc);
                dst[row1 * 136 + p1] = tfs(acc[nt][3] * sc);
            }
        }
    }

    for (int h = 0; h < 4; h++) {
        const int hb = h * 32;
        __syncthreads();
        {
            float acc[2][4] = {};
            #pragma unroll
            for (int kt = 0; kt < 4; kt++) {
                int ko = hb + kt * 8 + 2 * t4;
                uint2 pa0 = ldp(Qs + row0 * 136 + ko);
                uint2 pa1 = ldp(Qs + row1 * 136 + ko);
                #pragma unroll
                for (int nt = 0; nt < 2; nt++) {
                    int s0 = nh * 16 + nt * 8 + g;
                    uint2 pb = ldp(Ks + s0 * 136 + ko);
                    mma8(acc[nt], pa0.x, pa1.x, pa0.y, pa1.y, pb.x, pb.y);
                }
            }
            #pragma unroll
            for (int nt = 0; nt < 2; nt++) {
                int c0 = nh * 16 + nt * 8 + 2 * t4;
                Ss[row0 * 72 + c0]     = acc[nt][0];
                Ss[row0 * 72 + c0 + 1] = acc[nt][1];
                Ss[row1 * 72 + c0]     = acc[nt][2];
                Ss[row1 * 72 + c0 + 1] = acc[nt][3];
            }
        }
        __syncthreads();
        for (int r = warp; r < 64; r += 16) {
            float v0 = Ss[r * 72 + lane], v1 = Ss[r * 72 + 32 + lane];
            float mx = fmaxf(v0, v1);
            #pragma unroll
            for (int o = 16; o > 0; o >>= 1)
                mx = fmaxf(mx, __shfl_xor_sync(0xffffffffu, mx, o));
            float e0 = __expf(v0 - mx), e1 = __expf(v1 - mx);
            float su = e0 + e1;
            #pragma unroll
            for (int o = 16; o > 0; o >>= 1)
                su += __shfl_xor_sync(0xffffffffu, su, o);
            float inv = __frcp_rn(su);
            Ss[r * 72 + cperm(lane)]      = tfs(e0 * inv);
            Ss[r * 72 + cperm(32 + lane)] = tfs(e1 * inv);
        }
        __syncthreads();
        {
            float acc[4] = {};
            int n0 = hb + nh * 8 + g;
            #pragma unroll
            for (int kt = 0; kt < 8; kt++) {
                int ko = kt * 8 + 2 * t4;
                uint2 pa0 = ldp(Ss + row0 * 72 + ko);
                uint2 pa1 = ldp(Ss + row1 * 72 + ko);
                uint2 pb  = ldp(Vt + n0 * 72 + ko);
                mma8(acc, pa0.x, pa1.x, pa0.y, pa1.y, pb.x, pb.y);
            }
            int c0 = hb + nh * 8 + 2 * t4;
            int p0 = cperm(c0), p1 = cperm(c0 + 1);
            Os[row0 * 136 + p0] = tfs(acc[0]);
            Os[row0 * 136 + p1] = tfs(acc[1]);
            Os[row1 * 136 + p0] = tfs(acc[2]);
            Os[row1 * 136 + p1] = tfs(acc[3]);
        }
    }
    __syncthreads();

    for (int i = tid; i < 8192; i += 512) {
        int hk = i >> 6, d = i & 63;
        Ws[d * 136 + cperm(hk)] = tfs(wo[i]);
    }
    __syncthreads();
    {
        float acc[2][4];
        #pragma unroll
        for (int nt = 0; nt < 2; nt++) {
            int d0 = nh * 16 + nt * 8 + 2 * t4;
            acc[nt][0] = Bs[384 + d0]; acc[nt][1] = Bs[384 + d0 + 1];
            acc[nt][2] = acc[nt][0];   acc[nt][3] = acc[nt][1];
        }
        #pragma unroll
        for (int kt = 0; kt < 16; kt++) {
            int ko = kt * 8 + 2 * t4;
            uint2 pa0 = ldp(Os + row0 * 136 + ko);
            uint2 pa1 = ldp(Os + row1 * 136 + ko);
            #pragma unroll
            for (int nt = 0; nt < 2; nt++) {
                int n0 = nh * 16 + nt * 8 + g;
                uint2 pb = ldp(Ws + n0 * 136 + ko);
                mma8(acc[nt], pa0.x, pa1.x, pa0.y, pa1.y, pb.x, pb.y);
            }
        }
        #pragma unroll
        for (int nt = 0; nt < 2; nt++) {
            int d0 = nh * 16 + nt * 8 + 2 * t4;
            float2* p0 = (float2*)(out + (((size_t)(b * 64 + row0) * 128 + f) * 64 + d0));
            float2* p1 = (float2*)(out + (((size_t)(b * 64 + row1) * 128 + f) * 64 + d0));
            *p0 = make_float2(acc[nt][0], acc[nt][1]);
            *p1 = make_float2(acc[nt][2], acc[nt][3]);
        }
    }
}

// ---------------------------------------------------------------------------
// Feature branch v2: ONE CTA per (b,t), all 128 q-rows. 512 threads / 16 warps.
// No K/V projection duplication; out-projection accumulated in registers
// per head (K=32 partials), no big O buffer.
// smem floats: Xs[128][72]=9216 Kh[128][40]=5120 Vt[32][136]=4352
//   Qh[128][40]=5120 Ss[128][136]=17408 Oh[128][40]=5120 WB=6912 WoS=2560
//   Bs=448   total 56256 (225.0 KB)
// ---------------------------------------------------------------------------
__global__ void __launch_bounds__(512) feature_kernel(
    const float* __restrict__ x,
    const float* __restrict__ wq, const float* __restrict__ bq,
    const float* __restrict__ wk, const float* __restrict__ bk,
    const float* __restrict__ wv, const float* __restrict__ bv,
    const float* __restrict__ wo, const float* __restrict__ bo,
    float* __restrict__ out)
{
    extern __shared__ float sm[];
    float* Xs  = sm;            // 9216
    float* Kh  = sm + 9216;     // 5120  [s=128][k=32 perm] ld 40
    float* Vt  = sm + 14336;    // 4352  [k=32][s=128 perm] ld 136
    float* Qh  = sm + 18688;    // 5120  [q=128][k=32 perm] ld 40
    float* Ss  = sm + 23808;    // 17408 [q=128][s=128] ld 136
    float* Oh  = sm + 41216;    // 5120  [q=128][k=32 perm] ld 40
    float* WB  = sm + 46336;    // 6912  3 x [kout=32][d=64 perm] ld 72
    float* WoS = sm + 53248;    // 2560  [d=64][k=32 perm] ld 40
    float* Bs  = sm + 55808;    // 448

    const int tid  = threadIdx.x;
    const int lane = tid & 31, warp = tid >> 5;
    const int g = lane >> 2, t4 = lane & 3;
    const int b = blockIdx.x >> 6, t = blockIdx.x & 63;

    // X slice x[b,t,:,:] -> Xs[f][perm(d)] tf32
    {
        const float4* x4 = (const float4*)(x + (size_t)(b * 64 + t) * 128 * 64);
        for (int i = tid; i < 2048; i += 512) {
            int fr = i >> 4, c = i & 15;
            float4 v = x4[i];
            float* d = Xs + fr * 72;
            d[cperm(4 * c + 0)] = tfs(v.x);
            d[cperm(4 * c + 1)] = tfs(v.y);
            d[cperm(4 * c + 2)] = tfs(v.z);
            d[cperm(4 * c + 3)] = tfs(v.w);
        }
    }
    if (tid < 448) {
        float v;
        if      (tid < 128) v = bq[tid];
        else if (tid < 256) v = bk[tid - 128];
        else if (tid < 384) v = bv[tid - 256];
        else                v = bo[tid - 384];
        Bs[tid] = v;
    }

    const int mt8 = warp & 7, nh2 = warp >> 3;      // 8 m-tiles x 2 n-groups
    const int r0 = mt8 * 16 + g, r1 = r0 + 8;

    // persistent output-projection accumulators (M=128,N=64; warp tile 16x32)
    float pacc[4][4] = {};

    for (int h = 0; h < 4; h++) {
        const int hb = h * 32;
        __syncthreads();   // prev head's out-proj done; Xs/Bs ready at h=0
        // stage per-head weight slices
        for (int i = tid; i < 6144; i += 512) {
            int m = i >> 11, r = i & 2047;
            int ko = r & 31, d = r >> 5;
            const float* w = (m == 0) ? wq : (m == 1) ? wk : wv;
            WB[m * 2304 + ko * 72 + cperm(d)] = tfs(w[d * 128 + hb + ko]);
        }
        for (int i = tid; i < 2048; i += 512) {
            int k = i >> 6, d = i & 63;
            WoS[d * 40 + cperm(k)] = tfs(wo[(hb + k) * 64 + d]);
        }
        __syncthreads();

        // K+V projections fused: M=128 N=32 K=64, warp tile 16x16 (nt=2)
        {
            float aK[2][4], aV[2][4];
            #pragma unroll
            for (int nt = 0; nt < 2; nt++) {
                int c0 = nh2 * 16 + nt * 8 + 2 * t4;
                aK[nt][0] = Bs[128 + hb + c0]; aK[nt][1] = Bs[128 + hb + c0 + 1];
                aK[nt][2] = aK[nt][0];         aK[nt][3] = aK[nt][1];
                aV[nt][0] = Bs[256 + hb + c0]; aV[nt][1] = Bs[256 + hb + c0 + 1];
                aV[nt][2] = aV[nt][0];         aV[nt][3] = aV[nt][1];
            }
            #pragma unroll
            for (int kt = 0; kt < 8; kt++) {
                int ko = kt * 8 + 2 * t4;
                uint2 pa0 = ldp(Xs + r0 * 72 + ko);
                uint2 pa1 = ldp(Xs + r1 * 72 + ko);
                #pragma unroll
                for (int nt = 0; nt < 2; nt++) {
                    int n0 = nh2 * 16 + nt * 8 + g;
                    uint2 pk = ldp(WB + 2304 + n0 * 72 + ko);
                    uint2 pv = ldp(WB + 4608 + n0 * 72 + ko);
                    mma8(aK[nt], pa0.x, pa1.x, pa0.y, pa1.y, pk.x, pk.y);
                    mma8(aV[nt], pa0.x, pa1.x, pa0.y, pa1.y, pv.x, pv.y);
                }
            }
            #pragma unroll
            for (int nt = 0; nt < 2; nt++) {
                int c0 = nh2 * 16 + nt * 8 + 2 * t4;
                int p0 = cperm(c0), p1 = cperm(c0 + 1);
                Kh[r0 * 40 + p0] = tfs(aK[nt][0]);
                Kh[r0 * 40 + p1] = tfs(aK[nt][1]);
                Kh[r1 * 40 + p0] = tfs(aK[nt][2]);
                Kh[r1 * 40 + p1] = tfs(aK[nt][3]);
                int pr0 = mt8 * 16 + PI8(g), pr1 = pr0 + 8;   // Vt transposed
                Vt[(c0    ) * 136 + pr0] = tfs(aV[nt][0]);
                Vt[(c0 + 1) * 136 + pr0] = tfs(aV[nt][1]);
                Vt[(c0    ) * 136 + pr1] = tfs(aV[nt][2]);
                Vt[(c0 + 1) * 136 + pr1] = tfs(aV[nt][3]);
            }
        }
        // Q projection: M=128 N=32 K=64, warp tile 16x16 (nt=2)
        {
            float acc[2][4];
            #pragma unroll
            for (int nt = 0; nt < 2; nt++) {
                int c0 = nh2 * 16 + nt * 8 + 2 * t4;
                acc[nt][0] = Bs[hb + c0]; acc[nt][1] = Bs[hb + c0 + 1];
                acc[nt][2] = acc[nt][0];  acc[nt][3] = acc[nt][1];
            }
            #pragma unroll
            for (int kt = 0; kt < 8; kt++) {
                int ko = kt * 8 + 2 * t4;
                uint2 pa0 = ldp(Xs + r0 * 72 + ko);
                uint2 pa1 = ldp(Xs + r1 * 72 + ko);
                #pragma unroll
                for (int nt = 0; nt < 2; nt++) {
                    int n0 = nh2 * 16 + nt * 8 + g;
                    uint2 pb = ldp(WB + n0 * 72 + ko);
                    mma8(acc[nt], pa0.x, pa1.x, pa0.y, pa1.y, pb.x, pb.y);
                }
            }
            #pragma unroll
            for (int nt = 0; nt < 2; nt++) {
                int c0 = nh2 * 16 + nt * 8 + 2 * t4;
                int p0 = cperm(c0), p1 = cperm(c0 + 1);
                Qh[r0 * 40 + p0] = tfs(acc[nt][0] * QSCALE);
                Qh[r0 * 40 + p1] = tfs(acc[nt][1] * QSCALE);
                Qh[r1 * 40 + p0] = tfs(acc[nt][2] * QSCALE);
                Qh[r1 * 40 + p1] = tfs(acc[nt][3] * QSCALE);
            }
        }
        __syncthreads();

        // scores: M=128 N=128 K=32, warp tile 16x64 (nt=8)
        {
            float acc[8][4] = {};
            #pragma unroll
            for (int kt = 0; kt < 4; kt++) {
                int ko = kt * 8 + 2 * t4;
                uint2 pa0 = ldp(Qh + r0 * 40 + ko);
                uint2 pa1 = ldp(Qh + r1 * 40 + ko);
                #pragma unroll
                for (int nt = 0; nt < 8; nt++) {
                    int s0 = nh2 * 64 + nt * 8 + g;
                    uint2 pb = ldp(Kh + s0 * 40 + ko);
                    mma8(acc[nt], pa0.x, pa1.x, pa0.y, pa1.y, pb.x, pb.y);
                }
            }
            #pragma unroll
            for (int nt = 0; nt < 8; nt++) {
                int c0 = nh2 * 64 + nt * 8 + 2 * t4;
                Ss[r0 * 136 + c0]     = acc[nt][0];
                Ss[r0 * 136 + c0 + 1] = acc[nt][1];
                Ss[r1 * 136 + c0]     = acc[nt][2];
                Ss[r1 * 136 + c0 + 1] = acc[nt][3];
            }
        }
        __syncthreads();
        // softmax: 128 rows x 128 cols
        for (int r = warp; r < 128; r += 16) {
            float v0 = Ss[r * 136 + lane];
            float v1 = Ss[r * 136 + 32 + lane];
            float v2 = Ss[r * 136 + 64 + lane];
            float v3 = Ss[r * 136 + 96 + lane];
            float mx = fmaxf(fmaxf(v0, v1), fmaxf(v2, v3));
            #pragma unroll
            for (int o = 16; o > 0; o >>= 1)
                mx = fmaxf(mx, __shfl_xor_sync(0xffffffffu, mx, o));
            float e0 = __expf(v0 - mx), e1 = __expf(v1 - mx);
            float e2 = __expf(v2 - mx), e3 = __expf(v3 - mx);
            float su = (e0 + e1) + (e2 + e3);
            #pragma unroll
            for (int o = 16; o > 0; o >>= 1)
                su += __shfl_xor_sync(0xffffffffu, su, o);
            float inv = __frcp_rn(su);
            Ss[r * 136 + cperm(lane)]      = tfs(e0 * inv);
            Ss[r * 136 + cperm(32 + lane)] = tfs(e1 * inv);
            Ss[r * 136 + cperm(64 + lane)] = tfs(e2 * inv);
            Ss[r * 136 + cperm(96 + lane)] = tfs(e3 * inv);
        }
        __syncthreads();
        // AV: M=128 N=32 K=128, warp tile 16x16 (nt=2) -> Oh
        {
            float acc[2][4] = {};
            #pragma unroll
            for (int kt = 0; kt < 16; kt++) {
                int ko = kt * 8 + 2 * t4;
                uint2 pa0 = ldp(Ss + r0 * 136 + ko);
                uint2 pa1 = ldp(Ss + r1 * 136 + ko);
                #pragma unroll
                for (int nt = 0; nt < 2; nt++) {
                    int n0 = nh2 * 16 + nt * 8 + g;
                    uint2 pb = ldp(Vt + n0 * 136 + ko);
                    mma8(acc[nt], pa0.x, pa1.x, pa0.y, pa1.y, pb.x, pb.y);
                }
            }
            #pragma unroll
            for (int nt = 0; nt < 2; nt++) {
                int c0 = nh2 * 16 + nt * 8 + 2 * t4;
                int p0 = cperm(c0), p1 = cperm(c0 + 1);
                Oh[r0 * 40 + p0] = tfs(acc[nt][0]);
                Oh[r0 * 40 + p1] = tfs(acc[nt][1]);
                Oh[r1 * 40 + p0] = tfs(acc[nt][2]);
                Oh[r1 * 40 + p1] = tfs(acc[nt][3]);
            }
        }
        __syncthreads();
        // out-proj partial: M=128 N=64 K=32, warp tile 16x32 (nt=4), reg acc
        {
            #pragma unroll
            for (int kt = 0; kt < 4; kt++) {
                int ko = kt * 8 + 2 * t4;
                uint2 pa0 = ldp(Oh + r0 * 40 + ko);
                uint2 pa1 = ldp(Oh + r1 * 40 + ko);
                #pragma unroll
                for (int nt = 0; nt < 4; nt++) {
                    int n0 = nh2 * 32 + nt * 8 + g;
                    uint2 pb = ldp(WoS + n0 * 40 + ko);
                    mma8(pacc[nt], pa0.x, pa1.x, pa0.y, pa1.y, pb.x, pb.y);
                }
            }
        }
    }

    // epilogue: out[b,t,fr,d] += pacc + bo
    #pragma unroll
    for (int nt = 0; nt < 4; nt++) {
        int d0 = nh2 * 32 + nt * 8 + 2 * t4;
        float b0 = Bs[384 + d0], b1 = Bs[384 + d0 + 1];
        float2* p0 = (float2*)(out + (((size_t)(b * 64 + t) * 128 + r0) * 64 + d0));
        float2* p1 = (float2*)(out + (((size_t)(b * 64 + t) * 128 + r1) * 64 + d0));
        float2 v0 = *p0, v1 = *p1;
        v0.x += pacc[nt][0] + b0; v0.y += pacc[nt][1] + b1;
        v1.x += pacc[nt][2] + b0; v1.y += pacc[nt][3] + b1;
        *p0 = v0; *p1 = v1;
    }
}

// ---------------------------------------------------------------------------
extern "C" void kernel_launch(void* const* d_in, const int* in_sizes, int n_in,
                              void* d_out, int out_size)
{
    const float* x = (const float*)d_in[0];
    const float *tqw, *tqb, *tkw, *tkb, *tvw, *tvb, *tow, *tob;
    const float *fqw, *fqb, *fkw, *fkb, *fvw, *fvb, *fow, *fob;

    if (in_sizes[8] == 64) {   // reference-signature order
        tqw = (const float*)d_in[1];  tqb = (const float*)d_in[2];
        tkw = (const float*)d_in[3];  tkb = (const float*)d_in[4];
        tvw = (const float*)d_in[5];  tvb = (const float*)d_in[6];
        tow = (const float*)d_in[7];  tob = (const float*)d_in[8];
        fqw = (const float*)d_in[9];  fqb = (const float*)d_in[10];
        fkw = (const float*)d_in[11]; fkb = (const float*)d_in[12];
        fvw = (const float*)d_in[13]; fvb = (const float*)d_in[14];
        fow = (const float*)d_in[15]; fob = (const float*)d_in[16];
    } else {                    // setup_inputs dict order
        tqw = (const float*)d_in[1];  tqb = (const float*)d_in[2];
        tkw = (const float*)d_in[3];  tkb = (const float*)d_in[4];
        tvw = (const float*)d_in[5];  tvb = (const float*)d_in[6];
        fqw = (const float*)d_in[7];  fqb = (const float*)d_in[8];
        fkw = (const float*)d_in[9];  fkb = (const float*)d_in[10];
        fvw = (const float*)d_in[11]; fvb = (const float*)d_in[12];
        tow = (const float*)d_in[13]; tob = (const float*)d_in[14];
        fow = (const float*)d_in[15]; fob = (const float*)d_in[16];
    }

    float* out = (float*)d_out;

    const size_t sm_t = 54208 * sizeof(float);   // 216832 B
    const size_t sm_f = 56256 * sizeof(float);   // 225024 B

    cudaFuncSetAttribute(temporal_kernel,
                         cudaFuncAttributeMaxDynamicSharedMemorySize, (int)sm_t);
    cudaFuncSetAttribute(feature_kernel,
                         cudaFuncAttributeMaxDynamicSharedMemorySize, (int)sm_f);

    temporal_kernel<<<32 * 128, 512, sm_t>>>(x, tqw, tqb, tkw, tkb, tvw, tvb,
                                             tow, tob, out);
    feature_kernel<<<32 * 64, 512, sm_f>>>(x, fqw, fqb, fkw, fkb, fvw, fvb,
                                           fow, fob, out);
}

// round 8
// speedup vs baseline: 7.3698x; 1.0796x over previous
#include <cuda_runtime.h>

#define QSCALE 0.17677669529663687f  // 1/sqrt(32)

__device__ __forceinline__ unsigned f2tf(float f) {
    unsigned u;
    asm("cvt.rna.tf32.f32 %0, %1;" : "=r"(u) : "f"(f));
    return u;
}
__device__ __forceinline__ float tfs(float f) {   // tf32 bits as float for smem store
    return __uint_as_float(f2tf(f));
}
// column permutation within an 8-slab: logical c -> phys, pairs (t4, t4+4) adjacent
__device__ __forceinline__ int PI8(int s) { return ((s & 3) << 1) | ((s >> 2) & 1); }
__device__ __forceinline__ int cperm(int c) { return (c & ~7) | PI8(c & 7); }

__device__ __forceinline__ uint2 ldp(const float* p) { return *(const uint2*)p; }

__device__ __forceinline__ void mma8(float* c,
    unsigned a0, unsigned a1, unsigned a2, unsigned a3,
    unsigned b0, unsigned b1)
{
    asm volatile(
        "mma.sync.aligned.m16n8k8.row.col.f32.tf32.tf32.f32 "
        "{%0,%1,%2,%3}, {%4,%5,%6,%7}, {%8,%9}, {%0,%1,%2,%3};"
        : "+f"(c[0]), "+f"(c[1]), "+f"(c[2]), "+f"(c[3])
        : "r"(a0), "r"(a1), "r"(a2), "r"(a3), "r"(b0), "r"(b1));
}

// ---------------------------------------------------------------------------
// Temporal branch v2: ONE CTA per (b, f-pair). M=128 rows = two 64-row
// t-blocks (f = 2*fp + fb, fb = row>>6). Attention is block-diagonal.
// 512 threads / 16 warps (8 m-tiles x 2 n-groups). Per-head weight slices,
// fused Q/K/V projection, register-resident out-projection accumulators.
// smem floats: Xs[128][72]=9216 Kh[128][40]=5120 Vt[32][136]=4352
//   Qh[128][40]=5120 Ss[128][72]=9216 Oh[128][40]=5120 WB=6912 WoS=2560
//   Bs=448   total 48064 (192.3 KB)
// ---------------------------------------------------------------------------
__global__ void __launch_bounds__(512) temporal_kernel(
    const float* __restrict__ x,
    const float* __restrict__ wq, const float* __restrict__ bq,
    const float* __restrict__ wk, const float* __restrict__ bk,
    const float* __restrict__ wv, const float* __restrict__ bv,
    const float* __restrict__ wo, const float* __restrict__ bo,
    float* __restrict__ out)
{
    extern __shared__ float sm[];
    float* Xs  = sm;            // 9216  [row][d perm] ld 72
    float* Kh  = sm + 9216;     // 5120  [row][k=32 perm] ld 40
    float* Vt  = sm + 14336;    // 4352  [k=32][row perm] ld 136
    float* Qh  = sm + 18688;    // 5120  [row][k=32 perm] ld 40
    float* Ss  = sm + 23808;    // 9216  [row][s=64] ld 72
    float* Oh  = sm + 33024;    // 5120  [row][k=32 perm] ld 40
    float* WB  = sm + 38144;    // 6912  3 x [n=32][k=64 perm] ld 72
    float* WoS = sm + 45056;    // 2560  [d=64][k=32 perm] ld 40
    float* Bs  = sm + 47616;    // 448

    const int tid  = threadIdx.x;
    const int lane = tid & 31, warp = tid >> 5;
    const int g = lane >> 2, t4 = lane & 3;
    const int b = blockIdx.x >> 6, fp = blockIdx.x & 63;

    // X slices: row = fb*64 + t -> x[b, t, 2*fp+fb, :]
    {
        const float4* x4 = (const float4*)x;
        for (int i = tid; i < 2048; i += 512) {
            int row = i >> 4, c = i & 15;
            int fb = row >> 6, t = row & 63;
            int f = fp * 2 + fb;
            float4 v = x4[(((b * 64 + t) * 128 + f) << 4) + c];
            float* d = Xs + row * 72;
            d[cperm(4 * c + 0)] = tfs(v.x);
            d[cperm(4 * c + 1)] = tfs(v.y);
            d[cperm(4 * c + 2)] = tfs(v.z);
            d[cperm(4 * c + 3)] = tfs(v.w);
        }
    }
    if (tid < 448) {
        float v;
        if      (tid < 128) v = bq[tid];
        else if (tid < 256) v = bk[tid - 128];
        else if (tid < 384) v = bv[tid - 256];
        else                v = bo[tid - 384];
        Bs[tid] = v;
    }

    const int mt8 = warp & 7, nh2 = warp >> 3;
    const int r0 = mt8 * 16 + g, r1 = r0 + 8;
    const int blk = mt8 >> 2;          // f-block of this warp's m-tile

    float pacc[4][4] = {};             // persistent out-proj accumulators

    for (int h = 0; h < 4; h++) {
        const int hb = h * 32;
        __syncthreads();   // prev head's WB/WoS readers done; Xs/Bs at h=0
        // stage per-head weight slices: Wq@0 Wk@2304 Wv@4608, [n=32][k=64 perm]
        for (int i = tid; i < 6144; i += 512) {
            int m = i >> 11, r = i & 2047;
            int n = r & 31, d = r >> 5;
            const float* w = (m == 0) ? wq : (m == 1) ? wk : wv;
            WB[m * 2304 + n * 72 + cperm(d)] = tfs(w[d * 128 + hb + n]);
        }
        for (int i = tid; i < 2048; i += 512) {
            int k = i >> 6, d = i & 63;
            WoS[d * 40 + cperm(k)] = tfs(wo[(hb + k) * 64 + d]);
        }
        __syncthreads();

        // fused Q/K/V projections: M=128 N=32 K=64, warp tile 16x16 (nt=2)
        {
            float aQ[2][4], aK[2][4], aV[2][4];
            #pragma unroll
            for (int nt = 0; nt < 2; nt++) {
                int c0 = nh2 * 16 + nt * 8 + 2 * t4;
                aQ[nt][0] = Bs[hb + c0];       aQ[nt][1] = Bs[hb + c0 + 1];
                aQ[nt][2] = aQ[nt][0];         aQ[nt][3] = aQ[nt][1];
                aK[nt][0] = Bs[128 + hb + c0]; aK[nt][1] = Bs[128 + hb + c0 + 1];
                aK[nt][2] = aK[nt][0];         aK[nt][3] = aK[nt][1];
                aV[nt][0] = Bs[256 + hb + c0]; aV[nt][1] = Bs[256 + hb + c0 + 1];
                aV[nt][2] = aV[nt][0];         aV[nt][3] = aV[nt][1];
            }
            #pragma unroll
            for (int kt = 0; kt < 8; kt++) {
                int ko = kt * 8 + 2 * t4;
                uint2 pa0 = ldp(Xs + r0 * 72 + ko);
                uint2 pa1 = ldp(Xs + r1 * 72 + ko);
                #pragma unroll
                for (int nt = 0; nt < 2; nt++) {
                    int n0 = nh2 * 16 + nt * 8 + g;
                    uint2 pq = ldp(WB +        n0 * 72 + ko);
                    uint2 pk = ldp(WB + 2304 + n0 * 72 + ko);
                    uint2 pv = ldp(WB + 4608 + n0 * 72 + ko);
                    mma8(aQ[nt], pa0.x, pa1.x, pa0.y, pa1.y, pq.x, pq.y);
                    mma8(aK[nt], pa0.x, pa1.x, pa0.y, pa1.y, pk.x, pk.y);
                    mma8(aV[nt], pa0.x, pa1.x, pa0.y, pa1.y, pv.x, pv.y);
                }
            }
            #pragma unroll
            for (int nt = 0; nt < 2; nt++) {
                int c0 = nh2 * 16 + nt * 8 + 2 * t4;
                int p0 = cperm(c0), p1 = cperm(c0 + 1);
                Qh[r0 * 40 + p0] = tfs(aQ[nt][0] * QSCALE);
                Qh[r0 * 40 + p1] = tfs(aQ[nt][1] * QSCALE);
                Qh[r1 * 40 + p0] = tfs(aQ[nt][2] * QSCALE);
                Qh[r1 * 40 + p1] = tfs(aQ[nt][3] * QSCALE);
                Kh[r0 * 40 + p0] = tfs(aK[nt][0]);
                Kh[r0 * 40 + p1] = tfs(aK[nt][1]);
                Kh[r1 * 40 + p0] = tfs(aK[nt][2]);
                Kh[r1 * 40 + p1] = tfs(aK[nt][3]);
                int pr0 = mt8 * 16 + PI8(g), pr1 = pr0 + 8;   // Vt transposed
                Vt[(c0    ) * 136 + pr0] = tfs(aV[nt][0]);
                Vt[(c0 + 1) * 136 + pr0] = tfs(aV[nt][1]);
                Vt[(c0    ) * 136 + pr1] = tfs(aV[nt][2]);
                Vt[(c0 + 1) * 136 + pr1] = tfs(aV[nt][3]);
            }
        }
        __syncthreads();

        // scores: per f-block, M=128 N=64(own block) K=32, warp tile 16x32
        {
            float acc[4][4] = {};
            const int sbase = blk * 64;
            #pragma unroll
            for (int kt = 0; kt < 4; kt++) {
                int ko = kt * 8 + 2 * t4;
                uint2 pa0 = ldp(Qh + r0 * 40 + ko);
                uint2 pa1 = ldp(Qh + r1 * 40 + ko);
                #pragma unroll
                for (int nt = 0; nt < 4; nt++) {
                    int s0 = sbase + nh2 * 32 + nt * 8 + g;
                    uint2 pb = ldp(Kh + s0 * 40 + ko);
                    mma8(acc[nt], pa0.x, pa1.x, pa0.y, pa1.y, pb.x, pb.y);
                }
            }
            #pragma unroll
            for (int nt = 0; nt < 4; nt++) {
                int c0 = nh2 * 32 + nt * 8 + 2 * t4;
                Ss[r0 * 72 + c0]     = acc[nt][0];
                Ss[r0 * 72 + c0 + 1] = acc[nt][1];
                Ss[r1 * 72 + c0]     = acc[nt][2];
                Ss[r1 * 72 + c0 + 1] = acc[nt][3];
            }
        }
        __syncthreads();
        // softmax: 128 rows x 64 cols
        for (int r = warp; r < 128; r += 16) {
            float v0 = Ss[r * 72 + lane], v1 = Ss[r * 72 + 32 + lane];
            float mx = fmaxf(v0, v1);
            #pragma unroll
            for (int o = 16; o > 0; o >>= 1)
                mx = fmaxf(mx, __shfl_xor_sync(0xffffffffu, mx, o));
            float e0 = __expf(v0 - mx), e1 = __expf(v1 - mx);
            float su = e0 + e1;
            #pragma unroll
            for (int o = 16; o > 0; o >>= 1)
                su += __shfl_xor_sync(0xffffffffu, su, o);
            float inv = __frcp_rn(su);
            Ss[r * 72 + cperm(lane)]      = tfs(e0 * inv);
            Ss[r * 72 + cperm(32 + lane)] = tfs(e1 * inv);
        }
        __syncthreads();
        // AV: M=128 N=32 K=64(own block), warp tile 16x16 (nt=2) -> Oh
        {
            float acc[2][4] = {};
            const int kbase = blk * 64;
            #pragma unroll
            for (int kt = 0; kt < 8; kt++) {
                int ko = kt * 8 + 2 * t4;
                uint2 pa0 = ldp(Ss + r0 * 72 + ko);
                uint2 pa1 = ldp(Ss + r1 * 72 + ko);
                #pragma unroll
                for (int nt = 0; nt < 2; nt++) {
                    int n0 = nh2 * 16 + nt * 8 + g;
                    uint2 pb = ldp(Vt + n0 * 136 + kbase + ko);
                    mma8(acc[nt], pa0.x, pa1.x, pa0.y, pa1.y, pb.x, pb.y);
                }
            }
            #pragma unroll
            for (int nt = 0; nt < 2; nt++) {
                int c0 = nh2 * 16 + nt * 8 + 2 * t4;
                int p0 = cperm(c0), p1 = cperm(c0 + 1);
                Oh[r0 * 40 + p0] = tfs(acc[nt][0]);
                Oh[r0 * 40 + p1] = tfs(acc[nt][1]);
                Oh[r1 * 40 + p0] = tfs(acc[nt][2]);
                Oh[r1 * 40 + p1] = tfs(acc[nt][3]);
            }
        }
        __syncthreads();
        // out-proj partial: M=128 N=64 K=32, warp tile 16x32 (nt=4), reg acc
        #pragma unroll
        for (int kt = 0; kt < 4; kt++) {
            int ko = kt * 8 + 2 * t4;
            uint2 pa0 = ldp(Oh + r0 * 40 + ko);
            uint2 pa1 = ldp(Oh + r1 * 40 + ko);
            #pragma unroll
            for (int nt = 0; nt < 4; nt++) {
                int n0 = nh2 * 32 + nt * 8 + g;
                uint2 pb = ldp(WoS + n0 * 40 + ko);
                mma8(pacc[nt], pa0.x, pa1.x, pa0.y, pa1.y, pb.x, pb.y);
            }
        }
    }

    // epilogue: out[b, t, 2*fp+fb, d] = pacc + bo   (overwrite)
    {
        int fb = r0 >> 6, t0 = r0 & 63, t1 = r1 & 63;
        int f = fp * 2 + fb;
        #pragma unroll
        for (int nt = 0; nt < 4; nt++) {
            int d0 = nh2 * 32 + nt * 8 + 2 * t4;
            float b0 = Bs[384 + d0], b1 = Bs[384 + d0 + 1];
            float2* p0 = (float2*)(out + (((size_t)(b * 64 + t0) * 128 + f) * 64 + d0));
            float2* p1 = (float2*)(out + (((size_t)(b * 64 + t1) * 128 + f) * 64 + d0));
            *p0 = make_float2(pacc[nt][0] + b0, pacc[nt][1] + b1);
            *p1 = make_float2(pacc[nt][2] + b0, pacc[nt][3] + b1);
        }
    }
}

// ---------------------------------------------------------------------------
// Feature branch v2 (unchanged from R6): ONE CTA per (b,t), 128 q-rows.
// ---------------------------------------------------------------------------
__global__ void __launch_bounds__(512) feature_kernel(
    const float* __restrict__ x,
    const float* __restrict__ wq, const float* __restrict__ bq,
    const float* __restrict__ wk, const float* __restrict__ bk,
    const float* __restrict__ wv, const float* __restrict__ bv,
    const float* __restrict__ wo, const float* __restrict__ bo,
    float* __restrict__ out)
{
    extern __shared__ float sm[];
    float* Xs  = sm;            // 9216
    float* Kh  = sm + 9216;     // 5120
    float* Vt  = sm + 14336;    // 4352
    float* Qh  = sm + 18688;    // 5120
    float* Ss  = sm + 23808;    // 17408
    float* Oh  = sm + 41216;    // 5120
    float* WB  = sm + 46336;    // 6912
    float* WoS = sm + 53248;    // 2560
    float* Bs  = sm + 55808;    // 448

    const int tid  = threadIdx.x;
    const int lane = tid & 31, warp = tid >> 5;
    const int g = lane >> 2, t4 = lane & 3;
    const int b = blockIdx.x >> 6, t = blockIdx.x & 63;

    {
        const float4* x4 = (const float4*)(x + (size_t)(b * 64 + t) * 128 * 64);
        for (int i = tid; i < 2048; i += 512) {
            int fr = i >> 4, c = i & 15;
            float4 v = x4[i];
            float* d = Xs + fr * 72;
            d[cperm(4 * c + 0)] = tfs(v.x);
            d[cperm(4 * c + 1)] = tfs(v.y);
            d[cperm(4 * c + 2)] = tfs(v.z);
            d[cperm(4 * c + 3)] = tfs(v.w);
        }
    }
    if (tid < 448) {
        float v;
        if      (tid < 128) v = bq[tid];
        else if (tid < 256) v = bk[tid - 128];
        else if (tid < 384) v = bv[tid - 256];
        else                v = bo[tid - 384];
        Bs[tid] = v;
    }

    const int mt8 = warp & 7, nh2 = warp >> 3;
    const int r0 = mt8 * 16 + g, r1 = r0 + 8;

    float pacc[4][4] = {};

    for (int h = 0; h < 4; h++) {
        const int hb = h * 32;
        __syncthreads();
        for (int i = tid; i < 6144; i += 512) {
            int m = i >> 11, r = i & 2047;
            int ko = r & 31, d = r >> 5;
            const float* w = (m == 0) ? wq : (m == 1) ? wk : wv;
            WB[m * 2304 + ko * 72 + cperm(d)] = tfs(w[d * 128 + hb + ko]);
        }
        for (int i = tid; i < 2048; i += 512) {
            int k = i >> 6, d = i & 63;
            WoS[d * 40 + cperm(k)] = tfs(wo[(hb + k) * 64 + d]);
        }
        __syncthreads();

        {
            float aK[2][4], aV[2][4];
            #pragma unroll
            for (int nt = 0; nt < 2; nt++) {
                int c0 = nh2 * 16 + nt * 8 + 2 * t4;
                aK[nt][0] = Bs[128 + hb + c0]; aK[nt][1] = Bs[128 + hb + c0 + 1];
                aK[nt][2] = aK[nt][0];         aK[nt][3] = aK[nt][1];
                aV[nt][0] = Bs[256 + hb + c0]; aV[nt][1] = Bs[256 + hb + c0 + 1];
                aV[nt][2] = aV[nt][0];         aV[nt][3] = aV[nt][1];
            }
            #pragma unroll
            for (int kt = 0; kt < 8; kt++) {
                int ko = kt * 8 + 2 * t4;
                uint2 pa0 = ldp(Xs + r0 * 72 + ko);
                uint2 pa1 = ldp(Xs + r1 * 72 + ko);
                #pragma unroll
                for (int nt = 0; nt < 2; nt++) {
                    int n0 = nh2 * 16 + nt * 8 + g;
                    uint2 pk = ldp(WB + 2304 + n0 * 72 + ko);
                    uint2 pv = ldp(WB + 4608 + n0 * 72 + ko);
                    mma8(aK[nt], pa0.x, pa1.x, pa0.y, pa1.y, pk.x, pk.y);
                    mma8(aV[nt], pa0.x, pa1.x, pa0.y, pa1.y, pv.x, pv.y);
                }
            }
            #pragma unroll
            for (int nt = 0; nt < 2; nt++) {
                int c0 = nh2 * 16 + nt * 8 + 2 * t4;
                int p0 = cperm(c0), p1 = cperm(c0 + 1);
                Kh[r0 * 40 + p0] = tfs(aK[nt][0]);
                Kh[r0 * 40 + p1] = tfs(aK[nt][1]);
                Kh[r1 * 40 + p0] = tfs(aK[nt][2]);
                Kh[r1 * 40 + p1] = tfs(aK[nt][3]);
                int pr0 = mt8 * 16 + PI8(g), pr1 = pr0 + 8;
                Vt[(c0    ) * 136 + pr0] = tfs(aV[nt][0]);
                Vt[(c0 + 1) * 136 + pr0] = tfs(aV[nt][1]);
                Vt[(c0    ) * 136 + pr1] = tfs(aV[nt][2]);
                Vt[(c0 + 1) * 136 + pr1] = tfs(aV[nt][3]);
            }
        }
        {
            float acc[2][4];
            #pragma unroll
            for (int nt = 0; nt < 2; nt++) {
                int c0 = nh2 * 16 + nt * 8 + 2 * t4;
                acc[nt][0] = Bs[hb + c0]; acc[nt][1] = Bs[hb + c0 + 1];
                acc[nt][2] = acc[nt][0];  acc[nt][3] = acc[nt][1];
            }
            #pragma unroll
            for (int kt = 0; kt < 8; kt++) {
                int ko = kt * 8 + 2 * t4;
                uint2 pa0 = ldp(Xs + r0 * 72 + ko);
                uint2 pa1 = ldp(Xs + r1 * 72 + ko);
                #pragma unroll
                for (int nt = 0; nt < 2; nt++) {
                    int n0 = nh2 * 16 + nt * 8 + g;
                    uint2 pb = ldp(WB + n0 * 72 + ko);
                    mma8(acc[nt], pa0.x, pa1.x, pa0.y, pa1.y, pb.x, pb.y);
                }
            }
            #pragma unroll
            for (int nt = 0; nt < 2; nt++) {
                int c0 = nh2 * 16 + nt * 8 + 2 * t4;
                int p0 = cperm(c0), p1 = cperm(c0 + 1);
                Qh[r0 * 40 + p0] = tfs(acc[nt][0] * QSCALE);
                Qh[r0 * 40 + p1] = tfs(acc[nt][1] * QSCALE);
                Qh[r1 * 40 + p0] = tfs(acc[nt][2] * QSCALE);
                Qh[r1 * 40 + p1] = tfs(acc[nt][3] * QSCALE);
            }
        }
        __syncthreads();

        {
            float acc[8][4] = {};
            #pragma unroll
            for (int kt = 0; kt < 4; kt++) {
                int ko = kt * 8 + 2 * t4;
                uint2 pa0 = ldp(Qh + r0 * 40 + ko);
                uint2 pa1 = ldp(Qh + r1 * 40 + ko);
                #pragma unroll
                for (int nt = 0; nt < 8; nt++) {
                    int s0 = nh2 * 64 + nt * 8 + g;
                    uint2 pb = ldp(Kh + s0 * 40 + ko);
                    mma8(acc[nt], pa0.x, pa1.x, pa0.y, pa1.y, pb.x, pb.y);
                }
            }
            #pragma unroll
            for (int nt = 0; nt < 8; nt++) {
                int c0 = nh2 * 64 + nt * 8 + 2 * t4;
                Ss[r0 * 136 + c0]     = acc[nt][0];
                Ss[r0 * 136 + c0 + 1] = acc[nt][1];
                Ss[r1 * 136 + c0]     = acc[nt][2];
                Ss[r1 * 136 + c0 + 1] = acc[nt][3];
            }
        }
        __syncthreads();
        for (int r = warp; r < 128; r += 16) {
            float v0 = Ss[r * 136 + lane];
            float v1 = Ss[r * 136 + 32 + lane];
            float v2 = Ss[r * 136 + 64 + lane];
            float v3 = Ss[r * 136 + 96 + lane];
            float mx = fmaxf(fmaxf(v0, v1), fmaxf(v2, v3));
            #pragma unroll
            for (int o = 16; o > 0; o >>= 1)
                mx = fmaxf(mx, __shfl_xor_sync(0xffffffffu, mx, o));
            float e0 = __expf(v0 - mx), e1 = __expf(v1 - mx);
            float e2 = __expf(v2 - mx), e3 = __expf(v3 - mx);
            float su = (e0 + e1) + (e2 + e3);
            #pragma unroll
            for (int o = 16; o > 0; o >>= 1)
                su += __shfl_xor_sync(0xffffffffu, su, o);
            float inv = __frcp_rn(su);
            Ss[r * 136 + cperm(lane)]      = tfs(e0 * inv);
            Ss[r * 136 + cperm(32 + lane)] = tfs(e1 * inv);
            Ss[r * 136 + cperm(64 + lane)] = tfs(e2 * inv);
            Ss[r * 136 + cperm(96 + lane)] = tfs(e3 * inv);
        }
        __syncthreads();
        {
            float acc[2][4] = {};
            #pragma unroll
            for (int kt = 0; kt < 16; kt++) {
                int ko = kt * 8 + 2 * t4;
                uint2 pa0 = ldp(Ss + r0 * 136 + ko);
                uint2 pa1 = ldp(Ss + r1 * 136 + ko);
                #pragma unroll
                for (int nt = 0; nt < 2; nt++) {
                    int n0 = nh2 * 16 + nt * 8 + g;
                    uint2 pb = ldp(Vt + n0 * 136 + ko);
                    mma8(acc[nt], pa0.x, pa1.x, pa0.y, pa1.y, pb.x, pb.y);
                }
            }
            #pragma unroll
            for (int nt = 0; nt < 2; nt++) {
                int c0 = nh2 * 16 + nt * 8 + 2 * t4;
                int p0 = cperm(c0), p1 = cperm(c0 + 1);
                Oh[r0 * 40 + p0] = tfs(acc[nt][0]);
                Oh[r0 * 40 + p1] = tfs(acc[nt][1]);
                Oh[r1 * 40 + p0] = tfs(acc[nt][2]);
                Oh[r1 * 40 + p1] = tfs(acc[nt][3]);
            }
        }
        __syncthreads();
        #pragma unroll
        for (int kt = 0; kt < 4; kt++) {
            int ko = kt * 8 + 2 * t4;
            uint2 pa0 = ldp(Oh + r0 * 40 + ko);
            uint2 pa1 = ldp(Oh + r1 * 40 + ko);
            #pragma unroll
            for (int nt = 0; nt < 4; nt++) {
                int n0 = nh2 * 32 + nt * 8 + g;
                uint2 pb = ldp(WoS + n0 * 40 + ko);
                mma8(pacc[nt], pa0.x, pa1.x, pa0.y, pa1.y, pb.x, pb.y);
            }
        }
    }

    #pragma unroll
    for (int nt = 0; nt < 4; nt++) {
        int d0 = nh2 * 32 + nt * 8 + 2 * t4;
        float b0 = Bs[384 + d0], b1 = Bs[384 + d0 + 1];
        float2* p0 = (float2*)(out + (((size_t)(b * 64 + t) * 128 + r0) * 64 + d0));
        float2* p1 = (float2*)(out + (((size_t)(b * 64 + t) * 128 + r1) * 64 + d0));
        float2 v0 = *p0, v1 = *p1;
        v0.x += pacc[nt][0] + b0; v0.y += pacc[nt][1] + b1;
        v1.x += pacc[nt][2] + b0; v1.y += pacc[nt][3] + b1;
        *p0 = v0; *p1 = v1;
    }
}

// ---------------------------------------------------------------------------
extern "C" void kernel_launch(void* const* d_in, const int* in_sizes, int n_in,
                              void* d_out, int out_size)
{
    const float* x = (const float*)d_in[0];
    const float *tqw, *tqb, *tkw, *tkb, *tvw, *tvb, *tow, *tob;
    const float *fqw, *fqb, *fkw, *fkb, *fvw, *fvb, *fow, *fob;

    if (in_sizes[8] == 64) {   // reference-signature order
        tqw = (const float*)d_in[1];  tqb = (const float*)d_in[2];
        tkw = (const float*)d_in[3];  tkb = (const float*)d_in[4];
        tvw = (const float*)d_in[5];  tvb = (const float*)d_in[6];
        tow = (const float*)d_in[7];  tob = (const float*)d_in[8];
        fqw = (const float*)d_in[9];  fqb = (const float*)d_in[10];
        fkw = (const float*)d_in[11]; fkb = (const float*)d_in[12];
        fvw = (const float*)d_in[13]; fvb = (const float*)d_in[14];
        fow = (const float*)d_in[15]; fob = (const float*)d_in[16];
    } else {                    // setup_inputs dict order
        tqw = (const float*)d_in[1];  tqb = (const float*)d_in[2];
        tkw = (const float*)d_in[3];  tkb = (const float*)d_in[4];
        tvw = (const float*)d_in[5];  tvb = (const float*)d_in[6];
        fqw = (const float*)d_in[7];  fqb = (const float*)d_in[8];
        fkw = (const float*)d_in[9];  fkb = (const float*)d_in[10];
        fvw = (const float*)d_in[11]; fvb = (const float*)d_in[12];
        tow = (const float*)d_in[13]; tob = (const float*)d_in[14];
        fow = (const float*)d_in[15]; fob = (const float*)d_in[16];
    }

    float* out = (float*)d_out;

    const size_t sm_t = 48064 * sizeof(float);   // 192256 B
    const size_t sm_f = 56256 * sizeof(float);   // 225024 B

    cudaFuncSetAttribute(temporal_kernel,
                         cudaFuncAttributeMaxDynamicSharedMemorySize, (int)sm_t);
    cudaFuncSetAttribute(feature_kernel,
                         cudaFuncAttributeMaxDynamicSharedMemorySize, (int)sm_f);

    temporal_kernel<<<32 * 64, 512, sm_t>>>(x, tqw, tqb, tkw, tkb, tvw, tvb,
                                            tow, tob, out);
    feature_kernel<<<32 * 64, 512, sm_f>>>(x, fqw, fqb, fkw, fkb, fvw, fvb,
                                           fow, fob, out);
}

// round 9
// speedup vs baseline: 7.4997x; 1.0176x over previous
#include <cuda_runtime.h>

#define QSCALE 0.17677669529663687f  // 1/sqrt(32)

__device__ __forceinline__ unsigned f2tf(float f) {
    unsigned u;
    asm("cvt.rna.tf32.f32 %0, %1;" : "=r"(u) : "f"(f));
    return u;
}
__device__ __forceinline__ float tfs(float f) {   // tf32 bits as float for smem store
    return __uint_as_float(f2tf(f));
}
// column permutation within an 8-slab: logical c -> phys, pairs (t4, t4+4) adjacent
__device__ __forceinline__ int PI8(int s) { return ((s & 3) << 1) | ((s >> 2) & 1); }
__device__ __forceinline__ int cperm(int c) { return (c & ~7) | PI8(c & 7); }

__device__ __forceinline__ uint2 ldp(const float* p) { return *(const uint2*)p; }

// named barriers: pair (2 warps = 64 thr), block (8 warps = 256 thr)
__device__ __forceinline__ void pbar(int id) {
    asm volatile("bar.sync %0, 64;" :: "r"(id) : "memory");
}
__device__ __forceinline__ void bbar(int id) {
    asm volatile("bar.sync %0, 256;" :: "r"(id) : "memory");
}

__device__ __forceinline__ void mma8(float* c,
    unsigned a0, unsigned a1, unsigned a2, unsigned a3,
    unsigned b0, unsigned b1)
{
    asm volatile(
        "mma.sync.aligned.m16n8k8.row.col.f32.tf32.tf32.f32 "
        "{%0,%1,%2,%3}, {%4,%5,%6,%7}, {%8,%9}, {%0,%1,%2,%3};"
        : "+f"(c[0]), "+f"(c[1]), "+f"(c[2]), "+f"(c[3])
        : "r"(a0), "r"(a1), "r"(a2), "r"(a3), "r"(b0), "r"(b1));
}

// ---------------------------------------------------------------------------
// Temporal branch: ONE CTA per (b, f-pair). M=128 rows = two 64-row t-blocks
// (f = 2*fp + fb). Attention block-diagonal. 512 threads / 16 warps.
// Barriers: full(pre-stage, post-stage), block(post-proj), pair(rest).
// ---------------------------------------------------------------------------
__global__ void __launch_bounds__(512) temporal_kernel(
    const float* __restrict__ x,
    const float* __restrict__ wq, const float* __restrict__ bq,
    const float* __restrict__ wk, const float* __restrict__ bk,
    const float* __restrict__ wv, const float* __restrict__ bv,
    const float* __restrict__ wo, const float* __restrict__ bo,
    float* __restrict__ out)
{
    extern __shared__ float sm[];
    float* Xs  = sm;            // 9216  [row][d perm] ld 72
    float* Kh  = sm + 9216;     // 5120  [row][k=32 perm] ld 40
    float* Vt  = sm + 14336;    // 4352  [k=32][row perm] ld 136
    float* Qh  = sm + 18688;    // 5120
    float* Ss  = sm + 23808;    // 9216  [row][s=64] ld 72
    float* Oh  = sm + 33024;    // 5120
    float* WB  = sm + 38144;    // 6912  3 x [n=32][k=64 perm] ld 72
    float* WoS = sm + 45056;    // 2560  [d=64][k=32 perm] ld 40
    float* Bs  = sm + 47616;    // 448

    const int tid  = threadIdx.x;
    const int lane = tid & 31, warp = tid >> 5;
    const int g = lane >> 2, t4 = lane & 3;
    const int b = blockIdx.x >> 6, fp = blockIdx.x & 63;

    {
        const float4* x4 = (const float4*)x;
        for (int i = tid; i < 2048; i += 512) {
            int row = i >> 4, c = i & 15;
            int fb = row >> 6, t = row & 63;
            int f = fp * 2 + fb;
            float4 v = x4[(((b * 64 + t) * 128 + f) << 4) + c];
            float* d = Xs + row * 72;
            d[cperm(4 * c + 0)] = tfs(v.x);
            d[cperm(4 * c + 1)] = tfs(v.y);
            d[cperm(4 * c + 2)] = tfs(v.z);
            d[cperm(4 * c + 3)] = tfs(v.w);
        }
    }
    if (tid < 448) {
        float v;
        if      (tid < 128) v = bq[tid];
        else if (tid < 256) v = bk[tid - 128];
        else if (tid < 384) v = bv[tid - 256];
        else                v = bo[tid - 384];
        Bs[tid] = v;
    }

    const int mt8 = warp & 7, nh2 = warp >> 3;
    const int r0 = mt8 * 16 + g, r1 = r0 + 8;
    const int blk = mt8 >> 2;
    const int pid = 8 + mt8;           // pair barrier id
    const int bid = 1 + blk;           // block barrier id

    float pacc[4][4] = {};

    for (int h = 0; h < 4; h++) {
        const int hb = h * 32;
        __syncthreads();   // all readers of WB/WoS (and Xs/Bs at h=0) done
        for (int i = tid; i < 6144; i += 512) {
            int m = i >> 11, r = i & 2047;
            int n = r & 31, d = r >> 5;
            const float* w = (m == 0) ? wq : (m == 1) ? wk : wv;
            WB[m * 2304 + n * 72 + cperm(d)] = tfs(w[d * 128 + hb + n]);
        }
        for (int i = tid; i < 2048; i += 512) {
            int k = i >> 6, d = i & 63;
            WoS[d * 40 + cperm(k)] = tfs(wo[(hb + k) * 64 + d]);
        }
        __syncthreads();

        // fused Q/K/V projections: M=128 N=32 K=64, warp tile 16x16 (nt=2)
        {
            float aQ[2][4], aK[2][4], aV[2][4];
            #pragma unroll
            for (int nt = 0; nt < 2; nt++) {
                int c0 = nh2 * 16 + nt * 8 + 2 * t4;
                aQ[nt][0] = Bs[hb + c0];       aQ[nt][1] = Bs[hb + c0 + 1];
                aQ[nt][2] = aQ[nt][0];         aQ[nt][3] = aQ[nt][1];
                aK[nt][0] = Bs[128 + hb + c0]; aK[nt][1] = Bs[128 + hb + c0 + 1];
                aK[nt][2] = aK[nt][0];         aK[nt][3] = aK[nt][1];
                aV[nt][0] = Bs[256 + hb + c0]; aV[nt][1] = Bs[256 + hb + c0 + 1];
                aV[nt][2] = aV[nt][0];         aV[nt][3] = aV[nt][1];
            }
            #pragma unroll
            for (int kt = 0; kt < 8; kt++) {
                int ko = kt * 8 + 2 * t4;
                uint2 pa0 = ldp(Xs + r0 * 72 + ko);
                uint2 pa1 = ldp(Xs + r1 * 72 + ko);
                #pragma unroll
                for (int nt = 0; nt < 2; nt++) {
                    int n0 = nh2 * 16 + nt * 8 + g;
                    uint2 pq = ldp(WB +        n0 * 72 + ko);
                    uint2 pk = ldp(WB + 2304 + n0 * 72 + ko);
                    uint2 pv = ldp(WB + 4608 + n0 * 72 + ko);
                    mma8(aQ[nt], pa0.x, pa1.x, pa0.y, pa1.y, pq.x, pq.y);
                    mma8(aK[nt], pa0.x, pa1.x, pa0.y, pa1.y, pk.x, pk.y);
                    mma8(aV[nt], pa0.x, pa1.x, pa0.y, pa1.y, pv.x, pv.y);
                }
            }
            #pragma unroll
            for (int nt = 0; nt < 2; nt++) {
                int c0 = nh2 * 16 + nt * 8 + 2 * t4;
                int p0 = cperm(c0), p1 = cperm(c0 + 1);
                Qh[r0 * 40 + p0] = tfs(aQ[nt][0] * QSCALE);
                Qh[r0 * 40 + p1] = tfs(aQ[nt][1] * QSCALE);
                Qh[r1 * 40 + p0] = tfs(aQ[nt][2] * QSCALE);
                Qh[r1 * 40 + p1] = tfs(aQ[nt][3] * QSCALE);
                Kh[r0 * 40 + p0] = tfs(aK[nt][0]);
                Kh[r0 * 40 + p1] = tfs(aK[nt][1]);
                Kh[r1 * 40 + p0] = tfs(aK[nt][2]);
                Kh[r1 * 40 + p1] = tfs(aK[nt][3]);
                int pr0 = mt8 * 16 + PI8(g), pr1 = pr0 + 8;
                Vt[(c0    ) * 136 + pr0] = tfs(aV[nt][0]);
                Vt[(c0 + 1) * 136 + pr0] = tfs(aV[nt][1]);
                Vt[(c0    ) * 136 + pr1] = tfs(aV[nt][2]);
                Vt[(c0 + 1) * 136 + pr1] = tfs(aV[nt][3]);
            }
        }
        bbar(bid);   // Kh/Vt/Qh of this f-block ready

        // scores: M=128 N=64(own block) K=32, warp tile 16x32
        {
            float acc[4][4] = {};
            const int sbase = blk * 64;
            #pragma unroll
            for (int kt = 0; kt < 4; kt++) {
                int ko = kt * 8 + 2 * t4;
                uint2 pa0 = ldp(Qh + r0 * 40 + ko);
                uint2 pa1 = ldp(Qh + r1 * 40 + ko);
                #pragma unroll
                for (int nt = 0; nt < 4; nt++) {
                    int s0 = sbase + nh2 * 32 + nt * 8 + g;
                    uint2 pb = ldp(Kh + s0 * 40 + ko);
                    mma8(acc[nt], pa0.x, pa1.x, pa0.y, pa1.y, pb.x, pb.y);
                }
            }
            #pragma unroll
            for (int nt = 0; nt < 4; nt++) {
                int c0 = nh2 * 32 + nt * 8 + 2 * t4;
                Ss[r0 * 72 + c0]     = acc[nt][0];
                Ss[r0 * 72 + c0 + 1] = acc[nt][1];
                Ss[r1 * 72 + c0]     = acc[nt][2];
                Ss[r1 * 72 + c0 + 1] = acc[nt][3];
            }
        }
        pbar(pid);
        // softmax: own pair's 16 rows, this warp does 8 (64 cols)
        {
            const int rs = mt8 * 16 + nh2 * 8;
            #pragma unroll
            for (int rr = 0; rr < 8; rr++) {
                int r = rs + rr;
                float v0 = Ss[r * 72 + lane], v1 = Ss[r * 72 + 32 + lane];
                float mx = fmaxf(v0, v1);
                #pragma unroll
                for (int o = 16; o > 0; o >>= 1)
                    mx = fmaxf(mx, __shfl_xor_sync(0xffffffffu, mx, o));
                float e0 = __expf(v0 - mx), e1 = __expf(v1 - mx);
                float su = e0 + e1;
                #pragma unroll
                for (int o = 16; o > 0; o >>= 1)
                    su += __shfl_xor_sync(0xffffffffu, su, o);
                float inv = __frcp_rn(su);
                Ss[r * 72 + cperm(lane)]      = tfs(e0 * inv);
                Ss[r * 72 + cperm(32 + lane)] = tfs(e1 * inv);
            }
        }
        pbar(pid);
        // AV: M=128 N=32 K=64(own block), warp tile 16x16 -> Oh
        {
            float acc[2][4] = {};
            const int kbase = blk * 64;
            #pragma unroll
            for (int kt = 0; kt < 8; kt++) {
                int ko = kt * 8 + 2 * t4;
                uint2 pa0 = ldp(Ss + r0 * 72 + ko);
                uint2 pa1 = ldp(Ss + r1 * 72 + ko);
                #pragma unroll
                for (int nt = 0; nt < 2; nt++) {
                    int n0 = nh2 * 16 + nt * 8 + g;
                    uint2 pb = ldp(Vt + n0 * 136 + kbase + ko);
                    mma8(acc[nt], pa0.x, pa1.x, pa0.y, pa1.y, pb.x, pb.y);
                }
            }
            #pragma unroll
            for (int nt = 0; nt < 2; nt++) {
                int c0 = nh2 * 16 + nt * 8 + 2 * t4;
                int p0 = cperm(c0), p1 = cperm(c0 + 1);
                Oh[r0 * 40 + p0] = tfs(acc[nt][0]);
                Oh[r0 * 40 + p1] = tfs(acc[nt][1]);
                Oh[r1 * 40 + p0] = tfs(acc[nt][2]);
                Oh[r1 * 40 + p1] = tfs(acc[nt][3]);
            }
        }
        pbar(pid);
        // out-proj partial: M=128 N=64 K=32, warp tile 16x32, reg acc
        #pragma unroll
        for (int kt = 0; kt < 4; kt++) {
            int ko = kt * 8 + 2 * t4;
            uint2 pa0 = ldp(Oh + r0 * 40 + ko);
            uint2 pa1 = ldp(Oh + r1 * 40 + ko);
            #pragma unroll
            for (int nt = 0; nt < 4; nt++) {
                int n0 = nh2 * 32 + nt * 8 + g;
                uint2 pb = ldp(WoS + n0 * 40 + ko);
                mma8(pacc[nt], pa0.x, pa1.x, pa0.y, pa1.y, pb.x, pb.y);
            }
        }
    }

    {
        int fb = r0 >> 6, t0 = r0 & 63, t1 = r1 & 63;
        int f = fp * 2 + fb;
        #pragma unroll
        for (int nt = 0; nt < 4; nt++) {
            int d0 = nh2 * 32 + nt * 8 + 2 * t4;
            float b0 = Bs[384 + d0], b1 = Bs[384 + d0 + 1];
            float2* p0 = (float2*)(out + (((size_t)(b * 64 + t0) * 128 + f) * 64 + d0));
            float2* p1 = (float2*)(out + (((size_t)(b * 64 + t1) * 128 + f) * 64 + d0));
            *p0 = make_float2(pacc[nt][0] + b0, pacc[nt][1] + b1);
            *p1 = make_float2(pacc[nt][2] + b0, pacc[nt][3] + b1);
        }
    }
}

// ---------------------------------------------------------------------------
// Feature branch: ONE CTA per (b,t), 128 q-rows. 512 threads / 16 warps.
// Fused Q/K/V projection; pair barriers for scores->softmax->AV->outproj.
// ---------------------------------------------------------------------------
__global__ void __launch_bounds__(512) feature_kernel(
    const float* __restrict__ x,
    const float* __restrict__ wq, const float* __restrict__ bq,
    const float* __restrict__ wk, const float* __restrict__ bk,
    const float* __restrict__ wv, const float* __restrict__ bv,
    const float* __restrict__ wo, const float* __restrict__ bo,
    float* __restrict__ out)
{
    extern __shared__ float sm[];
    float* Xs  = sm;            // 9216
    float* Kh  = sm + 9216;     // 5120
    float* Vt  = sm + 14336;    // 4352  [k=32][s=128 perm] ld 136
    float* Qh  = sm + 18688;    // 5120
    float* Ss  = sm + 23808;    // 17408 [q=128][s=128] ld 136
    float* Oh  = sm + 41216;    // 5120
    float* WB  = sm + 46336;    // 6912
    float* WoS = sm + 53248;    // 2560
    float* Bs  = sm + 55808;    // 448

    const int tid  = threadIdx.x;
    const int lane = tid & 31, warp = tid >> 5;
    const int g = lane >> 2, t4 = lane & 3;
    const int b = blockIdx.x >> 6, t = blockIdx.x & 63;

    {
        const float4* x4 = (const float4*)(x + (size_t)(b * 64 + t) * 128 * 64);
        for (int i = tid; i < 2048; i += 512) {
            int fr = i >> 4, c = i & 15;
            float4 v = x4[i];
            float* d = Xs + fr * 72;
            d[cperm(4 * c + 0)] = tfs(v.x);
            d[cperm(4 * c + 1)] = tfs(v.y);
            d[cperm(4 * c + 2)] = tfs(v.z);
            d[cperm(4 * c + 3)] = tfs(v.w);
        }
    }
    if (tid < 448) {
        float v;
        if      (tid < 128) v = bq[tid];
        else if (tid < 256) v = bk[tid - 128];
        else if (tid < 384) v = bv[tid - 256];
        else                v = bo[tid - 384];
        Bs[tid] = v;
    }

    const int mt8 = warp & 7, nh2 = warp >> 3;
    const int r0 = mt8 * 16 + g, r1 = r0 + 8;
    const int pid = 8 + mt8;

    float pacc[4][4] = {};

    for (int h = 0; h < 4; h++) {
        const int hb = h * 32;
        __syncthreads();
        for (int i = tid; i < 6144; i += 512) {
            int m = i >> 11, r = i & 2047;
            int ko = r & 31, d = r >> 5;
            const float* w = (m == 0) ? wq : (m == 1) ? wk : wv;
            WB[m * 2304 + ko * 72 + cperm(d)] = tfs(w[d * 128 + hb + ko]);
        }
        for (int i = tid; i < 2048; i += 512) {
            int k = i >> 6, d = i & 63;
            WoS[d * 40 + cperm(k)] = tfs(wo[(hb + k) * 64 + d]);
        }
        __syncthreads();

        // fused Q/K/V projections: M=128 N=32 K=64, warp tile 16x16 (nt=2)
        {
            float aQ[2][4], aK[2][4], aV[2][4];
            #pragma unroll
            for (int nt = 0; nt < 2; nt++) {
                int c0 = nh2 * 16 + nt * 8 + 2 * t4;
                aQ[nt][0] = Bs[hb + c0];       aQ[nt][1] = Bs[hb + c0 + 1];
                aQ[nt][2] = aQ[nt][0];         aQ[nt][3] = aQ[nt][1];
                aK[nt][0] = Bs[128 + hb + c0]; aK[nt][1] = Bs[128 + hb + c0 + 1];
                aK[nt][2] = aK[nt][0];         aK[nt][3] = aK[nt][1];
                aV[nt][0] = Bs[256 + hb + c0]; aV[nt][1] = Bs[256 + hb + c0 + 1];
                aV[nt][2] = aV[nt][0];         aV[nt][3] = aV[nt][1];
            }
            #pragma unroll
            for (int kt = 0; kt < 8; kt++) {
                int ko = kt * 8 + 2 * t4;
                uint2 pa0 = ldp(Xs + r0 * 72 + ko);
                uint2 pa1 = ldp(Xs + r1 * 72 + ko);
                #pragma unroll
                for (int nt = 0; nt < 2; nt++) {
                    int n0 = nh2 * 16 + nt * 8 + g;
                    uint2 pq = ldp(WB +        n0 * 72 + ko);
                    uint2 pk = ldp(WB + 2304 + n0 * 72 + ko);
                    uint2 pv = ldp(WB + 4608 + n0 * 72 + ko);
                    mma8(aQ[nt], pa0.x, pa1.x, pa0.y, pa1.y, pq.x, pq.y);
                    mma8(aK[nt], pa0.x, pa1.x, pa0.y, pa1.y, pk.x, pk.y);
                    mma8(aV[nt], pa0.x, pa1.x, pa0.y, pa1.y, pv.x, pv.y);
                }
            }
            #pragma unroll
            for (int nt = 0; nt < 2; nt++) {
                int c0 = nh2 * 16 + nt * 8 + 2 * t4;
                int p0 = cperm(c0), p1 = cperm(c0 + 1);
                Qh[r0 * 40 + p0] = tfs(aQ[nt][0] * QSCALE);
                Qh[r0 * 40 + p1] = tfs(aQ[nt][1] * QSCALE);
                Qh[r1 * 40 + p0] = tfs(aQ[nt][2] * QSCALE);
                Qh[r1 * 40 + p1] = tfs(aQ[nt][3] * QSCALE);
                Kh[r0 * 40 + p0] = tfs(aK[nt][0]);
                Kh[r0 * 40 + p1] = tfs(aK[nt][1]);
                Kh[r1 * 40 + p0] = tfs(aK[nt][2]);
                Kh[r1 * 40 + p1] = tfs(aK[nt][3]);
                int pr0 = mt8 * 16 + PI8(g), pr1 = pr0 + 8;
                Vt[(c0    ) * 136 + pr0] = tfs(aV[nt][0]);
                Vt[(c0 + 1) * 136 + pr0] = tfs(aV[nt][1]);
                Vt[(c0    ) * 136 + pr1] = tfs(aV[nt][2]);
                Vt[(c0 + 1) * 136 + pr1] = tfs(aV[nt][3]);
            }
        }
        __syncthreads();   // Kh/Vt need all warps

        // scores: M=128 N=128 K=32, warp tile 16x64 (nt=8)
        {
            float acc[8][4] = {};
            #pragma unroll
            for (int kt = 0; kt < 4; kt++) {
                int ko = kt * 8 + 2 * t4;
                uint2 pa0 = ldp(Qh + r0 * 40 + ko);
                uint2 pa1 = ldp(Qh + r1 * 40 + ko);
                #pragma unroll
                for (int nt = 0; nt < 8; nt++) {
                    int s0 = nh2 * 64 + nt * 8 + g;
                    uint2 pb = ldp(Kh + s0 * 40 + ko);
                    mma8(acc[nt], pa0.x, pa1.x, pa0.y, pa1.y, pb.x, pb.y);
                }
            }
            #pragma unroll
            for (int nt = 0; nt < 8; nt++) {
                int c0 = nh2 * 64 + nt * 8 + 2 * t4;
                Ss[r0 * 136 + c0]     = acc[nt][0];
                Ss[r0 * 136 + c0 + 1] = acc[nt][1];
                Ss[r1 * 136 + c0]     = acc[nt][2];
                Ss[r1 * 136 + c0 + 1] = acc[nt][3];
            }
        }
        pbar(pid);
        // softmax: own pair's 16 rows, this warp does 8 (128 cols)
        {
            const int rs = mt8 * 16 + nh2 * 8;
            #pragma unroll
            for (int rr = 0; rr < 8; rr++) {
                int r = rs + rr;
                float v0 = Ss[r * 136 + lane];
                float v1 = Ss[r * 136 + 32 + lane];
                float v2 = Ss[r * 136 + 64 + lane];
                float v3 = Ss[r * 136 + 96 + lane];
                float mx = fmaxf(fmaxf(v0, v1), fmaxf(v2, v3));
                #pragma unroll
                for (int o = 16; o > 0; o >>= 1)
                    mx = fmaxf(mx, __shfl_xor_sync(0xffffffffu, mx, o));
                float e0 = __expf(v0 - mx), e1 = __expf(v1 - mx);
                float e2 = __expf(v2 - mx), e3 = __expf(v3 - mx);
                float su = (e0 + e1) + (e2 + e3);
                #pragma unroll
                for (int o = 16; o > 0; o >>= 1)
                    su += __shfl_xor_sync(0xffffffffu, su, o);
                float inv = __frcp_rn(su);
                Ss[r * 136 + cperm(lane)]      = tfs(e0 * inv);
                Ss[r * 136 + cperm(32 + lane)] = tfs(e1 * inv);
                Ss[r * 136 + cperm(64 + lane)] = tfs(e2 * inv);
                Ss[r * 136 + cperm(96 + lane)] = tfs(e3 * inv);
            }
        }
        pbar(pid);
        // AV: M=128 N=32 K=128, warp tile 16x16 (nt=2) -> Oh
        {
            float acc[2][4] = {};
            #pragma unroll
            for (int kt = 0; kt < 16; kt++) {
                int ko = kt * 8 + 2 * t4;
                uint2 pa0 = ldp(Ss + r0 * 136 + ko);
                uint2 pa1 = ldp(Ss + r1 * 136 + ko);
                #pragma unroll
                for (int nt = 0; nt < 2; nt++) {
                    int n0 = nh2 * 16 + nt * 8 + g;
                    uint2 pb = ldp(Vt + n0 * 136 + ko);
                    mma8(acc[nt], pa0.x, pa1.x, pa0.y, pa1.y, pb.x, pb.y);
                }
            }
            #pragma unroll
            for (int nt = 0; nt < 2; nt++) {
                int c0 = nh2 * 16 + nt * 8 + 2 * t4;
                int p0 = cperm(c0), p1 = cperm(c0 + 1);
                Oh[r0 * 40 + p0] = tfs(acc[nt][0]);
                Oh[r0 * 40 + p1] = tfs(acc[nt][1]);
                Oh[r1 * 40 + p0] = tfs(acc[nt][2]);
                Oh[r1 * 40 + p1] = tfs(acc[nt][3]);
            }
        }
        pbar(pid);
        // out-proj partial: M=128 N=64 K=32, warp tile 16x32, reg acc
        #pragma unroll
        for (int kt = 0; kt < 4; kt++) {
            int ko = kt * 8 + 2 * t4;
            uint2 pa0 = ldp(Oh + r0 * 40 + ko);
            uint2 pa1 = ldp(Oh + r1 * 40 + ko);
            #pragma unroll
            for (int nt = 0; nt < 4; nt++) {
                int n0 = nh2 * 32 + nt * 8 + g;
                uint2 pb = ldp(WoS + n0 * 40 + ko);
                mma8(pacc[nt], pa0.x, pa1.x, pa0.y, pa1.y, pb.x, pb.y);
            }
        }
    }

    #pragma unroll
    for (int nt = 0; nt < 4; nt++) {
        int d0 = nh2 * 32 + nt * 8 + 2 * t4;
        float b0 = Bs[384 + d0], b1 = Bs[384 + d0 + 1];
        float2* p0 = (float2*)(out + (((size_t)(b * 64 + t) * 128 + r0) * 64 + d0));
        float2* p1 = (float2*)(out + (((size_t)(b * 64 + t) * 128 + r1) * 64 + d0));
        float2 v0 = *p0, v1 = *p1;
        v0.x += pacc[nt][0] + b0; v0.y += pacc[nt][1] + b1;
        v1.x += pacc[nt][2] + b0; v1.y += pacc[nt][3] + b1;
        *p0 = v0; *p1 = v1;
    }
}

// ---------------------------------------------------------------------------
extern "C" void kernel_launch(void* const* d_in, const int* in_sizes, int n_in,
                              void* d_out, int out_size)
{
    const float* x = (const float*)d_in[0];
    const float *tqw, *tqb, *tkw, *tkb, *tvw, *tvb, *tow, *tob;
    const float *fqw, *fqb, *fkw, *fkb, *fvw, *fvb, *fow, *fob;

    if (in_sizes[8] == 64) {   // reference-signature order
        tqw = (const float*)d_in[1];  tqb = (const float*)d_in[2];
        tkw = (const float*)d_in[3];  tkb = (const float*)d_in[4];
        tvw = (const float*)d_in[5];  tvb = (const float*)d_in[6];
        tow = (const float*)d_in[7];  tob = (const float*)d_in[8];
        fqw = (const float*)d_in[9];  fqb = (const float*)d_in[10];
        fkw = (const float*)d_in[11]; fkb = (const float*)d_in[12];
        fvw = (const float*)d_in[13]; fvb = (const float*)d_in[14];
        fow = (const float*)d_in[15]; fob = (const float*)d_in[16];
    } else {                    // setup_inputs dict order
        tqw = (const float*)d_in[1];  tqb = (const float*)d_in[2];
        tkw = (const float*)d_in[3];  tkb = (const float*)d_in[4];
        tvw = (const float*)d_in[5];  tvb = (const float*)d_in[6];
        fqw = (const float*)d_in[7];  fqb = (const float*)d_in[8];
        fkw = (const float*)d_in[9];  fkb = (const float*)d_in[10];
        fvw = (const float*)d_in[11]; fvb = (const float*)d_in[12];
        tow = (const float*)d_in[13]; tob = (const float*)d_in[14];
        fow = (const float*)d_in[15]; fob = (const float*)d_in[16];
    }

    float* out = (float*)d_out;

    const size_t sm_t = 48064 * sizeof(float);   // 192256 B
    const size_t sm_f = 56256 * sizeof(float);   // 225024 B

    cudaFuncSetAttribute(temporal_kernel,
                         cudaFuncAttributeMaxDynamicSharedMemorySize, (int)sm_t);
    cudaFuncSetAttribute(feature_kernel,
                         cudaFuncAttributeMaxDynamicSharedMemorySize, (int)sm_f);

    temporal_kernel<<<32 * 64, 512, sm_t>>>(x, tqw, tqb, tkw, tkb, tvw, tvb,
                                            tow, tob, out);
    feature_kernel<<<32 * 64, 512, sm_f>>>(x, fqw, fqb, fkw, fkb, fvw, fvb,
                                           fow, fob, out);
}

// round 11
// speedup vs baseline: 8.0437x; 1.0725x over previous
#include <cuda_runtime.h>

#define QSCALE 0.17677669529663687f  // 1/sqrt(32)

// pack two fp32 -> half2 bits (lo = first/lower k index)
__device__ __forceinline__ unsigned h2pack(float lo, float hi) {
    unsigned u;
    asm("cvt.rn.f16x2.f32 %0, %1, %2;" : "=r"(u) : "f"(hi), "f"(lo));
    return u;
}
// pair permutation within an 8-pair slab: logical pair p -> phys, so that
// pairs (t4, t4+4) land at phys (2t4, 2t4+1)  => one LDS.64 per fragment
__device__ __forceinline__ int PI8(int s) { return ((s & 3) << 1) | ((s >> 2) & 1); }
__device__ __forceinline__ int pcperm(int p) { return (p & ~7) | PI8(p & 7); }

__device__ __forceinline__ uint2 ldu2(const unsigned* p) { return *(const uint2*)p; }

__device__ __forceinline__ void pbar(int id) {
    asm volatile("bar.sync %0, 64;" :: "r"(id) : "memory");
}
__device__ __forceinline__ void bbar(int id) {
    asm volatile("bar.sync %0, 256;" :: "r"(id) : "memory");
}

__device__ __forceinline__ void mma16(float* c,
    unsigned a0, unsigned a1, unsigned a2, unsigned a3,
    unsigned b0, unsigned b1)
{
    asm volatile(
        "mma.sync.aligned.m16n8k16.row.col.f32.f16.f16.f32 "
        "{%0,%1,%2,%3}, {%4,%5,%6,%7}, {%8,%9}, {%0,%1,%2,%3};"
        : "+f"(c[0]), "+f"(c[1]), "+f"(c[2]), "+f"(c[3])
        : "r"(a0), "r"(a1), "r"(a2), "r"(a3), "r"(b0), "r"(b1));
}

// ---------------------------------------------------------------------------
// Temporal: ONE CTA per (b, f-pair). 128 rows = two 64-row t-blocks.
// smem (b32 words): Xs@0[128][40] Kh@5120[128][24] Vt@8192[32][72]
//   Qh@10496[128][24] Ss@13568 fp32[128][72] Ps@22784[128][40]
//   Oh@27904[128][24] WB@30976 3x[32][40] WoS@34816[64][24] Bs@36352 fp32 448
// total 36800 words = 147200 B
// ---------------------------------------------------------------------------
__global__ void __launch_bounds__(512) temporal_kernel(
    const float* __restrict__ x,
    const float* __restrict__ wq, const float* __restrict__ bq,
    const float* __restrict__ wk, const float* __restrict__ bk,
    const float* __restrict__ wv, const float* __restrict__ bv,
    const float* __restrict__ wo, const float* __restrict__ bo,
    float* __restrict__ out)
{
    extern __shared__ float sm[];
    unsigned* Xs  = (unsigned*)sm;
    unsigned* Kh  = (unsigned*)sm + 5120;
    unsigned* Vt  = (unsigned*)sm + 8192;
    unsigned* Qh  = (unsigned*)sm + 10496;
    float*    Ss  = sm + 13568;
    unsigned* Ps  = (unsigned*)sm + 22784;
    unsigned* Oh  = (unsigned*)sm + 27904;
    unsigned* WB  = (unsigned*)sm + 30976;
    unsigned* WoS = (unsigned*)sm + 34816;
    float*    Bs  = sm + 36352;

    const int tid  = threadIdx.x;
    const int lane = tid & 31, warp = tid >> 5;
    const int g = lane >> 2, t4 = lane & 3;
    const int b = blockIdx.x >> 6, fp = blockIdx.x & 63;

    // X: row = fb*64 + t -> x[b, t, 2*fp+fb, :], packed half2 pair-permuted
    {
        const float4* x4 = (const float4*)x;
        for (int i = tid; i < 2048; i += 512) {
            int row = i >> 4, c = i & 15;
            int fb = row >> 6, t = row & 63;
            int f = fp * 2 + fb;
            float4 v = x4[(((b * 64 + t) * 128 + f) << 4) + c];
            Xs[row * 40 + pcperm(2 * c)]     = h2pack(v.x, v.y);
            Xs[row * 40 + pcperm(2 * c + 1)] = h2pack(v.z, v.w);
        }
    }
    if (tid < 448) {
        float v;
        if      (tid < 128) v = bq[tid];
        else if (tid < 256) v = bk[tid - 128];
        else if (tid < 384) v = bv[tid - 256];
        else                v = bo[tid - 384];
        Bs[tid] = v;
    }

    const int mt8 = warp & 7, nh2 = warp >> 3;
    const int r0 = mt8 * 16 + g, r1 = r0 + 8;
    const int blk = mt8 >> 2;
    const int pid = 8 + mt8;
    const int bid = 1 + blk;

    float pacc[4][4] = {};

    for (int h = 0; h < 4; h++) {
        const int hb = h * 32;
        __syncthreads();   // WB/WoS readers done (Xs/Bs at h=0)
        // stage per-head weight slices [n=32][k=64 -> 32 pairs] stride 40
        for (int i = tid; i < 3072; i += 512) {
            int m = i >> 10, r = i & 1023, n = r >> 5, p = r & 31;
            const float* w = (m == 0) ? wq : (m == 1) ? wk : wv;
            WB[m * 1280 + n * 40 + pcperm(p)] =
                h2pack(w[(2 * p) * 128 + hb + n], w[(2 * p + 1) * 128 + hb + n]);
        }
        // WoS: [d=64][k=32 -> 16 pairs] stride 24
        for (int i = tid; i < 1024; i += 512) {
            int d = i >> 4, p = i & 15;
            WoS[d * 24 + ((p & 8) | PI8(p & 7))] =
                h2pack(wo[(hb + 2 * p) * 64 + d], wo[(hb + 2 * p + 1) * 64 + d]);
        }
        __syncthreads();

        // fused Q/K/V projections: M=128 N=32 K=64 (4 k16-slabs)
        {
            float aQ[2][4], aK[2][4], aV[2][4];
            #pragma unroll
            for (int nt = 0; nt < 2; nt++) {
                int c0 = nh2 * 16 + nt * 8 + 2 * t4;
                aQ[nt][0] = Bs[hb + c0];       aQ[nt][1] = Bs[hb + c0 + 1];
                aQ[nt][2] = aQ[nt][0];         aQ[nt][3] = aQ[nt][1];
                aK[nt][0] = Bs[128 + hb + c0]; aK[nt][1] = Bs[128 + hb + c0 + 1];
                aK[nt][2] = aK[nt][0];         aK[nt][3] = aK[nt][1];
                aV[nt][0] = Bs[256 + hb + c0]; aV[nt][1] = Bs[256 + hb + c0 + 1];
                aV[nt][2] = aV[nt][0];         aV[nt][3] = aV[nt][1];
            }
            #pragma unroll
            for (int kt = 0; kt < 4; kt++) {
                int ko = kt * 8 + 2 * t4;
                uint2 pa0 = ldu2(Xs + r0 * 40 + ko);
                uint2 pa1 = ldu2(Xs + r1 * 40 + ko);
                #pragma unroll
                for (int nt = 0; nt < 2; nt++) {
                    int n0 = nh2 * 16 + nt * 8 + g;
                    uint2 pq = ldu2(WB +        n0 * 40 + ko);
                    uint2 pk = ldu2(WB + 1280 + n0 * 40 + ko);
                    uint2 pv = ldu2(WB + 2560 + n0 * 40 + ko);
                    mma16(aQ[nt], pa0.x, pa1.x, pa0.y, pa1.y, pq.x, pq.y);
                    mma16(aK[nt], pa0.x, pa1.x, pa0.y, pa1.y, pk.x, pk.y);
                    mma16(aV[nt], pa0.x, pa1.x, pa0.y, pa1.y, pv.x, pv.y);
                }
            }
            // V fragments of neighbor warp-row (lane+4) for s-pair packing
            float vb[2][4];
            #pragma unroll
            for (int nt = 0; nt < 2; nt++)
                #pragma unroll
                for (int j = 0; j < 4; j++)
                    vb[nt][j] = __shfl_down_sync(0xffffffffu, aV[nt][j], 4);
            #pragma unroll
            for (int nt = 0; nt < 2; nt++) {
                int pr = nh2 * 8 + PI8(nt * 4 + t4);   // phys pair col
                Qh[r0 * 24 + pr] = h2pack(aQ[nt][0] * QSCALE, aQ[nt][1] * QSCALE);
                Qh[r1 * 24 + pr] = h2pack(aQ[nt][2] * QSCALE, aQ[nt][3] * QSCALE);
                Kh[r0 * 24 + pr] = h2pack(aK[nt][0], aK[nt][1]);
                Kh[r1 * 24 + pr] = h2pack(aK[nt][2], aK[nt][3]);
            }
            if ((g & 1) == 0) {
                int p0 = mt8 * 8 + PI8(g >> 1);         // s-pair (r0, r0+1)
                int p1 = mt8 * 8 + PI8(4 + (g >> 1));   // s-pair (r1, r1+1)
                #pragma unroll
                for (int nt = 0; nt < 2; nt++) {
                    int c0 = nh2 * 16 + nt * 8 + 2 * t4;
                    Vt[(c0    ) * 72 + p0] = h2pack(aV[nt][0], vb[nt][0]);
                    Vt[(c0 + 1) * 72 + p0] = h2pack(aV[nt][1], vb[nt][1]);
                    Vt[(c0    ) * 72 + p1] = h2pack(aV[nt][2], vb[nt][2]);
                    Vt[(c0 + 1) * 72 + p1] = h2pack(aV[nt][3], vb[nt][3]);
                }
            }
        }
        bbar(bid);

        // scores: M=128 N=64(own block) K=32 (2 slabs), warp tile 16x32
        {
            float acc[4][4] = {};
            const int sbase = blk * 64;
            #pragma unroll
            for (int kt = 0; kt < 2; kt++) {
                int ko = kt * 8 + 2 * t4;
                uint2 pa0 = ldu2(Qh + r0 * 24 + ko);
                uint2 pa1 = ldu2(Qh + r1 * 24 + ko);
                #pragma unroll
                for (int nt = 0; nt < 4; nt++) {
                    int s0 = sbase + nh2 * 32 + nt * 8 + g;
                    uint2 pb = ldu2(Kh + s0 * 24 + ko);
                    mma16(acc[nt], pa0.x, pa1.x, pa0.y, pa1.y, pb.x, pb.y);
                }
            }
            #pragma unroll
            for (int nt = 0; nt < 4; nt++) {
                int c0 = nh2 * 32 + nt * 8 + 2 * t4;
                Ss[r0 * 72 + c0]     = acc[nt][0];
                Ss[r0 * 72 + c0 + 1] = acc[nt][1];
                Ss[r1 * 72 + c0]     = acc[nt][2];
                Ss[r1 * 72 + c0 + 1] = acc[nt][3];
            }
        }
        pbar(pid);
        // softmax: 8 rows/warp, lane owns cols {2lane, 2lane+1}
        {
            const int rs = mt8 * 16 + nh2 * 8;
            #pragma unroll
            for (int rr = 0; rr < 8; rr++) {
                int r = rs + rr;
                float2 v = *(const float2*)(Ss + r * 72 + 2 * lane);
                float mx = fmaxf(v.x, v.y);
                #pragma unroll
                for (int o = 16; o > 0; o >>= 1)
                    mx = fmaxf(mx, __shfl_xor_sync(0xffffffffu, mx, o));
                float e0 = __expf(v.x - mx), e1 = __expf(v.y - mx);
                float su = e0 + e1;
                #pragma unroll
                for (int o = 16; o > 0; o >>= 1)
                    su += __shfl_xor_sync(0xffffffffu, su, o);
                float inv = __frcp_rn(su);
                Ps[r * 40 + pcperm(lane)] = h2pack(e0 * inv, e1 * inv);
            }
        }
        pbar(pid);
        // AV: M=128 N=32 K=64(own block, 4 slabs) -> Oh
        {
            float acc[2][4] = {};
            const int kbase = blk * 32;   // b32 offset into Vt rows
            #pragma unroll
            for (int kt = 0; kt < 4; kt++) {
                int ko = kt * 8 + 2 * t4;
                uint2 pa0 = ldu2(Ps + r0 * 40 + ko);
                uint2 pa1 = ldu2(Ps + r1 * 40 + ko);
                #pragma unroll
                for (int nt = 0; nt < 2; nt++) {
                    int n0 = nh2 * 16 + nt * 8 + g;
                    uint2 pb = ldu2(Vt + n0 * 72 + kbase + ko);
                    mma16(acc[nt], pa0.x, pa1.x, pa0.y, pa1.y, pb.x, pb.y);
                }
            }
            #pragma unroll
            for (int nt = 0; nt < 2; nt++) {
                int pr = nh2 * 8 + PI8(nt * 4 + t4);
                Oh[r0 * 24 + pr] = h2pack(acc[nt][0], acc[nt][1]);
                Oh[r1 * 24 + pr] = h2pack(acc[nt][2], acc[nt][3]);
            }
        }
        pbar(pid);
        // out-proj partial: M=128 N=64 K=32 (2 slabs), reg acc
        #pragma unroll
        for (int kt = 0; kt < 2; kt++) {
            int ko = kt * 8 + 2 * t4;
            uint2 pa0 = ldu2(Oh + r0 * 24 + ko);
            uint2 pa1 = ldu2(Oh + r1 * 24 + ko);
            #pragma unroll
            for (int nt = 0; nt < 4; nt++) {
                int n0 = nh2 * 32 + nt * 8 + g;
                uint2 pb = ldu2(WoS + n0 * 24 + ko);
                mma16(pacc[nt], pa0.x, pa1.x, pa0.y, pa1.y, pb.x, pb.y);
            }
        }
    }

    {
        int fb = r0 >> 6, t0 = r0 & 63, t1 = r1 & 63;
        int f = fp * 2 + fb;
        #pragma unroll
        for (int nt = 0; nt < 4; nt++) {
            int d0 = nh2 * 32 + nt * 8 + 2 * t4;
            float b0 = Bs[384 + d0], b1 = Bs[384 + d0 + 1];
            float2* p0 = (float2*)(out + (((size_t)(b * 64 + t0) * 128 + f) * 64 + d0));
            float2* p1 = (float2*)(out + (((size_t)(b * 64 + t1) * 128 + f) * 64 + d0));
            *p0 = make_float2(pacc[nt][0] + b0, pacc[nt][1] + b1);
            *p1 = make_float2(pacc[nt][2] + b0, pacc[nt][3] + b1);
        }
    }
}

// ---------------------------------------------------------------------------
// Feature: ONE CTA per (b,t), 128 q-rows.
// smem (b32): Xs@0[128][40] Kh@5120[128][24] Vt@8192[32][72] Qh@10496[128][24]
//   Ss@13568 fp32[128][136] Ps@30976[128][72] Oh@40192[128][24]
//   WB@43264 3x[32][40] WoS@47104[64][24] Bs@48640 fp32 448
// total 49088 words = 196352 B
// ---------------------------------------------------------------------------
__global__ void __launch_bounds__(512) feature_kernel(
    const float* __restrict__ x,
    const float* __restrict__ wq, const float* __restrict__ bq,
    const float* __restrict__ wk, const float* __restrict__ bk,
    const float* __restrict__ wv, const float* __restrict__ bv,
    const float* __restrict__ wo, const float* __restrict__ bo,
    float* __restrict__ out)
{
    extern __shared__ float sm[];
    unsigned* Xs  = (unsigned*)sm;
    unsigned* Kh  = (unsigned*)sm + 5120;
    unsigned* Vt  = (unsigned*)sm + 8192;
    unsigned* Qh  = (unsigned*)sm + 10496;
    float*    Ss  = sm + 13568;
    unsigned* Ps  = (unsigned*)sm + 30976;
    unsigned* Oh  = (unsigned*)sm + 40192;
    unsigned* WB  = (unsigned*)sm + 43264;
    unsigned* WoS = (unsigned*)sm + 47104;
    float*    Bs  = sm + 48640;

    const int tid  = threadIdx.x;
    const int lane = tid & 31, warp = tid >> 5;
    const int g = lane >> 2, t4 = lane & 3;
    const int b = blockIdx.x >> 6, t = blockIdx.x & 63;

    {
        const float4* x4 = (const float4*)(x + (size_t)(b * 64 + t) * 128 * 64);
        for (int i = tid; i < 2048; i += 512) {
            int row = i >> 4, c = i & 15;
            float4 v = x4[i];
            Xs[row * 40 + pcperm(2 * c)]     = h2pack(v.x, v.y);
            Xs[row * 40 + pcperm(2 * c + 1)] = h2pack(v.z, v.w);
        }
    }
    if (tid < 448) {
        float v;
        if      (tid < 128) v = bq[tid];
        else if (tid < 256) v = bk[tid - 128];
        else if (tid < 384) v = bv[tid - 256];
        else                v = bo[tid - 384];
        Bs[tid] = v;
    }

    const int mt8 = warp & 7, nh2 = warp >> 3;
    const int r0 = mt8 * 16 + g, r1 = r0 + 8;
    const int pid = 8 + mt8;

    float pacc[4][4] = {};

    for (int h = 0; h < 4; h++) {
        const int hb = h * 32;
        __syncthreads();
        for (int i = tid; i < 3072; i += 512) {
            int m = i >> 10, r = i & 1023, n = r >> 5, p = r & 31;
            const float* w = (m == 0) ? wq : (m == 1) ? wk : wv;
            WB[m * 1280 + n * 40 + pcperm(p)] =
                h2pack(w[(2 * p) * 128 + hb + n], w[(2 * p + 1) * 128 + hb + n]);
        }
        for (int i = tid; i < 1024; i += 512) {
            int d = i >> 4, p = i & 15;
            WoS[d * 24 + ((p & 8) | PI8(p & 7))] =
                h2pack(wo[(hb + 2 * p) * 64 + d], wo[(hb + 2 * p + 1) * 64 + d]);
        }
        __syncthreads();

        // fused Q/K/V projections: M=128 N=32 K=64 (4 slabs)
        {
            float aQ[2][4], aK[2][4], aV[2][4];
            #pragma unroll
            for (int nt = 0; nt < 2; nt++) {
                int c0 = nh2 * 16 + nt * 8 + 2 * t4;
                aQ[nt][0] = Bs[hb + c0];       aQ[nt][1] = Bs[hb + c0 + 1];
                aQ[nt][2] = aQ[nt][0];         aQ[nt][3] = aQ[nt][1];
                aK[nt][0] = Bs[128 + hb + c0]; aK[nt][1] = Bs[128 + hb + c0 + 1];
                aK[nt][2] = aK[nt][0];         aK[nt][3] = aK[nt][1];
                aV[nt][0] = Bs[256 + hb + c0]; aV[nt][1] = Bs[256 + hb + c0 + 1];
                aV[nt][2] = aV[nt][0];         aV[nt][3] = aV[nt][1];
            }
            #pragma unroll
            for (int kt = 0; kt < 4; kt++) {
                int ko = kt * 8 + 2 * t4;
                uint2 pa0 = ldu2(Xs + r0 * 40 + ko);
                uint2 pa1 = ldu2(Xs + r1 * 40 + ko);
                #pragma unroll
                for (int nt = 0; nt < 2; nt++) {
                    int n0 = nh2 * 16 + nt * 8 + g;
                    uint2 pq = ldu2(WB +        n0 * 40 + ko);
                    uint2 pk = ldu2(WB + 1280 + n0 * 40 + ko);
                    uint2 pv = ldu2(WB + 2560 + n0 * 40 + ko);
                    mma16(aQ[nt], pa0.x, pa1.x, pa0.y, pa1.y, pq.x, pq.y);
                    mma16(aK[nt], pa0.x, pa1.x, pa0.y, pa1.y, pk.x, pk.y);
                    mma16(aV[nt], pa0.x, pa1.x, pa0.y, pa1.y, pv.x, pv.y);
                }
            }
            float vb[2][4];
            #pragma unroll
            for (int nt = 0; nt < 2; nt++)
                #pragma unroll
                for (int j = 0; j < 4; j++)
                    vb[nt][j] = __shfl_down_sync(0xffffffffu, aV[nt][j], 4);
            #pragma unroll
            for (int nt = 0; nt < 2; nt++) {
                int pr = nh2 * 8 + PI8(nt * 4 + t4);
                Qh[r0 * 24 + pr] = h2pack(aQ[nt][0] * QSCALE, aQ[nt][1] * QSCALE);
                Qh[r1 * 24 + pr] = h2pack(aQ[nt][2] * QSCALE, aQ[nt][3] * QSCALE);
                Kh[r0 * 24 + pr] = h2pack(aK[nt][0], aK[nt][1]);
                Kh[r1 * 24 + pr] = h2pack(aK[nt][2], aK[nt][3]);
            }
            if ((g & 1) == 0) {
                int p0 = mt8 * 8 + PI8(g >> 1);
                int p1 = mt8 * 8 + PI8(4 + (g >> 1));
                #pragma unroll
                for (int nt = 0; nt < 2; nt++) {
                    int c0 = nh2 * 16 + nt * 8 + 2 * t4;
                    Vt[(c0    ) * 72 + p0] = h2pack(aV[nt][0], vb[nt][0]);
                    Vt[(c0 + 1) * 72 + p0] = h2pack(aV[nt][1], vb[nt][1]);
                    Vt[(c0    ) * 72 + p1] = h2pack(aV[nt][2], vb[nt][2]);
                    Vt[(c0 + 1) * 72 + p1] = h2pack(aV[nt][3], vb[nt][3]);
                }
            }
        }
        __syncthreads();   // Kh/Vt consumed CTA-wide

        // scores: M=128 N=128 K=32 (2 slabs), warp tile 16x64
        {
            float acc[8][4] = {};
            #pragma unroll
            for (int kt = 0; kt < 2; kt++) {
                int ko = kt * 8 + 2 * t4;
                uint2 pa0 = ldu2(Qh + r0 * 24 + ko);
                uint2 pa1 = ldu2(Qh + r1 * 24 + ko);
                #pragma unroll
                for (int nt = 0; nt < 8; nt++) {
                    int s0 = nh2 * 64 + nt * 8 + g;
                    uint2 pb = ldu2(Kh + s0 * 24 + ko);
                    mma16(acc[nt], pa0.x, pa1.x, pa0.y, pa1.y, pb.x, pb.y);
                }
            }
            #pragma unroll
            for (int nt = 0; nt < 8; nt++) {
                int c0 = nh2 * 64 + nt * 8 + 2 * t4;
                Ss[r0 * 136 + c0]     = acc[nt][0];
                Ss[r0 * 136 + c0 + 1] = acc[nt][1];
                Ss[r1 * 136 + c0]     = acc[nt][2];
                Ss[r1 * 136 + c0 + 1] = acc[nt][3];
            }
        }
        pbar(pid);
        // softmax: 8 rows/warp, lane owns col pairs {2lane,2lane+1},{64+..}
        {
            const int rs = mt8 * 16 + nh2 * 8;
            #pragma unroll
            for (int rr = 0; rr < 8; rr++) {
                int r = rs + rr;
                float2 va = *(const float2*)(Ss + r * 136 + 2 * lane);
                float2 vc = *(const float2*)(Ss + r * 136 + 64 + 2 * lane);
                float mx = fmaxf(fmaxf(va.x, va.y), fmaxf(vc.x, vc.y));
                #pragma unroll
                for (int o = 16; o > 0; o >>= 1)
                    mx = fmaxf(mx, __shfl_xor_sync(0xffffffffu, mx, o));
                float e0 = __expf(va.x - mx), e1 = __expf(va.y - mx);
                float e2 = __expf(vc.x - mx), e3 = __expf(vc.y - mx);
                float su = (e0 + e1) + (e2 + e3);
                #pragma unroll
                for (int o = 16; o > 0; o >>= 1)
                    su += __shfl_xor_sync(0xffffffffu, su, o);
                float inv = __frcp_rn(su);
                Ps[r * 72 + pcperm(lane)]      = h2pack(e0 * inv, e1 * inv);
                Ps[r * 72 + pcperm(32 + lane)] = h2pack(e2 * inv, e3 * inv);
            }
        }
        pbar(pid);
        // AV: M=128 N=32 K=128 (8 slabs) -> Oh
        {
            float acc[2][4] = {};
            #pragma unroll
            for (int kt = 0; kt < 8; kt++) {
                int ko = kt * 8 + 2 * t4;
                uint2 pa0 = ldu2(Ps + r0 * 72 + ko);
                uint2 pa1 = ldu2(Ps + r1 * 72 + ko);
                #pragma unroll
                for (int nt = 0; nt < 2; nt++) {
                    int n0 = nh2 * 16 + nt * 8 + g;
                    uint2 pb = ldu2(Vt + n0 * 72 + ko);
                    mma16(acc[nt], pa0.x, pa1.x, pa0.y, pa1.y, pb.x, pb.y);
                }
            }
            #pragma unroll
            for (int nt = 0; nt < 2; nt++) {
                int pr = nh2 * 8 + PI8(nt * 4 + t4);
                Oh[r0 * 24 + pr] = h2pack(acc[nt][0], acc[nt][1]);
                Oh[r1 * 24 + pr] = h2pack(acc[nt][2], acc[nt][3]);
            }
        }
        pbar(pid);
        // out-proj partial: M=128 N=64 K=32 (2 slabs), reg acc
        #pragma unroll
        for (int kt = 0; kt < 2; kt++) {
            int ko = kt * 8 + 2 * t4;
            uint2 pa0 = ldu2(Oh + r0 * 24 + ko);
            uint2 pa1 = ldu2(Oh + r1 * 24 + ko);
            #pragma unroll
            for (int nt = 0; nt < 4; nt++) {
                int n0 = nh2 * 32 + nt * 8 + g;
                uint2 pb = ldu2(WoS + n0 * 24 + ko);
                mma16(pacc[nt], pa0.x, pa1.x, pa0.y, pa1.y, pb.x, pb.y);
            }
        }
    }

    #pragma unroll
    for (int nt = 0; nt < 4; nt++) {
        int d0 = nh2 * 32 + nt * 8 + 2 * t4;
        float b0 = Bs[384 + d0], b1 = Bs[384 + d0 + 1];
        float2* p0 = (float2*)(out + (((size_t)(b * 64 + t) * 128 + r0) * 64 + d0));
        float2* p1 = (float2*)(out + (((size_t)(b * 64 + t) * 128 + r1) * 64 + d0));
        float2 v0 = *p0, v1 = *p1;
        v0.x += pacc[nt][0] + b0; v0.y += pacc[nt][1] + b1;
        v1.x += pacc[nt][2] + b0; v1.y += pacc[nt][3] + b1;
        *p0 = v0; *p1 = v1;
    }
}

// ---------------------------------------------------------------------------
extern "C" void kernel_launch(void* const* d_in, const int* in_sizes, int n_in,
                              void* d_out, int out_size)
{
    const float* x = (const float*)d_in[0];
    const float *tqw, *tqb, *tkw, *tkb, *tvw, *tvb, *tow, *tob;
    const float *fqw, *fqb, *fkw, *fkb, *fvw, *fvb, *fow, *fob;

    if (in_sizes[8] == 64) {   // reference-signature order
        tqw = (const float*)d_in[1];  tqb = (const float*)d_in[2];
        tkw = (const float*)d_in[3];  tkb = (const float*)d_in[4];
        tvw = (const float*)d_in[5];  tvb = (const float*)d_in[6];
        tow = (const float*)d_in[7];  tob = (const float*)d_in[8];
        fqw = (const float*)d_in[9];  fqb = (const float*)d_in[10];
        fkw = (const float*)d_in[11]; fkb = (const float*)d_in[12];
        fvw = (const float*)d_in[13]; fvb = (const float*)d_in[14];
        fow = (const float*)d_in[15]; fob = (const float*)d_in[16];
    } else {                    // setup_inputs dict order
        tqw = (const float*)d_in[1];  tqb = (const float*)d_in[2];
        tkw = (const float*)d_in[3];  tkb = (const float*)d_in[4];
        tvw = (const float*)d_in[5];  tvb = (const float*)d_in[6];
        fqw = (const float*)d_in[7];  fqb = (const float*)d_in[8];
        fkw = (const float*)d_in[9];  fkb = (const float*)d_in[10];
        fvw = (const float*)d_in[11]; fvb = (const float*)d_in[12];
        tow = (const float*)d_in[13]; tob = (const float*)d_in[14];
        fow = (const float*)d_in[15]; fob = (const float*)d_in[16];
    }

    float* out = (float*)d_out;

    const size_t sm_t = 36800 * sizeof(float);   // 147200 B
    const size_t sm_f = 49088 * sizeof(float);   // 196352 B

    cudaFuncSetAttribute(temporal_kernel,
                         cudaFuncAttributeMaxDynamicSharedMemorySize, (int)sm_t);
    cudaFuncSetAttribute(feature_kernel,
                         cudaFuncAttributeMaxDynamicSharedMemorySize, (int)sm_f);

    temporal_kernel<<<32 * 64, 512, sm_t>>>(x, tqw, tqb, tkw, tkb, tvw, tvb,
                                            tow, tob, out);
    feature_kernel<<<32 * 64, 512, sm_f>>>(x, fqw, fqb, fkw, fkb, fvw, fvb,
                                           fow, fob, out);
}

// round 13
// speedup vs baseline: 10.3811x; 1.2906x over previous
#include <cuda_runtime.h>

#define QSCALE 0.17677669529663687f  // 1/sqrt(32)

// pack two fp32 -> half2 bits (lo = first/lower k index)
__device__ __forceinline__ unsigned h2pack(float lo, float hi) {
    unsigned u;
    asm("cvt.rn.f16x2.f32 %0, %1, %2;" : "=r"(u) : "f"(hi), "f"(lo));
    return u;
}
// pair permutation within an 8-pair slab
__device__ __forceinline__ int PI8(int s) { return ((s & 3) << 1) | ((s >> 2) & 1); }
__device__ __forceinline__ int pcperm(int p) { return (p & ~7) | PI8(p & 7); }

__device__ __forceinline__ uint2 ldu2(const unsigned* p) { return *(const uint2*)p; }

__device__ __forceinline__ void pbar(int id) {
    asm volatile("bar.sync %0, 64;" :: "r"(id) : "memory");
}
__device__ __forceinline__ void bbar(int id) {
    asm volatile("bar.sync %0, 256;" :: "r"(id) : "memory");
}

__device__ __forceinline__ void mma16(float* c,
    unsigned a0, unsigned a1, unsigned a2, unsigned a3,
    unsigned b0, unsigned b1)
{
    asm volatile(
        "mma.sync.aligned.m16n8k16.row.col.f32.f16.f16.f32 "
        "{%0,%1,%2,%3}, {%4,%5,%6,%7}, {%8,%9}, {%0,%1,%2,%3};"
        : "+f"(c[0]), "+f"(c[1]), "+f"(c[2]), "+f"(c[3])
        : "r"(a0), "r"(a1), "r"(a2), "r"(a3), "r"(b0), "r"(b1));
}

// ---------------------------------------------------------------------------
// Temporal: ONE CTA per (b, f-pair). 128 rows = two 64-row t-blocks.
// In-register softmax (scores never hit smem).
// smem words: Xs@0[128][40] Kh@5120[128][24] Vt@8192[32][72] Qh@10496[128][24]
//  Ps@13568[128][40] Oh@18688[128][24] WB@21760 3x[32][40] WoS@25600[64][24]
//  Bs@27136(448) ExM@27584(256) ExS@27840(256)  total 28096 w = 112384 B
// ---------------------------------------------------------------------------
__global__ void __launch_bounds__(512) temporal_kernel(
    const float* __restrict__ x,
    const float* __restrict__ wq, const float* __restrict__ bq,
    const float* __restrict__ wk, const float* __restrict__ bk,
    const float* __restrict__ wv, const float* __restrict__ bv,
    const float* __restrict__ wo, const float* __restrict__ bo,
    float* __restrict__ out)
{
    extern __shared__ float sm[];
    unsigned* Xs  = (unsigned*)sm;
    unsigned* Kh  = (unsigned*)sm + 5120;
    unsigned* Vt  = (unsigned*)sm + 8192;
    unsigned* Qh  = (unsigned*)sm + 10496;
    unsigned* Ps  = (unsigned*)sm + 13568;
    unsigned* Oh  = (unsigned*)sm + 18688;
    unsigned* WB  = (unsigned*)sm + 21760;
    unsigned* WoS = (unsigned*)sm + 25600;
    float*    Bs  = sm + 27136;
    float*    ExM = sm + 27584;
    float*    ExS = sm + 27840;

    const int tid  = threadIdx.x;
    const int lane = tid & 31, warp = tid >> 5;
    const int g = lane >> 2, t4 = lane & 3;
    const int b = blockIdx.x >> 6, fp = blockIdx.x & 63;

    {
        const float4* x4 = (const float4*)x;
        for (int i = tid; i < 2048; i += 512) {
            int row = i >> 4, c = i & 15;
            int fb = row >> 6, t = row & 63;
            int f = fp * 2 + fb;
            float4 v = x4[(((b * 64 + t) * 128 + f) << 4) + c];
            Xs[row * 40 + pcperm(2 * c)]     = h2pack(v.x, v.y);
            Xs[row * 40 + pcperm(2 * c + 1)] = h2pack(v.z, v.w);
        }
    }
    if (tid < 448) {
        float v;
        if      (tid < 128) v = bq[tid];
        else if (tid < 256) v = bk[tid - 128];
        else if (tid < 384) v = bv[tid - 256];
        else                v = bo[tid - 384];
        Bs[tid] = v;
    }

    const int mt8 = warp & 7, nh2 = warp >> 3;
    const int r0 = mt8 * 16 + g, r1 = r0 + 8;
    const int blk = mt8 >> 2;
    const int pid = 8 + mt8;
    const int bid = 1 + blk;

    float pacc[4][4] = {};

    for (int h = 0; h < 4; h++) {
        const int hb = h * 32;
        __syncthreads();
        for (int i = tid; i < 3072; i += 512) {
            int m = i >> 10, r = i & 1023, n = r >> 5, p = r & 31;
            const float* w = (m == 0) ? wq : (m == 1) ? wk : wv;
            WB[m * 1280 + n * 40 + pcperm(p)] =
                h2pack(w[(2 * p) * 128 + hb + n], w[(2 * p + 1) * 128 + hb + n]);
        }
        for (int i = tid; i < 1024; i += 512) {
            int d = i >> 4, p = i & 15;
            WoS[d * 24 + ((p & 8) | PI8(p & 7))] =
                h2pack(wo[(hb + 2 * p) * 64 + d], wo[(hb + 2 * p + 1) * 64 + d]);
        }
        __syncthreads();

        // fused Q/K/V projections: M=128 N=32 K=64 (4 k16-slabs)
        {
            float aQ[2][4], aK[2][4], aV[2][4];
            #pragma unroll
            for (int nt = 0; nt < 2; nt++) {
                int c0 = nh2 * 16 + nt * 8 + 2 * t4;
                aQ[nt][0] = Bs[hb + c0];       aQ[nt][1] = Bs[hb + c0 + 1];
                aQ[nt][2] = aQ[nt][0];         aQ[nt][3] = aQ[nt][1];
                aK[nt][0] = Bs[128 + hb + c0]; aK[nt][1] = Bs[128 + hb + c0 + 1];
                aK[nt][2] = aK[nt][0];         aK[nt][3] = aK[nt][1];
                aV[nt][0] = Bs[256 + hb + c0]; aV[nt][1] = Bs[256 + hb + c0 + 1];
                aV[nt][2] = aV[nt][0];         aV[nt][3] = aV[nt][1];
            }
            #pragma unroll
            for (int kt = 0; kt < 4; kt++) {
                int ko = kt * 8 + 2 * t4;
                uint2 pa0 = ldu2(Xs + r0 * 40 + ko);
                uint2 pa1 = ldu2(Xs + r1 * 40 + ko);
                #pragma unroll
                for (int nt = 0; nt < 2; nt++) {
                    int n0 = nh2 * 16 + nt * 8 + g;
                    uint2 pq = ldu2(WB +        n0 * 40 + ko);
                    uint2 pk = ldu2(WB + 1280 + n0 * 40 + ko);
                    uint2 pv = ldu2(WB + 2560 + n0 * 40 + ko);
                    mma16(aQ[nt], pa0.x, pa1.x, pa0.y, pa1.y, pq.x, pq.y);
                    mma16(aK[nt], pa0.x, pa1.x, pa0.y, pa1.y, pk.x, pk.y);
                    mma16(aV[nt], pa0.x, pa1.x, pa0.y, pa1.y, pv.x, pv.y);
                }
            }
            float vb[2][4];
            #pragma unroll
            for (int nt = 0; nt < 2; nt++)
                #pragma unroll
                for (int j = 0; j < 4; j++)
                    vb[nt][j] = __shfl_down_sync(0xffffffffu, aV[nt][j], 4);
            #pragma unroll
            for (int nt = 0; nt < 2; nt++) {
                int pr = nh2 * 8 + PI8(nt * 4 + t4);
                Qh[r0 * 24 + pr] = h2pack(aQ[nt][0] * QSCALE, aQ[nt][1] * QSCALE);
                Qh[r1 * 24 + pr] = h2pack(aQ[nt][2] * QSCALE, aQ[nt][3] * QSCALE);
                Kh[r0 * 24 + pr] = h2pack(aK[nt][0], aK[nt][1]);
                Kh[r1 * 24 + pr] = h2pack(aK[nt][2], aK[nt][3]);
            }
            if ((g & 1) == 0) {
                int p0 = mt8 * 8 + PI8(g >> 1);
                int p1 = mt8 * 8 + PI8(4 + (g >> 1));
                #pragma unroll
                for (int nt = 0; nt < 2; nt++) {
                    int c0 = nh2 * 16 + nt * 8 + 2 * t4;
                    Vt[(c0    ) * 72 + p0] = h2pack(aV[nt][0], vb[nt][0]);
                    Vt[(c0 + 1) * 72 + p0] = h2pack(aV[nt][1], vb[nt][1]);
                    Vt[(c0    ) * 72 + p1] = h2pack(aV[nt][2], vb[nt][2]);
                    Vt[(c0 + 1) * 72 + p1] = h2pack(aV[nt][3], vb[nt][3]);
                }
            }
        }
        bbar(bid);

        // scores in regs: M=128 N=64(own block) K=32, warp tile 16x32
        float acc[4][4] = {};
        {
            const int sbase = blk * 64;
            #pragma unroll
            for (int kt = 0; kt < 2; kt++) {
                int ko = kt * 8 + 2 * t4;
                uint2 pa0 = ldu2(Qh + r0 * 24 + ko);
                uint2 pa1 = ldu2(Qh + r1 * 24 + ko);
                #pragma unroll
                for (int nt = 0; nt < 4; nt++) {
                    int s0 = sbase + nh2 * 32 + nt * 8 + g;
                    uint2 pb = ldu2(Kh + s0 * 24 + ko);
                    mma16(acc[nt], pa0.x, pa1.x, pa0.y, pa1.y, pb.x, pb.y);
                }
            }
        }
        // in-register softmax over 64 cols (pair of warps shares rows)
        {
            float m0 = acc[0][0], m1 = acc[0][2];
            #pragma unroll
            for (int nt = 0; nt < 4; nt++) {
                m0 = fmaxf(m0, fmaxf(acc[nt][0], acc[nt][1]));
                m1 = fmaxf(m1, fmaxf(acc[nt][2], acc[nt][3]));
            }
            #pragma unroll
            for (int o = 1; o <= 2; o <<= 1) {
                m0 = fmaxf(m0, __shfl_xor_sync(0xffffffffu, m0, o));
                m1 = fmaxf(m1, __shfl_xor_sync(0xffffffffu, m1, o));
            }
            if (t4 == 0) { ExM[nh2 * 128 + r0] = m0; ExM[nh2 * 128 + r1] = m1; }
            pbar(pid);
            m0 = fmaxf(m0, ExM[(1 - nh2) * 128 + r0]);
            m1 = fmaxf(m1, ExM[(1 - nh2) * 128 + r1]);
            float s0 = 0.f, s1 = 0.f;
            #pragma unroll
            for (int nt = 0; nt < 4; nt++) {
                acc[nt][0] = __expf(acc[nt][0] - m0);
                acc[nt][1] = __expf(acc[nt][1] - m0);
                acc[nt][2] = __expf(acc[nt][2] - m1);
                acc[nt][3] = __expf(acc[nt][3] - m1);
                s0 += acc[nt][0] + acc[nt][1];
                s1 += acc[nt][2] + acc[nt][3];
            }
            #pragma unroll
            for (int o = 1; o <= 2; o <<= 1) {
                s0 += __shfl_xor_sync(0xffffffffu, s0, o);
                s1 += __shfl_xor_sync(0xffffffffu, s1, o);
            }
            if (t4 == 0) { ExS[nh2 * 128 + r0] = s0; ExS[nh2 * 128 + r1] = s1; }
            pbar(pid);
            s0 += ExS[(1 - nh2) * 128 + r0];
            s1 += ExS[(1 - nh2) * 128 + r1];
            float i0 = __frcp_rn(s0), i1 = __frcp_rn(s1);
            #pragma unroll
            for (int nt = 0; nt < 4; nt++) {
                int pp = pcperm(nh2 * 16 + nt * 4 + t4);
                Ps[r0 * 40 + pp] = h2pack(acc[nt][0] * i0, acc[nt][1] * i0);
                Ps[r1 * 40 + pp] = h2pack(acc[nt][2] * i1, acc[nt][3] * i1);
            }
        }
        pbar(pid);
        // AV: M=128 N=32 K=64(own block) -> Oh
        {
            float av[2][4] = {};
            const int kbase = blk * 32;
            #pragma unroll
            for (int kt = 0; kt < 4; kt++) {
                int ko = kt * 8 + 2 * t4;
                uint2 pa0 = ldu2(Ps + r0 * 40 + ko);
                uint2 pa1 = ldu2(Ps + r1 * 40 + ko);
                #pragma unroll
                for (int nt = 0; nt < 2; nt++) {
                    int n0 = nh2 * 16 + nt * 8 + g;
                    uint2 pb = ldu2(Vt + n0 * 72 + kbase + ko);
                    mma16(av[nt], pa0.x, pa1.x, pa0.y, pa1.y, pb.x, pb.y);
                }
            }
            #pragma unroll
            for (int nt = 0; nt < 2; nt++) {
                int pr = nh2 * 8 + PI8(nt * 4 + t4);
                Oh[r0 * 24 + pr] = h2pack(av[nt][0], av[nt][1]);
                Oh[r1 * 24 + pr] = h2pack(av[nt][2], av[nt][3]);
            }
        }
        pbar(pid);
        // out-proj partial: M=128 N=64 K=32, reg acc
        #pragma unroll
        for (int kt = 0; kt < 2; kt++) {
            int ko = kt * 8 + 2 * t4;
            uint2 pa0 = ldu2(Oh + r0 * 24 + ko);
            uint2 pa1 = ldu2(Oh + r1 * 24 + ko);
            #pragma unroll
            for (int nt = 0; nt < 4; nt++) {
                int n0 = nh2 * 32 + nt * 8 + g;
                uint2 pb = ldu2(WoS + n0 * 24 + ko);
                mma16(pacc[nt], pa0.x, pa1.x, pa0.y, pa1.y, pb.x, pb.y);
            }
        }
    }

    {
        int fb = r0 >> 6, t0 = r0 & 63, t1 = r1 & 63;
        int f = fp * 2 + fb;
        #pragma unroll
        for (int nt = 0; nt < 4; nt++) {
            int d0 = nh2 * 32 + nt * 8 + 2 * t4;
            float b0 = Bs[384 + d0], b1 = Bs[384 + d0 + 1];
            float2* p0 = (float2*)(out + (((size_t)(b * 64 + t0) * 128 + f) * 64 + d0));
            float2* p1 = (float2*)(out + (((size_t)(b * 64 + t1) * 128 + f) * 64 + d0));
            *p0 = make_float2(pacc[nt][0] + b0, pacc[nt][1] + b1);
            *p1 = make_float2(pacc[nt][2] + b0, pacc[nt][3] + b1);
        }
    }
}

// ---------------------------------------------------------------------------
// Feature: ONE CTA per (b,t), 128 q-rows. In-register softmax.
// smem words: Xs@0[128][40] Kh@5120[128][24] Vt@8192[32][72] Qh@10496[128][24]
//  Ps@13568[128][72] Oh@22784[128][24] WB@25856 3x[32][40] WoS@29696[64][24]
//  Bs@31232(448) ExM@31680(256) ExS@31936(256)  total 32192 w = 128768 B
// ---------------------------------------------------------------------------
__global__ void __launch_bounds__(512) feature_kernel(
    const float* __restrict__ x,
    const float* __restrict__ wq, const float* __restrict__ bq,
    const float* __restrict__ wk, const float* __restrict__ bk,
    const float* __restrict__ wv, const float* __restrict__ bv,
    const float* __restrict__ wo, const float* __restrict__ bo,
    float* __restrict__ out)
{
    extern __shared__ float sm[];
    unsigned* Xs  = (unsigned*)sm;
    unsigned* Kh  = (unsigned*)sm + 5120;
    unsigned* Vt  = (unsigned*)sm + 8192;
    unsigned* Qh  = (unsigned*)sm + 10496;
    unsigned* Ps  = (unsigned*)sm + 13568;
    unsigned* Oh  = (unsigned*)sm + 22784;
    unsigned* WB  = (unsigned*)sm + 25856;
    unsigned* WoS = (unsigned*)sm + 29696;
    float*    Bs  = sm + 31232;
    float*    ExM = sm + 31680;
    float*    ExS = sm + 31936;

    const int tid  = threadIdx.x;
    const int lane = tid & 31, warp = tid >> 5;
    const int g = lane >> 2, t4 = lane & 3;
    const int b = blockIdx.x >> 6, t = blockIdx.x & 63;

    {
        const float4* x4 = (const float4*)(x + (size_t)(b * 64 + t) * 128 * 64);
        for (int i = tid; i < 2048; i += 512) {
            int row = i >> 4, c = i & 15;
            float4 v = x4[i];
            Xs[row * 40 + pcperm(2 * c)]     = h2pack(v.x, v.y);
            Xs[row * 40 + pcperm(2 * c + 1)] = h2pack(v.z, v.w);
        }
    }
    if (tid < 448) {
        float v;
        if      (tid < 128) v = bq[tid];
        else if (tid < 256) v = bk[tid - 128];
        else if (tid < 384) v = bv[tid - 256];
        else                v = bo[tid - 384];
        Bs[tid] = v;
    }

    const int mt8 = warp & 7, nh2 = warp >> 3;
    const int r0 = mt8 * 16 + g, r1 = r0 + 8;
    const int pid = 8 + mt8;

    float pacc[4][4] = {};

    for (int h = 0; h < 4; h++) {
        const int hb = h * 32;
        __syncthreads();
        for (int i = tid; i < 3072; i += 512) {
            int m = i >> 10, r = i & 1023, n = r >> 5, p = r & 31;
            const float* w = (m == 0) ? wq : (m == 1) ? wk : wv;
            WB[m * 1280 + n * 40 + pcperm(p)] =
                h2pack(w[(2 * p) * 128 + hb + n], w[(2 * p + 1) * 128 + hb + n]);
        }
        for (int i = tid; i < 1024; i += 512) {
            int d = i >> 4, p = i & 15;
            WoS[d * 24 + ((p & 8) | PI8(p & 7))] =
                h2pack(wo[(hb + 2 * p) * 64 + d], wo[(hb + 2 * p + 1) * 64 + d]);
        }
        __syncthreads();

        // fused Q/K/V projections: M=128 N=32 K=64
        {
            float aQ[2][4], aK[2][4], aV[2][4];
            #pragma unroll
            for (int nt = 0; nt < 2; nt++) {
                int c0 = nh2 * 16 + nt * 8 + 2 * t4;
                aQ[nt][0] = Bs[hb + c0];       aQ[nt][1] = Bs[hb + c0 + 1];
                aQ[nt][2] = aQ[nt][0];         aQ[nt][3] = aQ[nt][1];
                aK[nt][0] = Bs[128 + hb + c0]; aK[nt][1] = Bs[128 + hb + c0 + 1];
                aK[nt][2] = aK[nt][0];         aK[nt][3] = aK[nt][1];
                aV[nt][0] = Bs[256 + hb + c0]; aV[nt][1] = Bs[256 + hb + c0 + 1];
                aV[nt][2] = aV[nt][0];         aV[nt][3] = aV[nt][1];
            }
            #pragma unroll
            for (int kt = 0; kt < 4; kt++) {
                int ko = kt * 8 + 2 * t4;
                uint2 pa0 = ldu2(Xs + r0 * 40 + ko);
                uint2 pa1 = ldu2(Xs + r1 * 40 + ko);
                #pragma unroll
                for (int nt = 0; nt < 2; nt++) {
                    int n0 = nh2 * 16 + nt * 8 + g;
                    uint2 pq = ldu2(WB +        n0 * 40 + ko);
                    uint2 pk = ldu2(WB + 1280 + n0 * 40 + ko);
                    uint2 pv = ldu2(WB + 2560 + n0 * 40 + ko);
                    mma16(aQ[nt], pa0.x, pa1.x, pa0.y, pa1.y, pq.x, pq.y);
                    mma16(aK[nt], pa0.x, pa1.x, pa0.y, pa1.y, pk.x, pk.y);
                    mma16(aV[nt], pa0.x, pa1.x, pa0.y, pa1.y, pv.x, pv.y);
                }
            }
            float vb[2][4];
            #pragma unroll
            for (int nt = 0; nt < 2; nt++)
                #pragma unroll
                for (int j = 0; j < 4; j++)
                    vb[nt][j] = __shfl_down_sync(0xffffffffu, aV[nt][j], 4);
            #pragma unroll
            for (int nt = 0; nt < 2; nt++) {
                int pr = nh2 * 8 + PI8(nt * 4 + t4);
                Qh[r0 * 24 + pr] = h2pack(aQ[nt][0] * QSCALE, aQ[nt][1] * QSCALE);
                Qh[r1 * 24 + pr] = h2pack(aQ[nt][2] * QSCALE, aQ[nt][3] * QSCALE);
                Kh[r0 * 24 + pr] = h2pack(aK[nt][0], aK[nt][1]);
                Kh[r1 * 24 + pr] = h2pack(aK[nt][2], aK[nt][3]);
            }
            if ((g & 1) == 0) {
                int p0 = mt8 * 8 + PI8(g >> 1);
                int p1 = mt8 * 8 + PI8(4 + (g >> 1));
                #pragma unroll
                for (int nt = 0; nt < 2; nt++) {
                    int c0 = nh2 * 16 + nt * 8 + 2 * t4;
                    Vt[(c0    ) * 72 + p0] = h2pack(aV[nt][0], vb[nt][0]);
                    Vt[(c0 + 1) * 72 + p0] = h2pack(aV[nt][1], vb[nt][1]);
                    Vt[(c0    ) * 72 + p1] = h2pack(aV[nt][2], vb[nt][2]);
                    Vt[(c0 + 1) * 72 + p1] = h2pack(aV[nt][3], vb[nt][3]);
                }
            }
        }
        __syncthreads();   // Kh/Vt consumed CTA-wide

        // scores in regs: M=128 N=128 K=32, warp tile 16x64 (nt=8)
        float acc[8][4] = {};
        {
            #pragma unroll
            for (int kt = 0; kt < 2; kt++) {
                int ko = kt * 8 + 2 * t4;
                uint2 pa0 = ldu2(Qh + r0 * 24 + ko);
                uint2 pa1 = ldu2(Qh + r1 * 24 + ko);
                #pragma unroll
                for (int nt = 0; nt < 8; nt++) {
                    int s0 = nh2 * 64 + nt * 8 + g;
                    uint2 pb = ldu2(Kh + s0 * 24 + ko);
                    mma16(acc[nt], pa0.x, pa1.x, pa0.y, pa1.y, pb.x, pb.y);
                }
            }
        }
        // in-register softmax over 128 cols (pair shares rows)
        {
            float m0 = acc[0][0], m1 = acc[0][2];
            #pragma unroll
            for (int nt = 0; nt < 8; nt++) {
                m0 = fmaxf(m0, fmaxf(acc[nt][0], acc[nt][1]));
                m1 = fmaxf(m1, fmaxf(acc[nt][2], acc[nt][3]));
            }
            #pragma unroll
            for (int o = 1; o <= 2; o <<= 1) {
                m0 = fmaxf(m0, __shfl_xor_sync(0xffffffffu, m0, o));
                m1 = fmaxf(m1, __shfl_xor_sync(0xffffffffu, m1, o));
            }
            if (t4 == 0) { ExM[nh2 * 128 + r0] = m0; ExM[nh2 * 128 + r1] = m1; }
            pbar(pid);
            m0 = fmaxf(m0, ExM[(1 - nh2) * 128 + r0]);
            m1 = fmaxf(m1, ExM[(1 - nh2) * 128 + r1]);
            float s0 = 0.f, s1 = 0.f;
            #pragma unroll
            for (int nt = 0; nt < 8; nt++) {
                acc[nt][0] = __expf(acc[nt][0] - m0);
                acc[nt][1] = __expf(acc[nt][1] - m0);
                acc[nt][2] = __expf(acc[nt][2] - m1);
                acc[nt][3] = __expf(acc[nt][3] - m1);
                s0 += acc[nt][0] + acc[nt][1];
                s1 += acc[nt][2] + acc[nt][3];
            }
            #pragma unroll
            for (int o = 1; o <= 2; o <<= 1) {
                s0 += __shfl_xor_sync(0xffffffffu, s0, o);
                s1 += __shfl_xor_sync(0xffffffffu, s1, o);
            }
            if (t4 == 0) { ExS[nh2 * 128 + r0] = s0; ExS[nh2 * 128 + r1] = s1; }
            pbar(pid);
            s0 += ExS[(1 - nh2) * 128 + r0];
            s1 += ExS[(1 - nh2) * 128 + r1];
            float i0 = __frcp_rn(s0), i1 = __frcp_rn(s1);
            #pragma unroll
            for (int nt = 0; nt < 8; nt++) {
                int pp = pcperm(nh2 * 32 + nt * 4 + t4);
                Ps[r0 * 72 + pp] = h2pack(acc[nt][0] * i0, acc[nt][1] * i0);
                Ps[r1 * 72 + pp] = h2pack(acc[nt][2] * i1, acc[nt][3] * i1);
            }
        }
        pbar(pid);
        // AV: M=128 N=32 K=128 -> Oh
        {
            float av[2][4] = {};
            #pragma unroll
            for (int kt = 0; kt < 8; kt++) {
                int ko = kt * 8 + 2 * t4;
                uint2 pa0 = ldu2(Ps + r0 * 72 + ko);
                uint2 pa1 = ldu2(Ps + r1 * 72 + ko);
                #pragma unroll
                for (int nt = 0; nt < 2; nt++) {
                    int n0 = nh2 * 16 + nt * 8 + g;
                    uint2 pb = ldu2(Vt + n0 * 72 + ko);
                    mma16(av[nt], pa0.x, pa1.x, pa0.y, pa1.y, pb.x, pb.y);
                }
            }
            #pragma unroll
            for (int nt = 0; nt < 2; nt++) {
                int pr = nh2 * 8 + PI8(nt * 4 + t4);
                Oh[r0 * 24 + pr] = h2pack(av[nt][0], av[nt][1]);
                Oh[r1 * 24 + pr] = h2pack(av[nt][2], av[nt][3]);
            }
        }
        pbar(pid);
        // out-proj partial: M=128 N=64 K=32, reg acc
        #pragma unroll
        for (int kt = 0; kt < 2; kt++) {
            int ko = kt * 8 + 2 * t4;
            uint2 pa0 = ldu2(Oh + r0 * 24 + ko);
            uint2 pa1 = ldu2(Oh + r1 * 24 + ko);
            #pragma unroll
            for (int nt = 0; nt < 4; nt++) {
                int n0 = nh2 * 32 + nt * 8 + g;
                uint2 pb = ldu2(WoS + n0 * 24 + ko);
                mma16(pacc[nt], pa0.x, pa1.x, pa0.y, pa1.y, pb.x, pb.y);
            }
        }
    }

    #pragma unroll
    for (int nt = 0; nt < 4; nt++) {
        int d0 = nh2 * 32 + nt * 8 + 2 * t4;
        float b0 = Bs[384 + d0], b1 = Bs[384 + d0 + 1];
        float2* p0 = (float2*)(out + (((size_t)(b * 64 + t) * 128 + r0) * 64 + d0));
        float2* p1 = (float2*)(out + (((size_t)(b * 64 + t) * 128 + r1) * 64 + d0));
        float2 v0 = *p0, v1 = *p1;
        v0.x += pacc[nt][0] + b0; v0.y += pacc[nt][1] + b1;
        v1.x += pacc[nt][2] + b0; v1.y += pacc[nt][3] + b1;
        *p0 = v0; *p1 = v1;
    }
}

// ---------------------------------------------------------------------------
extern "C" void kernel_launch(void* const* d_in, const int* in_sizes, int n_in,
                              void* d_out, int out_size)
{
    const float* x = (const float*)d_in[0];
    const float *tqw, *tqb, *tkw, *tkb, *tvw, *tvb, *tow, *tob;
    const float *fqw, *fqb, *fkw, *fkb, *fvw, *fvb, *fow, *fob;

    if (in_sizes[8] == 64) {   // reference-signature order
        tqw = (const float*)d_in[1];  tqb = (const float*)d_in[2];
        tkw = (const float*)d_in[3];  tkb = (const float*)d_in[4];
        tvw = (const float*)d_in[5];  tvb = (const float*)d_in[6];
        tow = (const float*)d_in[7];  tob = (const float*)d_in[8];
        fqw = (const float*)d_in[9];  fqb = (const float*)d_in[10];
        fkw = (const float*)d_in[11]; fkb = (const float*)d_in[12];
        fvw = (const float*)d_in[13]; fvb = (const float*)d_in[14];
        fow = (const float*)d_in[15]; fob = (const float*)d_in[16];
    } else {                    // setup_inputs dict order
        tqw = (const float*)d_in[1];  tqb = (const float*)d_in[2];
        tkw = (const float*)d_in[3];  tkb = (const float*)d_in[4];
        tvw = (const float*)d_in[5];  tvb = (const float*)d_in[6];
        fqw = (const float*)d_in[7];  fqb = (const float*)d_in[8];
        fkw = (const float*)d_in[9];  fkb = (const float*)d_in[10];
        fvw = (const float*)d_in[11]; fvb = (const float*)d_in[12];
        tow = (const float*)d_in[13]; tob = (const float*)d_in[14];
        fow = (const float*)d_in[15]; fob = (const float*)d_in[16];
    }

    float* out = (float*)d_out;

    const size_t sm_t = 28096 * sizeof(float);   // 112384 B
    const size_t sm_f = 32192 * sizeof(float);   // 128768 B

    cudaFuncSetAttribute(temporal_kernel,
                         cudaFuncAttributeMaxDynamicSharedMemorySize, (int)sm_t);
    cudaFuncSetAttribute(feature_kernel,
                         cudaFuncAttributeMaxDynamicSharedMemorySize, (int)sm_f);

    temporal_kernel<<<32 * 64, 512, sm_t>>>(x, tqw, tqb, tkw, tkb, tvw, tvb,
                                            tow, tob, out);
    feature_kernel<<<32 * 64, 512, sm_f>>>(x, fqw, fqb, fkw, fkb, fvw, fvb,
                                           fow, fob, out);
}